// round 3
// baseline (speedup 1.0000x reference)
#include <cuda_runtime.h>
#include <math.h>

#define DIM 3072
#define HEADS 24
#define HD 128
#define SIMG 2048
#define STXT 256
#define STOT 2304

// scratch (static __device__ globals per allocation rules)
__device__ float g_q[(size_t)STOT * DIM];
__device__ float g_k[(size_t)STOT * DIM];
__device__ float g_v[(size_t)STOT * DIM];
__device__ float g_o[(size_t)STOT * DIM];

// ---------------------------------------------------------------------------
// SGEMM: C[M,N] = A @ W + bias.  K = N = DIM = 3072.
// A rows come from A0 (rows < split) or A1 (rows >= split) to handle the
// virtual concat of hidden_states and encoder_hidden_states without a copy.
// 128x128 block tile, BK=16, 256 threads, 8x8 microtile per thread.
// ---------------------------------------------------------------------------
__global__ __launch_bounds__(256) void sgemm_bias(
    const float* __restrict__ A0, const float* __restrict__ A1, int split,
    const float* __restrict__ W, const float* __restrict__ bias,
    float* __restrict__ C)
{
    __shared__ float As[16 * 129];   // transposed: As[k][m], pad to kill conflicts
    __shared__ float Bs[16 * 128];   // Bs[k][n]

    const int tid = threadIdx.x;
    const int tx = tid & 15;         // column group
    const int ty = tid >> 4;         // row group
    const int bm = blockIdx.y * 128;
    const int bn = blockIdx.x * 128;

    float acc[8][8] = {};

    for (int k0 = 0; k0 < DIM; k0 += 16) {
        // --- load A tile: 128 rows x 16 cols (float4 global loads) ---
        #pragma unroll
        for (int i = 0; i < 2; i++) {
            int f4 = tid + i * 256;              // 0..511
            int r  = f4 >> 2;                    // 0..127
            int c4 = (f4 & 3) * 4;               // 0,4,8,12
            int rg = bm + r;
            const float* arow = (rg < split) ? (A0 + (size_t)rg * DIM)
                                             : (A1 + (size_t)(rg - split) * DIM);
            float4 v = *(const float4*)(arow + k0 + c4);
            As[(c4 + 0) * 129 + r] = v.x;
            As[(c4 + 1) * 129 + r] = v.y;
            As[(c4 + 2) * 129 + r] = v.z;
            As[(c4 + 3) * 129 + r] = v.w;
        }
        // --- load B tile: 16 rows x 128 cols ---
        #pragma unroll
        for (int i = 0; i < 2; i++) {
            int f4 = tid + i * 256;
            int r  = f4 >> 5;                    // 0..15
            int c4 = (f4 & 31) * 4;              // 0..124
            float4 v = *(const float4*)(W + (size_t)(k0 + r) * DIM + bn + c4);
            *(float4*)(Bs + r * 128 + c4) = v;
        }
        __syncthreads();

        #pragma unroll
        for (int kc = 0; kc < 16; kc++) {
            float a[8], b[8];
            #pragma unroll
            for (int ii = 0; ii < 8; ii++) a[ii] = As[kc * 129 + ty * 8 + ii];
            #pragma unroll
            for (int jj = 0; jj < 8; jj++) b[jj] = Bs[kc * 128 + jj * 16 + tx];
            #pragma unroll
            for (int ii = 0; ii < 8; ii++)
                #pragma unroll
                for (int jj = 0; jj < 8; jj++)
                    acc[ii][jj] = fmaf(a[ii], b[jj], acc[ii][jj]);
        }
        __syncthreads();
    }

    #pragma unroll
    for (int ii = 0; ii < 8; ii++) {
        int r = bm + ty * 8 + ii;
        #pragma unroll
        for (int jj = 0; jj < 8; jj++) {
            int c = bn + jj * 16 + tx;
            C[(size_t)r * DIM + c] = acc[ii][jj] + bias[c];
        }
    }
}

// ---------------------------------------------------------------------------
// Fused per-head RMSNorm + RoPE (rope only for s < SIMG). In-place.
// grid (STOT, HEADS), block 128 (one thread per head-dim element).
// ---------------------------------------------------------------------------
__global__ void rmsnorm_rope(float* __restrict__ buf, const float* __restrict__ w,
                             const float* __restrict__ cb, const float* __restrict__ sb)
{
    const int s = blockIdx.x, h = blockIdx.y, d = threadIdx.x;
    float* p = buf + (size_t)s * DIM + h * HD;
    float val = p[d];

    float sq = val * val;
    #pragma unroll
    for (int off = 16; off; off >>= 1) sq += __shfl_xor_sync(0xffffffffu, sq, off);
    __shared__ float red[4];
    if ((d & 31) == 0) red[d >> 5] = sq;
    __syncthreads();
    float tot = red[0] + red[1] + red[2] + red[3];

    float n = val * rsqrtf(tot * (1.0f / HD) + 1e-6f) * w[d];

    __shared__ float nv[HD];
    nv[d] = n;
    __syncthreads();

    float outv = n;
    if (s < SIMG) {
        float c  = cb[s * HD + d];
        float si = sb[s * HD + d];
        // rot[2i] = -x[2i+1], rot[2i+1] = x[2i]
        float partner = (d & 1) ? nv[d - 1] : -nv[d + 1];
        outv = n * c + partner * si;
    }
    p[d] = outv;
}

// ---------------------------------------------------------------------------
// Flash attention, fp32, online softmax. BQ = BK = 64, 256 threads.
// grid (STOT/64, HEADS). Dynamic smem ~83.5 KB.
// S-phase microtile 4x4 (rows tg*4+ii, cols tx*4+jj)
// O-phase microtile 4x8 (rows tg*4+ii, cols cc*16+tx)
// ---------------------------------------------------------------------------
#define BQ 64
#define BK 64

__global__ __launch_bounds__(256) void attn_kernel(
    const float* __restrict__ q, const float* __restrict__ k,
    const float* __restrict__ v, float* __restrict__ o)
{
    extern __shared__ float sm[];
    float* Qs  = sm;                       // 64 * 129
    float* KVs = Qs + 64 * 129;            // 64 * 129 (K tile, then V tile)
    float* Ss  = KVs + 64 * 129;           // 64 * 65  (scores -> probs)
    float* rm  = Ss + 64 * 65;             // 64 running max
    float* rl  = rm + 64;                  // 64 running sum
    float* rc  = rl + 64;                  // 64 correction factors

    const int tid = threadIdx.x;
    const int tx = tid & 15;
    const int tg = tid >> 4;               // 0..15, owns rows tg*4 .. tg*4+3
    const int q0 = blockIdx.x * BQ;
    const int h  = blockIdx.y;
    const float scale = 0.08838834764831845f; // 1/sqrt(128)

    // load Q tile (64 x 128)
    #pragma unroll
    for (int i = 0; i < 8; i++) {
        int f4 = tid + i * 256;
        int r  = f4 >> 5;
        int c4 = (f4 & 31) * 4;
        float4 vv = *(const float4*)(q + (size_t)(q0 + r) * DIM + h * HD + c4);
        Qs[r * 129 + c4 + 0] = vv.x; Qs[r * 129 + c4 + 1] = vv.y;
        Qs[r * 129 + c4 + 2] = vv.z; Qs[r * 129 + c4 + 3] = vv.w;
    }
    if (tid < 64) { rm[tid] = -1e30f; rl[tid] = 0.0f; }

    float oacc[4][8] = {};

    for (int kt = 0; kt < STOT; kt += BK) {
        __syncthreads();   // protect KVs (prev V) and Ss (prev P) from overwrite
        // load K tile
        #pragma unroll
        for (int i = 0; i < 8; i++) {
            int f4 = tid + i * 256;
            int r  = f4 >> 5;
            int c4 = (f4 & 31) * 4;
            float4 vv = *(const float4*)(k + (size_t)(kt + r) * DIM + h * HD + c4);
            KVs[r * 129 + c4 + 0] = vv.x; KVs[r * 129 + c4 + 1] = vv.y;
            KVs[r * 129 + c4 + 2] = vv.z; KVs[r * 129 + c4 + 3] = vv.w;
        }
        __syncthreads();

        // S = scale * Q @ K^T  (64x64)
        float sacc[4][4] = {};
        #pragma unroll 4
        for (int d = 0; d < HD; d++) {
            float a[4], b[4];
            #pragma unroll
            for (int ii = 0; ii < 4; ii++) a[ii] = Qs[(tg * 4 + ii) * 129 + d];
            #pragma unroll
            for (int jj = 0; jj < 4; jj++) b[jj] = KVs[(tx * 4 + jj) * 129 + d];
            #pragma unroll
            for (int ii = 0; ii < 4; ii++)
                #pragma unroll
                for (int jj = 0; jj < 4; jj++)
                    sacc[ii][jj] = fmaf(a[ii], b[jj], sacc[ii][jj]);
        }
        #pragma unroll
        for (int ii = 0; ii < 4; ii++)
            #pragma unroll
            for (int jj = 0; jj < 4; jj++)
                Ss[(tg * 4 + ii) * 65 + tx * 4 + jj] = sacc[ii][jj] * scale;
        __syncthreads();   // S complete, K tile no longer needed

        // load V tile into KVs (overlaps with softmax below)
        #pragma unroll
        for (int i = 0; i < 8; i++) {
            int f4 = tid + i * 256;
            int r  = f4 >> 5;
            int c4 = (f4 & 31) * 4;
            float4 vv = *(const float4*)(v + (size_t)(kt + r) * DIM + h * HD + c4);
            KVs[r * 129 + c4 + 0] = vv.x; KVs[r * 129 + c4 + 1] = vv.y;
            KVs[r * 129 + c4 + 2] = vv.z; KVs[r * 129 + c4 + 3] = vv.w;
        }
        // online softmax (one thread per row)
        if (tid < 64) {
            int r = tid;
            float mold = rm[r], mnew = mold;
            #pragma unroll 8
            for (int j = 0; j < BK; j++) mnew = fmaxf(mnew, Ss[r * 65 + j]);
            float corr = __expf(mold - mnew);
            float ls = 0.0f;
            #pragma unroll 8
            for (int j = 0; j < BK; j++) {
                float pp = __expf(Ss[r * 65 + j] - mnew);
                Ss[r * 65 + j] = pp;
                ls += pp;
            }
            rm[r] = mnew;
            rl[r] = rl[r] * corr + ls;
            rc[r] = corr;
        }
        __syncthreads();   // V loaded, P & corr ready

        // O = O*corr + P @ V
        #pragma unroll
        for (int ii = 0; ii < 4; ii++) {
            float cr = rc[tg * 4 + ii];
            #pragma unroll
            for (int cc = 0; cc < 8; cc++) oacc[ii][cc] *= cr;
        }
        #pragma unroll 2
        for (int j = 0; j < BK; j++) {
            float p[4], vv[8];
            #pragma unroll
            for (int ii = 0; ii < 4; ii++) p[ii] = Ss[(tg * 4 + ii) * 65 + j];
            #pragma unroll
            for (int cc = 0; cc < 8; cc++) vv[cc] = KVs[j * 129 + cc * 16 + tx];
            #pragma unroll
            for (int ii = 0; ii < 4; ii++)
                #pragma unroll
                for (int cc = 0; cc < 8; cc++)
                    oacc[ii][cc] = fmaf(p[ii], vv[cc], oacc[ii][cc]);
        }
    }

    // normalize and write out: o[s][h*128 + c]
    #pragma unroll
    for (int ii = 0; ii < 4; ii++) {
        float inv = 1.0f / rl[tg * 4 + ii];
        #pragma unroll
        for (int cc = 0; cc < 8; cc++) {
            o[(size_t)(q0 + tg * 4 + ii) * DIM + h * HD + cc * 16 + tx] =
                oacc[ii][cc] * inv;
        }
    }
}

// copy txt part of attention output straight to d_out (no projection)
__global__ void copy_txt(const float* __restrict__ src, float* __restrict__ dst)
{
    int i = blockIdx.x * blockDim.x + threadIdx.x;
    if (i < STXT * DIM) dst[i] = src[i];
}

// ---------------------------------------------------------------------------
extern "C" void kernel_launch(void* const* d_in, const int* in_sizes, int n_in,
                              void* d_out, int out_size)
{
    const float* hidden = (const float*)d_in[0];
    const float* enc    = (const float*)d_in[1];
    const float* cosb   = (const float*)d_in[2];
    const float* sinb   = (const float*)d_in[3];
    const float* wq     = (const float*)d_in[4];
    const float* bq     = (const float*)d_in[5];
    const float* wk     = (const float*)d_in[6];
    const float* bk     = (const float*)d_in[7];
    const float* wv     = (const float*)d_in[8];
    const float* bv     = (const float*)d_in[9];
    const float* nqw    = (const float*)d_in[10];
    const float* nkw    = (const float*)d_in[11];
    const float* wo     = (const float*)d_in[12];
    const float* bo     = (const float*)d_in[13];
    float* out = (float*)d_out;

    float *pq, *pk, *pv, *po;
    cudaGetSymbolAddress((void**)&pq, g_q);
    cudaGetSymbolAddress((void**)&pk, g_k);
    cudaGetSymbolAddress((void**)&pv, g_v);
    cudaGetSymbolAddress((void**)&po, g_o);

    const int attn_smem = (64 * 129 * 2 + 64 * 65 + 3 * 64) * (int)sizeof(float);
    cudaFuncSetAttribute(attn_kernel, cudaFuncAttributeMaxDynamicSharedMemorySize,
                         attn_smem);

    // Q, K, V projections (A = virtual concat of hidden + encoder)
    dim3 gp(DIM / 128, STOT / 128);   // (24, 18)
    sgemm_bias<<<gp, 256>>>(hidden, enc, SIMG, wq, bq, pq);
    sgemm_bias<<<gp, 256>>>(hidden, enc, SIMG, wk, bk, pk);
    sgemm_bias<<<gp, 256>>>(hidden, enc, SIMG, wv, bv, pv);

    // per-head RMSNorm + RoPE
    dim3 gn(STOT, HEADS);
    rmsnorm_rope<<<gn, 128>>>(pq, nqw, cosb, sinb);
    rmsnorm_rope<<<gn, 128>>>(pk, nkw, cosb, sinb);

    // attention
    dim3 ga(STOT / BQ, HEADS);        // (36, 24)
    attn_kernel<<<ga, 256, attn_smem>>>(pq, pk, pv, po);

    // output projection for image tokens
    dim3 go(DIM / 128, SIMG / 128);   // (24, 16)
    sgemm_bias<<<go, 256>>>(po, po, 1 << 30, wo, bo, out);

    // raw copy of text tokens
    copy_txt<<<(STXT * DIM + 255) / 256, 256>>>(po + (size_t)SIMG * DIM,
                                                out + (size_t)SIMG * DIM);
}

// round 5
// speedup vs baseline: 2.8330x; 2.8330x over previous
#include <cuda_runtime.h>
#include <cuda_bf16.h>
#include <cstdint>
#include <math.h>

#define DIM 3072
#define HEADS 24
#define HD 128
#define SIMG 2048
#define STXT 256
#define STOT 2304

// ---------------------------------------------------------------------------
// scratch (static __device__ globals per allocation rules)
// ---------------------------------------------------------------------------
__device__ float g_q[(size_t)STOT * DIM];
__device__ float g_k[(size_t)STOT * DIM];
__device__ float g_v[(size_t)STOT * DIM];
__device__ float g_o[(size_t)STOT * DIM];
__device__ __nv_bfloat16 g_xhi[(size_t)STOT * DIM];
__device__ __nv_bfloat16 g_xlo[(size_t)STOT * DIM];
__device__ __nv_bfloat16 g_whi[(size_t)DIM * DIM];
__device__ __nv_bfloat16 g_wlo[(size_t)DIM * DIM];

// ---------------------------------------------------------------------------
// PTX helpers
// ---------------------------------------------------------------------------
__device__ __forceinline__ void cpa16(uint32_t s, const void* g) {
    asm volatile("cp.async.cg.shared.global [%0], [%1], 16;" :: "r"(s), "l"(g));
}
__device__ __forceinline__ void ldm_x4(uint32_t addr, uint32_t* r) {
    asm volatile("ldmatrix.sync.aligned.m8n8.x4.shared.b16 {%0,%1,%2,%3}, [%4];"
        : "=r"(r[0]), "=r"(r[1]), "=r"(r[2]), "=r"(r[3]) : "r"(addr));
}
__device__ __forceinline__ void ldm_x4t(uint32_t addr, uint32_t* r) {
    asm volatile("ldmatrix.sync.aligned.m8n8.x4.trans.shared.b16 {%0,%1,%2,%3}, [%4];"
        : "=r"(r[0]), "=r"(r[1]), "=r"(r[2]), "=r"(r[3]) : "r"(addr));
}
__device__ __forceinline__ void mma_bf16(float* d, const uint32_t* a,
                                         uint32_t b0, uint32_t b1) {
    asm volatile(
        "mma.sync.aligned.m16n8k16.row.col.f32.bf16.bf16.f32 "
        "{%0,%1,%2,%3}, {%4,%5,%6,%7}, {%8,%9}, {%0,%1,%2,%3};"
        : "+f"(d[0]), "+f"(d[1]), "+f"(d[2]), "+f"(d[3])
        : "r"(a[0]), "r"(a[1]), "r"(a[2]), "r"(a[3]), "r"(b0), "r"(b1));
}

// ---------------------------------------------------------------------------
// split fp32 -> bf16 hi/lo.  n must be a multiple of 4.
// ---------------------------------------------------------------------------
__global__ void conv_split(const float* __restrict__ src,
                           __nv_bfloat16* __restrict__ hi,
                           __nv_bfloat16* __restrict__ lo, int n)
{
    int i = (blockIdx.x * blockDim.x + threadIdx.x) * 4;
    if (i >= n) return;
    float4 v = *(const float4*)(src + i);
    __nv_bfloat16 h0 = __float2bfloat16(v.x);
    __nv_bfloat16 h1 = __float2bfloat16(v.y);
    __nv_bfloat16 h2 = __float2bfloat16(v.z);
    __nv_bfloat16 h3 = __float2bfloat16(v.w);
    __nv_bfloat16 l0 = __float2bfloat16(v.x - __bfloat162float(h0));
    __nv_bfloat16 l1 = __float2bfloat16(v.y - __bfloat162float(h1));
    __nv_bfloat16 l2 = __float2bfloat16(v.z - __bfloat162float(h2));
    __nv_bfloat16 l3 = __float2bfloat16(v.w - __bfloat162float(h3));
    __nv_bfloat162* hp = (__nv_bfloat162*)(hi + i);
    __nv_bfloat162* lp = (__nv_bfloat162*)(lo + i);
    hp[0] = __halves2bfloat162(h0, h1);
    hp[1] = __halves2bfloat162(h2, h3);
    lp[0] = __halves2bfloat162(l0, l1);
    lp[1] = __halves2bfloat162(l2, l3);
}

// ---------------------------------------------------------------------------
// Tensor-core split-bf16 GEMM: C[M,3072] = A @ W + bias (fp32 accurate).
// 128x128 block tile, BK=32, 256 threads (8 warps, 4x2), warp tile 32x64.
// cp.async double-buffered smem; 3 mma terms: hi*hi + hi*lo + lo*hi.
// ---------------------------------------------------------------------------
#define A_LO   5120          // elements: 128*40
#define B_HI   10240         // 2*5120
#define B_LO   14592         // B_HI + 32*136
#define STG_E  18944         // stage elements (37888 bytes)

__device__ __forceinline__ void load_stage(
    uint32_t sb, int tid, int bm, int bn, int k0,
    const __nv_bfloat16* Ahi, const __nv_bfloat16* Alo,
    const __nv_bfloat16* Bhi, const __nv_bfloat16* Blo)
{
    #pragma unroll
    for (int i = 0; i < 2; i++) {
        int c = tid + i * 256;
        int r = c >> 2, cc = (c & 3) * 8;
        size_t go = (size_t)(bm + r) * DIM + k0 + cc;
        cpa16(sb + (r * 40 + cc) * 2, Ahi + go);
        cpa16(sb + (A_LO + r * 40 + cc) * 2, Alo + go);
    }
    #pragma unroll
    for (int i = 0; i < 2; i++) {
        int c = tid + i * 256;
        int r = c >> 4, cc = (c & 15) * 8;
        size_t go = (size_t)(k0 + r) * DIM + bn + cc;
        cpa16(sb + (B_HI + r * 136 + cc) * 2, Bhi + go);
        cpa16(sb + (B_LO + r * 136 + cc) * 2, Blo + go);
    }
    asm volatile("cp.async.commit_group;" ::: "memory");
}

__global__ __launch_bounds__(256) void gemm_tc(
    const __nv_bfloat16* __restrict__ Ahi, const __nv_bfloat16* __restrict__ Alo,
    const __nv_bfloat16* __restrict__ Bhi, const __nv_bfloat16* __restrict__ Blo,
    const float* __restrict__ bias, float* __restrict__ C)
{
    extern __shared__ __nv_bfloat16 smbuf[];
    const int tid  = threadIdx.x;
    const int lane = tid & 31;
    const int wid  = tid >> 5;
    const int wm   = wid & 3;          // 4 warps along M
    const int wn   = wid >> 2;         // 2 warps along N
    const int bm   = blockIdx.y * 128;
    const int bn   = blockIdx.x * 128;
    uint32_t sb0 = (uint32_t)__cvta_generic_to_shared(smbuf);

    float acc[2][8][4] = {};

    load_stage(sb0, tid, bm, bn, 0, Ahi, Alo, Bhi, Blo);

    const int NIT = DIM / 32;          // 96
    for (int it = 0; it < NIT; it++) {
        if (it + 1 < NIT) {
            load_stage(sb0 + ((it + 1) & 1) * (STG_E * 2), tid, bm, bn,
                       (it + 1) * 32, Ahi, Alo, Bhi, Blo);
            asm volatile("cp.async.wait_group 1;" ::: "memory");
        } else {
            asm volatile("cp.async.wait_group 0;" ::: "memory");
        }
        __syncthreads();

        uint32_t sb = sb0 + (it & 1) * (STG_E * 2);
        #pragma unroll
        for (int kk = 0; kk < 32; kk += 16) {
            uint32_t ra_h[2][4];
            uint32_t ra_l[2][4];
            uint32_t rb_h[4][4];
            uint32_t rb_l[4][4];
            uint32_t arow = wm * 32 + (lane & 15);
            uint32_t aoff = (arow * 40 + kk + (lane >> 4) * 8) * 2;
            ldm_x4(sb + aoff, ra_h[0]);
            ldm_x4(sb + aoff + 16 * 40 * 2, ra_h[1]);
            ldm_x4(sb + A_LO * 2 + aoff, ra_l[0]);
            ldm_x4(sb + A_LO * 2 + aoff + 16 * 40 * 2, ra_l[1]);

            int g = lane >> 3;
            uint32_t brow = kk + (g & 1) * 8 + (lane & 7);
            #pragma unroll
            for (int ng = 0; ng < 4; ng++) {
                uint32_t col  = wn * 64 + ng * 16 + (g >> 1) * 8;
                uint32_t boff = (brow * 136 + col) * 2;
                ldm_x4t(sb + B_HI * 2 + boff, rb_h[ng]);
                ldm_x4t(sb + B_LO * 2 + boff, rb_l[ng]);
            }
            #pragma unroll
            for (int mi = 0; mi < 2; mi++) {
                #pragma unroll
                for (int t = 0; t < 8; t++) {
                    uint32_t bh0 = rb_h[t >> 1][(t & 1) * 2];
                    uint32_t bh1 = rb_h[t >> 1][(t & 1) * 2 + 1];
                    uint32_t bl0 = rb_l[t >> 1][(t & 1) * 2];
                    uint32_t bl1 = rb_l[t >> 1][(t & 1) * 2 + 1];
                    mma_bf16(acc[mi][t], ra_h[mi], bh0, bh1);
                    mma_bf16(acc[mi][t], ra_h[mi], bl0, bl1);
                    mma_bf16(acc[mi][t], ra_l[mi], bh0, bh1);
                }
            }
        }
        __syncthreads();
    }

    // epilogue: add bias, store fp32
    #pragma unroll
    for (int mi = 0; mi < 2; mi++) {
        int r0 = bm + wm * 32 + mi * 16 + (lane >> 2);
        #pragma unroll
        for (int t = 0; t < 8; t++) {
            int c = bn + wn * 64 + t * 8 + (lane & 3) * 2;
            C[(size_t)r0 * DIM + c]           = acc[mi][t][0] + bias[c];
            C[(size_t)r0 * DIM + c + 1]       = acc[mi][t][1] + bias[c + 1];
            C[(size_t)(r0 + 8) * DIM + c]     = acc[mi][t][2] + bias[c];
            C[(size_t)(r0 + 8) * DIM + c + 1] = acc[mi][t][3] + bias[c + 1];
        }
    }
}

// ---------------------------------------------------------------------------
// Fused per-head RMSNorm + RoPE (rope only for s < SIMG). In-place.
// ---------------------------------------------------------------------------
__global__ void rmsnorm_rope(float* __restrict__ buf, const float* __restrict__ w,
                             const float* __restrict__ cb, const float* __restrict__ sb)
{
    const int s = blockIdx.x, h = blockIdx.y, d = threadIdx.x;
    float* p = buf + (size_t)s * DIM + h * HD;
    float val = p[d];

    float sq = val * val;
    #pragma unroll
    for (int off = 16; off; off >>= 1) sq += __shfl_xor_sync(0xffffffffu, sq, off);
    __shared__ float red[4];
    if ((d & 31) == 0) red[d >> 5] = sq;
    __syncthreads();
    float tot = red[0] + red[1] + red[2] + red[3];

    float n = val * rsqrtf(tot * (1.0f / HD) + 1e-6f) * w[d];

    __shared__ float nv[HD];
    nv[d] = n;
    __syncthreads();

    float outv = n;
    if (s < SIMG) {
        float c  = cb[s * HD + d];
        float si = sb[s * HD + d];
        float partner = (d & 1) ? nv[d - 1] : -nv[d + 1];
        outv = n * c + partner * si;
    }
    p[d] = outv;
}

// ---------------------------------------------------------------------------
// Flash attention, fp32, online softmax. BQ = BK = 64, 256 threads.
// ---------------------------------------------------------------------------
#define BQ 64
#define BKT 64

__global__ __launch_bounds__(256) void attn_kernel(
    const float* __restrict__ q, const float* __restrict__ k,
    const float* __restrict__ v, float* __restrict__ o)
{
    extern __shared__ float sm[];
    float* Qs  = sm;                       // 64 * 129
    float* KVs = Qs + 64 * 129;            // 64 * 129
    float* Ss  = KVs + 64 * 129;           // 64 * 65
    float* rm  = Ss + 64 * 65;
    float* rl  = rm + 64;
    float* rc  = rl + 64;

    const int tid = threadIdx.x;
    const int tx = tid & 15;
    const int tg = tid >> 4;
    const int q0 = blockIdx.x * BQ;
    const int h  = blockIdx.y;
    const float scale = 0.08838834764831845f;

    #pragma unroll
    for (int i = 0; i < 8; i++) {
        int f4 = tid + i * 256;
        int r  = f4 >> 5;
        int c4 = (f4 & 31) * 4;
        float4 vv = *(const float4*)(q + (size_t)(q0 + r) * DIM + h * HD + c4);
        Qs[r * 129 + c4 + 0] = vv.x; Qs[r * 129 + c4 + 1] = vv.y;
        Qs[r * 129 + c4 + 2] = vv.z; Qs[r * 129 + c4 + 3] = vv.w;
    }
    if (tid < 64) { rm[tid] = -1e30f; rl[tid] = 0.0f; }

    float oacc[4][8] = {};

    for (int kt = 0; kt < STOT; kt += BKT) {
        __syncthreads();
        #pragma unroll
        for (int i = 0; i < 8; i++) {
            int f4 = tid + i * 256;
            int r  = f4 >> 5;
            int c4 = (f4 & 31) * 4;
            float4 vv = *(const float4*)(k + (size_t)(kt + r) * DIM + h * HD + c4);
            KVs[r * 129 + c4 + 0] = vv.x; KVs[r * 129 + c4 + 1] = vv.y;
            KVs[r * 129 + c4 + 2] = vv.z; KVs[r * 129 + c4 + 3] = vv.w;
        }
        __syncthreads();

        float sacc[4][4] = {};
        #pragma unroll 4
        for (int d = 0; d < HD; d++) {
            float a[4], b[4];
            #pragma unroll
            for (int ii = 0; ii < 4; ii++) a[ii] = Qs[(tg * 4 + ii) * 129 + d];
            #pragma unroll
            for (int jj = 0; jj < 4; jj++) b[jj] = KVs[(tx * 4 + jj) * 129 + d];
            #pragma unroll
            for (int ii = 0; ii < 4; ii++)
                #pragma unroll
                for (int jj = 0; jj < 4; jj++)
                    sacc[ii][jj] = fmaf(a[ii], b[jj], sacc[ii][jj]);
        }
        #pragma unroll
        for (int ii = 0; ii < 4; ii++)
            #pragma unroll
            for (int jj = 0; jj < 4; jj++)
                Ss[(tg * 4 + ii) * 65 + tx * 4 + jj] = sacc[ii][jj] * scale;
        __syncthreads();

        #pragma unroll
        for (int i = 0; i < 8; i++) {
            int f4 = tid + i * 256;
            int r  = f4 >> 5;
            int c4 = (f4 & 31) * 4;
            float4 vv = *(const float4*)(v + (size_t)(kt + r) * DIM + h * HD + c4);
            KVs[r * 129 + c4 + 0] = vv.x; KVs[r * 129 + c4 + 1] = vv.y;
            KVs[r * 129 + c4 + 2] = vv.z; KVs[r * 129 + c4 + 3] = vv.w;
        }
        if (tid < 64) {
            int r = tid;
            float mold = rm[r], mnew = mold;
            #pragma unroll 8
            for (int j = 0; j < BKT; j++) mnew = fmaxf(mnew, Ss[r * 65 + j]);
            float corr = __expf(mold - mnew);
            float ls = 0.0f;
            #pragma unroll 8
            for (int j = 0; j < BKT; j++) {
                float pp = __expf(Ss[r * 65 + j] - mnew);
                Ss[r * 65 + j] = pp;
                ls += pp;
            }
            rm[r] = mnew;
            rl[r] = rl[r] * corr + ls;
            rc[r] = corr;
        }
        __syncthreads();

        #pragma unroll
        for (int ii = 0; ii < 4; ii++) {
            float cr = rc[tg * 4 + ii];
            #pragma unroll
            for (int cc = 0; cc < 8; cc++) oacc[ii][cc] *= cr;
        }
        #pragma unroll 2
        for (int j = 0; j < BKT; j++) {
            float p[4], vv[8];
            #pragma unroll
            for (int ii = 0; ii < 4; ii++) p[ii] = Ss[(tg * 4 + ii) * 65 + j];
            #pragma unroll
            for (int cc = 0; cc < 8; cc++) vv[cc] = KVs[j * 129 + cc * 16 + tx];
            #pragma unroll
            for (int ii = 0; ii < 4; ii++)
                #pragma unroll
                for (int cc = 0; cc < 8; cc++)
                    oacc[ii][cc] = fmaf(p[ii], vv[cc], oacc[ii][cc]);
        }
    }

    #pragma unroll
    for (int ii = 0; ii < 4; ii++) {
        float inv = 1.0f / rl[tg * 4 + ii];
        #pragma unroll
        for (int cc = 0; cc < 8; cc++) {
            o[(size_t)(q0 + tg * 4 + ii) * DIM + h * HD + cc * 16 + tx] =
                oacc[ii][cc] * inv;
        }
    }
}

__global__ void copy_txt(const float* __restrict__ src, float* __restrict__ dst)
{
    int i = blockIdx.x * blockDim.x + threadIdx.x;
    if (i < STXT * DIM) dst[i] = src[i];
}

// ---------------------------------------------------------------------------
extern "C" void kernel_launch(void* const* d_in, const int* in_sizes, int n_in,
                              void* d_out, int out_size)
{
    const float* hidden = (const float*)d_in[0];
    const float* enc    = (const float*)d_in[1];
    const float* cosb   = (const float*)d_in[2];
    const float* sinb   = (const float*)d_in[3];
    const float* wq     = (const float*)d_in[4];
    const float* bq     = (const float*)d_in[5];
    const float* wk     = (const float*)d_in[6];
    const float* bk     = (const float*)d_in[7];
    const float* wv     = (const float*)d_in[8];
    const float* bv     = (const float*)d_in[9];
    const float* nqw    = (const float*)d_in[10];
    const float* nkw    = (const float*)d_in[11];
    const float* wo     = (const float*)d_in[12];
    const float* bo     = (const float*)d_in[13];
    float* out = (float*)d_out;

    float *pq, *pk, *pv, *po;
    __nv_bfloat16 *xhi, *xlo, *whi, *wlo;
    cudaGetSymbolAddress((void**)&pq, g_q);
    cudaGetSymbolAddress((void**)&pk, g_k);
    cudaGetSymbolAddress((void**)&pv, g_v);
    cudaGetSymbolAddress((void**)&po, g_o);
    cudaGetSymbolAddress((void**)&xhi, g_xhi);
    cudaGetSymbolAddress((void**)&xlo, g_xlo);
    cudaGetSymbolAddress((void**)&whi, g_whi);
    cudaGetSymbolAddress((void**)&wlo, g_wlo);

    const int gemm_smem = STG_E * 2 * 2;   // 75776 bytes
    cudaFuncSetAttribute(gemm_tc, cudaFuncAttributeMaxDynamicSharedMemorySize,
                         gemm_smem);
    const int attn_smem = (64 * 129 * 2 + 64 * 65 + 3 * 64) * (int)sizeof(float);
    cudaFuncSetAttribute(attn_kernel, cudaFuncAttributeMaxDynamicSharedMemorySize,
                         attn_smem);

    const int NW = DIM * DIM;          // weight elems
    const int conv_blk = 256;
    const int grid_w = (NW / 4 + conv_blk - 1) / conv_blk;

    // split-convert input (virtual concat of hidden + encoder)
    conv_split<<<(SIMG * DIM / 4 + 255) / 256, 256>>>(hidden, xhi, xlo, SIMG * DIM);
    conv_split<<<(STXT * DIM / 4 + 255) / 256, 256>>>(
        enc, xhi + (size_t)SIMG * DIM, xlo + (size_t)SIMG * DIM, STXT * DIM);

    // Q, K, V projections (tensor cores, split-bf16)
    dim3 gp(DIM / 128, STOT / 128);    // (24, 18)
    conv_split<<<grid_w, conv_blk>>>(wq, whi, wlo, NW);
    gemm_tc<<<gp, 256, gemm_smem>>>(xhi, xlo, whi, wlo, bq, pq);
    conv_split<<<grid_w, conv_blk>>>(wk, whi, wlo, NW);
    gemm_tc<<<gp, 256, gemm_smem>>>(xhi, xlo, whi, wlo, bk, pk);
    conv_split<<<grid_w, conv_blk>>>(wv, whi, wlo, NW);
    gemm_tc<<<gp, 256, gemm_smem>>>(xhi, xlo, whi, wlo, bv, pv);

    // per-head RMSNorm + RoPE
    dim3 gn(STOT, HEADS);
    rmsnorm_rope<<<gn, 128>>>(pq, nqw, cosb, sinb);
    rmsnorm_rope<<<gn, 128>>>(pk, nkw, cosb, sinb);

    // attention (fp32)
    dim3 ga(STOT / BQ, HEADS);         // (36, 24)
    attn_kernel<<<ga, 256, attn_smem>>>(pq, pk, pv, po);

    // output projection for image tokens (tensor cores)
    conv_split<<<(SIMG * DIM / 4 + 255) / 256, 256>>>(po, xhi, xlo, SIMG * DIM);
    conv_split<<<grid_w, conv_blk>>>(wo, whi, wlo, NW);
    dim3 go(DIM / 128, SIMG / 128);    // (24, 16)
    gemm_tc<<<go, 256, gemm_smem>>>(xhi, xlo, whi, wlo, bo, out);

    // raw copy of text tokens
    copy_txt<<<(STXT * DIM + 255) / 256, 256>>>(po + (size_t)SIMG * DIM,
                                                out + (size_t)SIMG * DIM);
}

// round 6
// speedup vs baseline: 4.7594x; 1.6800x over previous
#include <cuda_runtime.h>
#include <cuda_bf16.h>
#include <cstdint>
#include <math.h>

#define DIM 3072
#define HEADS 24
#define HD 128
#define SIMG 2048
#define STXT 256
#define STOT 2304

// ---------------------------------------------------------------------------
// scratch (static __device__ globals per allocation rules)
// ---------------------------------------------------------------------------
__device__ float g_q[(size_t)STOT * DIM];
__device__ float g_k[(size_t)STOT * DIM];
__device__ float g_v[(size_t)STOT * DIM];
__device__ float g_o[(size_t)STOT * DIM];
__device__ __nv_bfloat16 g_xhi[(size_t)STOT * DIM];
__device__ __nv_bfloat16 g_xlo[(size_t)STOT * DIM];
__device__ __nv_bfloat16 g_whi[(size_t)DIM * DIM];
__device__ __nv_bfloat16 g_wlo[(size_t)DIM * DIM];
__device__ __nv_bfloat16 g_qhi[(size_t)STOT * DIM];
__device__ __nv_bfloat16 g_qlo[(size_t)STOT * DIM];
__device__ __nv_bfloat16 g_khi[(size_t)STOT * DIM];
__device__ __nv_bfloat16 g_klo[(size_t)STOT * DIM];
__device__ __nv_bfloat16 g_vhi[(size_t)STOT * DIM];
__device__ __nv_bfloat16 g_vlo[(size_t)STOT * DIM];

// ---------------------------------------------------------------------------
// PTX helpers
// ---------------------------------------------------------------------------
__device__ __forceinline__ void cpa16(uint32_t s, const void* g) {
    asm volatile("cp.async.cg.shared.global [%0], [%1], 16;" :: "r"(s), "l"(g));
}
__device__ __forceinline__ void ldm_x4(uint32_t addr, uint32_t* r) {
    asm volatile("ldmatrix.sync.aligned.m8n8.x4.shared.b16 {%0,%1,%2,%3}, [%4];"
        : "=r"(r[0]), "=r"(r[1]), "=r"(r[2]), "=r"(r[3]) : "r"(addr));
}
__device__ __forceinline__ void ldm_x4t(uint32_t addr, uint32_t* r) {
    asm volatile("ldmatrix.sync.aligned.m8n8.x4.trans.shared.b16 {%0,%1,%2,%3}, [%4];"
        : "=r"(r[0]), "=r"(r[1]), "=r"(r[2]), "=r"(r[3]) : "r"(addr));
}
__device__ __forceinline__ void mma_bf16(float* d, const uint32_t* a,
                                         uint32_t b0, uint32_t b1) {
    asm volatile(
        "mma.sync.aligned.m16n8k16.row.col.f32.bf16.bf16.f32 "
        "{%0,%1,%2,%3}, {%4,%5,%6,%7}, {%8,%9}, {%0,%1,%2,%3};"
        : "+f"(d[0]), "+f"(d[1]), "+f"(d[2]), "+f"(d[3])
        : "r"(a[0]), "r"(a[1]), "r"(a[2]), "r"(a[3]), "r"(b0), "r"(b1));
}
// pack two floats into bf16x2 hi fragment + bf16x2 lo (residual) fragment
__device__ __forceinline__ void split2(float x, float y, uint32_t& h, uint32_t& l) {
    __nv_bfloat16 hx = __float2bfloat16(x), hy = __float2bfloat16(y);
    __nv_bfloat162 hh = __halves2bfloat162(hx, hy);
    h = *reinterpret_cast<uint32_t*>(&hh);
    __nv_bfloat162 ll = __floats2bfloat162_rn(x - __bfloat162float(hx),
                                              y - __bfloat162float(hy));
    l = *reinterpret_cast<uint32_t*>(&ll);
}

// ---------------------------------------------------------------------------
// split fp32 -> bf16 hi/lo.  n must be a multiple of 4.
// ---------------------------------------------------------------------------
__global__ void conv_split(const float* __restrict__ src,
                           __nv_bfloat16* __restrict__ hi,
                           __nv_bfloat16* __restrict__ lo, int n)
{
    int i = (blockIdx.x * blockDim.x + threadIdx.x) * 4;
    if (i >= n) return;
    float4 v = *(const float4*)(src + i);
    __nv_bfloat16 h0 = __float2bfloat16(v.x);
    __nv_bfloat16 h1 = __float2bfloat16(v.y);
    __nv_bfloat16 h2 = __float2bfloat16(v.z);
    __nv_bfloat16 h3 = __float2bfloat16(v.w);
    __nv_bfloat16 l0 = __float2bfloat16(v.x - __bfloat162float(h0));
    __nv_bfloat16 l1 = __float2bfloat16(v.y - __bfloat162float(h1));
    __nv_bfloat16 l2 = __float2bfloat16(v.z - __bfloat162float(h2));
    __nv_bfloat16 l3 = __float2bfloat16(v.w - __bfloat162float(h3));
    __nv_bfloat162* hp = (__nv_bfloat162*)(hi + i);
    __nv_bfloat162* lp = (__nv_bfloat162*)(lo + i);
    hp[0] = __halves2bfloat162(h0, h1);
    hp[1] = __halves2bfloat162(h2, h3);
    lp[0] = __halves2bfloat162(l0, l1);
    lp[1] = __halves2bfloat162(l2, l3);
}

// ---------------------------------------------------------------------------
// Tensor-core split-bf16 GEMM: C[M,3072] = A @ W + bias (fp32 accurate).
// ---------------------------------------------------------------------------
#define A_LO   5120          // elements: 128*40
#define B_HI   10240         // 2*5120
#define B_LO   14592         // B_HI + 32*136
#define STG_E  18944         // stage elements (37888 bytes)

__device__ __forceinline__ void load_stage(
    uint32_t sb, int tid, int bm, int bn, int k0,
    const __nv_bfloat16* Ahi, const __nv_bfloat16* Alo,
    const __nv_bfloat16* Bhi, const __nv_bfloat16* Blo)
{
    #pragma unroll
    for (int i = 0; i < 2; i++) {
        int c = tid + i * 256;
        int r = c >> 2, cc = (c & 3) * 8;
        size_t go = (size_t)(bm + r) * DIM + k0 + cc;
        cpa16(sb + (r * 40 + cc) * 2, Ahi + go);
        cpa16(sb + (A_LO + r * 40 + cc) * 2, Alo + go);
    }
    #pragma unroll
    for (int i = 0; i < 2; i++) {
        int c = tid + i * 256;
        int r = c >> 4, cc = (c & 15) * 8;
        size_t go = (size_t)(k0 + r) * DIM + bn + cc;
        cpa16(sb + (B_HI + r * 136 + cc) * 2, Bhi + go);
        cpa16(sb + (B_LO + r * 136 + cc) * 2, Blo + go);
    }
    asm volatile("cp.async.commit_group;" ::: "memory");
}

__global__ __launch_bounds__(256) void gemm_tc(
    const __nv_bfloat16* __restrict__ Ahi, const __nv_bfloat16* __restrict__ Alo,
    const __nv_bfloat16* __restrict__ Bhi, const __nv_bfloat16* __restrict__ Blo,
    const float* __restrict__ bias, float* __restrict__ C)
{
    extern __shared__ __nv_bfloat16 smbuf[];
    const int tid  = threadIdx.x;
    const int lane = tid & 31;
    const int wid  = tid >> 5;
    const int wm   = wid & 3;
    const int wn   = wid >> 2;
    const int bm   = blockIdx.y * 128;
    const int bn   = blockIdx.x * 128;
    uint32_t sb0 = (uint32_t)__cvta_generic_to_shared(smbuf);

    float acc[2][8][4] = {};

    load_stage(sb0, tid, bm, bn, 0, Ahi, Alo, Bhi, Blo);

    const int NIT = DIM / 32;
    for (int it = 0; it < NIT; it++) {
        if (it + 1 < NIT) {
            load_stage(sb0 + ((it + 1) & 1) * (STG_E * 2), tid, bm, bn,
                       (it + 1) * 32, Ahi, Alo, Bhi, Blo);
            asm volatile("cp.async.wait_group 1;" ::: "memory");
        } else {
            asm volatile("cp.async.wait_group 0;" ::: "memory");
        }
        __syncthreads();

        uint32_t sb = sb0 + (it & 1) * (STG_E * 2);
        #pragma unroll
        for (int kk = 0; kk < 32; kk += 16) {
            uint32_t ra_h[2][4];
            uint32_t ra_l[2][4];
            uint32_t rb_h[4][4];
            uint32_t rb_l[4][4];
            uint32_t arow = wm * 32 + (lane & 15);
            uint32_t aoff = (arow * 40 + kk + (lane >> 4) * 8) * 2;
            ldm_x4(sb + aoff, ra_h[0]);
            ldm_x4(sb + aoff + 16 * 40 * 2, ra_h[1]);
            ldm_x4(sb + A_LO * 2 + aoff, ra_l[0]);
            ldm_x4(sb + A_LO * 2 + aoff + 16 * 40 * 2, ra_l[1]);

            int g = lane >> 3;
            uint32_t brow = kk + (g & 1) * 8 + (lane & 7);
            #pragma unroll
            for (int ng = 0; ng < 4; ng++) {
                uint32_t col  = wn * 64 + ng * 16 + (g >> 1) * 8;
                uint32_t boff = (brow * 136 + col) * 2;
                ldm_x4t(sb + B_HI * 2 + boff, rb_h[ng]);
                ldm_x4t(sb + B_LO * 2 + boff, rb_l[ng]);
            }
            #pragma unroll
            for (int mi = 0; mi < 2; mi++) {
                #pragma unroll
                for (int t = 0; t < 8; t++) {
                    uint32_t bh0 = rb_h[t >> 1][(t & 1) * 2];
                    uint32_t bh1 = rb_h[t >> 1][(t & 1) * 2 + 1];
                    uint32_t bl0 = rb_l[t >> 1][(t & 1) * 2];
                    uint32_t bl1 = rb_l[t >> 1][(t & 1) * 2 + 1];
                    mma_bf16(acc[mi][t], ra_h[mi], bh0, bh1);
                    mma_bf16(acc[mi][t], ra_h[mi], bl0, bl1);
                    mma_bf16(acc[mi][t], ra_l[mi], bh0, bh1);
                }
            }
        }
        __syncthreads();
    }

    #pragma unroll
    for (int mi = 0; mi < 2; mi++) {
        int r0 = bm + wm * 32 + mi * 16 + (lane >> 2);
        #pragma unroll
        for (int t = 0; t < 8; t++) {
            int c = bn + wn * 64 + t * 8 + (lane & 3) * 2;
            C[(size_t)r0 * DIM + c]           = acc[mi][t][0] + bias[c];
            C[(size_t)r0 * DIM + c + 1]       = acc[mi][t][1] + bias[c + 1];
            C[(size_t)(r0 + 8) * DIM + c]     = acc[mi][t][2] + bias[c];
            C[(size_t)(r0 + 8) * DIM + c + 1] = acc[mi][t][3] + bias[c + 1];
        }
    }
}

// ---------------------------------------------------------------------------
// Fused per-head RMSNorm + RoPE + scale, writing split bf16 hi/lo.
// grid (STOT, HEADS), block 128.
// ---------------------------------------------------------------------------
__global__ void rmsnorm_rope_split(const float* __restrict__ in,
                                   const float* __restrict__ w,
                                   const float* __restrict__ cb,
                                   const float* __restrict__ sb,
                                   float scale,
                                   __nv_bfloat16* __restrict__ ohi,
                                   __nv_bfloat16* __restrict__ olo)
{
    const int s = blockIdx.x, h = blockIdx.y, d = threadIdx.x;
    const float* p = in + (size_t)s * DIM + h * HD;
    float val = p[d];

    float sq = val * val;
    #pragma unroll
    for (int off = 16; off; off >>= 1) sq += __shfl_xor_sync(0xffffffffu, sq, off);
    __shared__ float red[4];
    if ((d & 31) == 0) red[d >> 5] = sq;
    __syncthreads();
    float tot = red[0] + red[1] + red[2] + red[3];

    float n = val * rsqrtf(tot * (1.0f / HD) + 1e-6f) * w[d];

    __shared__ float nv[HD];
    nv[d] = n;
    __syncthreads();

    float outv = n;
    if (s < SIMG) {
        float c  = cb[s * HD + d];
        float si = sb[s * HD + d];
        float partner = (d & 1) ? nv[d - 1] : -nv[d + 1];
        outv = n * c + partner * si;
    }
    outv *= scale;

    size_t off = (size_t)s * DIM + h * HD + d;
    __nv_bfloat16 hi = __float2bfloat16(outv);
    ohi[off] = hi;
    olo[off] = __float2bfloat16(outv - __bfloat162float(hi));
}

// ---------------------------------------------------------------------------
// Flash attention, split-bf16 MMA, fp32 accumulators, register softmax.
// 128 threads (4 warps x 16 q-rows), BQ=64, BK=64, grid (36, 24).
// smem: Q/K/V hi+lo tiles, 64 x 136-padded bf16 each = 104448 bytes.
// ---------------------------------------------------------------------------
#define AQHI 0
#define AQLO 8704
#define AKHI 17408
#define AKLO 26112
#define AVHI 34816
#define AVLO 43520
#define ATT_SMEM (52224 * 2)

__global__ __launch_bounds__(128) void attn_mma(
    const __nv_bfloat16* __restrict__ qhi, const __nv_bfloat16* __restrict__ qlo,
    const __nv_bfloat16* __restrict__ khi, const __nv_bfloat16* __restrict__ klo,
    const __nv_bfloat16* __restrict__ vhi, const __nv_bfloat16* __restrict__ vlo,
    float* __restrict__ o_out)
{
    extern __shared__ __nv_bfloat16 sm2[];
    uint32_t sb = (uint32_t)__cvta_generic_to_shared(sm2);
    const int tid = threadIdx.x, lane = tid & 31, wid = tid >> 5;
    const int q0 = blockIdx.x * 64, h = blockIdx.y;

    // ---- load Q tile (once) + first K/V tile ----
    #pragma unroll
    for (int i = 0; i < 8; i++) {
        int idx = tid + i * 128, r = idx >> 4, c = (idx & 15) * 8;
        size_t go = (size_t)(q0 + r) * DIM + h * HD + c;
        uint32_t so = (uint32_t)(r * 136 + c) * 2;
        cpa16(sb + AQHI * 2 + so, qhi + go);
        cpa16(sb + AQLO * 2 + so, qlo + go);
    }
    #pragma unroll
    for (int i = 0; i < 8; i++) {
        int idx = tid + i * 128, r = idx >> 4, c = (idx & 15) * 8;
        size_t go = (size_t)r * DIM + h * HD + c;
        uint32_t so = (uint32_t)(r * 136 + c) * 2;
        cpa16(sb + AKHI * 2 + so, khi + go);
        cpa16(sb + AKLO * 2 + so, klo + go);
        cpa16(sb + AVHI * 2 + so, vhi + go);
        cpa16(sb + AVLO * 2 + so, vlo + go);
    }
    asm volatile("cp.async.commit_group;" ::: "memory");
    asm volatile("cp.async.wait_group 0;" ::: "memory");
    __syncthreads();

    float m0 = -1e30f, m1 = -1e30f, l0 = 0.f, l1 = 0.f;
    float oa[16][4] = {};

    // ldmatrix address components (constant per thread)
    const uint32_t aoff = (uint32_t)((wid * 16 + (lane & 15)) * 136 +
                                     ((lane >> 4) << 3)) * 2;         // Q (A, non-trans)
    const int brow = ((lane >> 4) << 3) + (lane & 7);                  // K (B, non-trans)
    const int bcol = ((lane >> 3) & 1) << 3;
    const int vrow = ((lane >> 3) & 1) * 8 + (lane & 7);               // V (B, trans)
    const int vcol = (lane >> 4) << 3;

    const int NIT = STOT / 64;   // 36
    for (int it = 0; it < NIT; it++) {
        // ---- S = Q @ K^T (pre-scaled Q) ----
        float sc[8][4] = {};
        #pragma unroll
        for (int ks = 0; ks < 8; ks++) {
            uint32_t qh[4], ql[4];
            ldm_x4(sb + AQHI * 2 + aoff + ks * 32, qh);
            ldm_x4(sb + AQLO * 2 + aoff + ks * 32, ql);
            #pragma unroll
            for (int bt = 0; bt < 4; bt++) {
                uint32_t kh[4], kl[4];
                uint32_t ko = (uint32_t)((bt * 16 + brow) * 136 + ks * 16 + bcol) * 2;
                ldm_x4(sb + AKHI * 2 + ko, kh);
                ldm_x4(sb + AKLO * 2 + ko, kl);
                mma_bf16(sc[2 * bt],     qh, kh[0], kh[1]);
                mma_bf16(sc[2 * bt],     qh, kl[0], kl[1]);
                mma_bf16(sc[2 * bt],     ql, kh[0], kh[1]);
                mma_bf16(sc[2 * bt + 1], qh, kh[2], kh[3]);
                mma_bf16(sc[2 * bt + 1], qh, kl[2], kl[3]);
                mma_bf16(sc[2 * bt + 1], ql, kh[2], kh[3]);
            }
        }

        // ---- online softmax in registers (rows r=lane>>2 and r+8) ----
        float mx0 = -1e30f, mx1 = -1e30f;
        #pragma unroll
        for (int nt = 0; nt < 8; nt++) {
            mx0 = fmaxf(mx0, fmaxf(sc[nt][0], sc[nt][1]));
            mx1 = fmaxf(mx1, fmaxf(sc[nt][2], sc[nt][3]));
        }
        mx0 = fmaxf(mx0, __shfl_xor_sync(0xffffffffu, mx0, 1));
        mx0 = fmaxf(mx0, __shfl_xor_sync(0xffffffffu, mx0, 2));
        mx1 = fmaxf(mx1, __shfl_xor_sync(0xffffffffu, mx1, 1));
        mx1 = fmaxf(mx1, __shfl_xor_sync(0xffffffffu, mx1, 2));
        float mn0 = fmaxf(m0, mx0), mn1 = fmaxf(m1, mx1);
        float c0 = __expf(m0 - mn0), c1 = __expf(m1 - mn1);
        float ls0 = 0.f, ls1 = 0.f;
        #pragma unroll
        for (int nt = 0; nt < 8; nt++) {
            sc[nt][0] = __expf(sc[nt][0] - mn0);
            sc[nt][1] = __expf(sc[nt][1] - mn0);
            sc[nt][2] = __expf(sc[nt][2] - mn1);
            sc[nt][3] = __expf(sc[nt][3] - mn1);
            ls0 += sc[nt][0] + sc[nt][1];
            ls1 += sc[nt][2] + sc[nt][3];
        }
        ls0 += __shfl_xor_sync(0xffffffffu, ls0, 1);
        ls0 += __shfl_xor_sync(0xffffffffu, ls0, 2);
        ls1 += __shfl_xor_sync(0xffffffffu, ls1, 1);
        ls1 += __shfl_xor_sync(0xffffffffu, ls1, 2);
        m0 = mn0; m1 = mn1;
        l0 = l0 * c0 + ls0;
        l1 = l1 * c1 + ls1;
        #pragma unroll
        for (int nt = 0; nt < 16; nt++) {
            oa[nt][0] *= c0; oa[nt][1] *= c0;
            oa[nt][2] *= c1; oa[nt][3] *= c1;
        }

        // ---- P: accumulator frags -> A frags (registers only), split hi/lo ----
        uint32_t ph[4][4], pl[4][4];
        #pragma unroll
        for (int t = 0; t < 4; t++) {
            split2(sc[2 * t][0],     sc[2 * t][1],     ph[t][0], pl[t][0]);
            split2(sc[2 * t][2],     sc[2 * t][3],     ph[t][1], pl[t][1]);
            split2(sc[2 * t + 1][0], sc[2 * t + 1][1], ph[t][2], pl[t][2]);
            split2(sc[2 * t + 1][2], sc[2 * t + 1][3], ph[t][3], pl[t][3]);
        }

        // ---- O += P @ V ----
        #pragma unroll
        for (int kst = 0; kst < 4; kst++) {
            #pragma unroll
            for (int dt = 0; dt < 8; dt++) {
                uint32_t vh[4], vl[4];
                uint32_t vo = (uint32_t)((kst * 16 + vrow) * 136 + dt * 16 + vcol) * 2;
                ldm_x4t(sb + AVHI * 2 + vo, vh);
                ldm_x4t(sb + AVLO * 2 + vo, vl);
                mma_bf16(oa[2 * dt],     ph[kst], vh[0], vh[1]);
                mma_bf16(oa[2 * dt],     ph[kst], vl[0], vl[1]);
                mma_bf16(oa[2 * dt],     pl[kst], vh[0], vh[1]);
                mma_bf16(oa[2 * dt + 1], ph[kst], vh[2], vh[3]);
                mma_bf16(oa[2 * dt + 1], ph[kst], vl[2], vl[3]);
                mma_bf16(oa[2 * dt + 1], pl[kst], vh[2], vh[3]);
            }
        }

        __syncthreads();        // everyone done reading K/V
        if (it + 1 < NIT) {
            int kt = (it + 1) * 64;
            #pragma unroll
            for (int i = 0; i < 8; i++) {
                int idx = tid + i * 128, r = idx >> 4, c = (idx & 15) * 8;
                size_t go = (size_t)(kt + r) * DIM + h * HD + c;
                uint32_t so = (uint32_t)(r * 136 + c) * 2;
                cpa16(sb + AKHI * 2 + so, khi + go);
                cpa16(sb + AKLO * 2 + so, klo + go);
                cpa16(sb + AVHI * 2 + so, vhi + go);
                cpa16(sb + AVLO * 2 + so, vlo + go);
            }
            asm volatile("cp.async.commit_group;" ::: "memory");
            asm volatile("cp.async.wait_group 0;" ::: "memory");
        }
        __syncthreads();
    }

    // ---- normalize + store fp32 ----
    float inv0 = 1.0f / l0, inv1 = 1.0f / l1;
    int r0 = q0 + wid * 16 + (lane >> 2);
    int cb0 = h * HD + (lane & 3) * 2;
    #pragma unroll
    for (int nt = 0; nt < 16; nt++) {
        float2 v0 = make_float2(oa[nt][0] * inv0, oa[nt][1] * inv0);
        float2 v1 = make_float2(oa[nt][2] * inv1, oa[nt][3] * inv1);
        *(float2*)(o_out + (size_t)r0 * DIM + cb0 + nt * 8)       = v0;
        *(float2*)(o_out + (size_t)(r0 + 8) * DIM + cb0 + nt * 8) = v1;
    }
}

__global__ void copy_txt(const float* __restrict__ src, float* __restrict__ dst)
{
    int i = blockIdx.x * blockDim.x + threadIdx.x;
    if (i < STXT * DIM) dst[i] = src[i];
}

// ---------------------------------------------------------------------------
extern "C" void kernel_launch(void* const* d_in, const int* in_sizes, int n_in,
                              void* d_out, int out_size)
{
    const float* hidden = (const float*)d_in[0];
    const float* enc    = (const float*)d_in[1];
    const float* cosb   = (const float*)d_in[2];
    const float* sinb   = (const float*)d_in[3];
    const float* wq     = (const float*)d_in[4];
    const float* bq     = (const float*)d_in[5];
    const float* wk     = (const float*)d_in[6];
    const float* bk     = (const float*)d_in[7];
    const float* wv     = (const float*)d_in[8];
    const float* bv     = (const float*)d_in[9];
    const float* nqw    = (const float*)d_in[10];
    const float* nkw    = (const float*)d_in[11];
    const float* wo     = (const float*)d_in[12];
    const float* bo     = (const float*)d_in[13];
    float* out = (float*)d_out;

    float *pq, *pk, *pv, *po;
    __nv_bfloat16 *xhi, *xlo, *whi, *wlo;
    __nv_bfloat16 *aqh, *aql, *akh, *akl, *avh, *avl;
    cudaGetSymbolAddress((void**)&pq, g_q);
    cudaGetSymbolAddress((void**)&pk, g_k);
    cudaGetSymbolAddress((void**)&pv, g_v);
    cudaGetSymbolAddress((void**)&po, g_o);
    cudaGetSymbolAddress((void**)&xhi, g_xhi);
    cudaGetSymbolAddress((void**)&xlo, g_xlo);
    cudaGetSymbolAddress((void**)&whi, g_whi);
    cudaGetSymbolAddress((void**)&wlo, g_wlo);
    cudaGetSymbolAddress((void**)&aqh, g_qhi);
    cudaGetSymbolAddress((void**)&aql, g_qlo);
    cudaGetSymbolAddress((void**)&akh, g_khi);
    cudaGetSymbolAddress((void**)&akl, g_klo);
    cudaGetSymbolAddress((void**)&avh, g_vhi);
    cudaGetSymbolAddress((void**)&avl, g_vlo);

    const int gemm_smem = STG_E * 2 * 2;   // 75776 bytes
    cudaFuncSetAttribute(gemm_tc, cudaFuncAttributeMaxDynamicSharedMemorySize,
                         gemm_smem);
    cudaFuncSetAttribute(attn_mma, cudaFuncAttributeMaxDynamicSharedMemorySize,
                         ATT_SMEM);

    const int NW = DIM * DIM;
    const int conv_blk = 256;
    const int grid_w = (NW / 4 + conv_blk - 1) / conv_blk;

    // split-convert input (virtual concat of hidden + encoder)
    conv_split<<<(SIMG * DIM / 4 + 255) / 256, 256>>>(hidden, xhi, xlo, SIMG * DIM);
    conv_split<<<(STXT * DIM / 4 + 255) / 256, 256>>>(
        enc, xhi + (size_t)SIMG * DIM, xlo + (size_t)SIMG * DIM, STXT * DIM);

    // Q, K, V projections (tensor cores, split-bf16)
    dim3 gp(DIM / 128, STOT / 128);    // (24, 18)
    conv_split<<<grid_w, conv_blk>>>(wq, whi, wlo, NW);
    gemm_tc<<<gp, 256, gemm_smem>>>(xhi, xlo, whi, wlo, bq, pq);
    conv_split<<<grid_w, conv_blk>>>(wk, whi, wlo, NW);
    gemm_tc<<<gp, 256, gemm_smem>>>(xhi, xlo, whi, wlo, bk, pk);
    conv_split<<<grid_w, conv_blk>>>(wv, whi, wlo, NW);
    gemm_tc<<<gp, 256, gemm_smem>>>(xhi, xlo, whi, wlo, bv, pv);

    // per-head RMSNorm + RoPE -> split bf16 (scale folded into Q)
    dim3 gn(STOT, HEADS);
    rmsnorm_rope_split<<<gn, 128>>>(pq, nqw, cosb, sinb,
                                    0.08838834764831845f, aqh, aql);
    rmsnorm_rope_split<<<gn, 128>>>(pk, nkw, cosb, sinb, 1.0f, akh, akl);
    conv_split<<<(STOT * DIM / 4 + 255) / 256, 256>>>(pv, avh, avl, STOT * DIM);

    // attention (tensor cores, split-bf16)
    dim3 ga(STOT / 64, HEADS);         // (36, 24)
    attn_mma<<<ga, 128, ATT_SMEM>>>(aqh, aql, akh, akl, avh, avl, po);

    // output projection for image tokens (tensor cores)
    conv_split<<<(SIMG * DIM / 4 + 255) / 256, 256>>>(po, xhi, xlo, SIMG * DIM);
    conv_split<<<grid_w, conv_blk>>>(wo, whi, wlo, NW);
    dim3 go(DIM / 128, SIMG / 128);    // (24, 16)
    gemm_tc<<<go, 256, gemm_smem>>>(xhi, xlo, whi, wlo, bo, out);

    // raw copy of text tokens
    copy_txt<<<(STXT * DIM + 255) / 256, 256>>>(po + (size_t)SIMG * DIM,
                                                out + (size_t)SIMG * DIM);
}

// round 7
// speedup vs baseline: 5.3001x; 1.1136x over previous
#include <cuda_runtime.h>
#include <cuda_bf16.h>
#include <cstdint>
#include <math.h>

#define DIM 3072
#define HEADS 24
#define HD 128
#define SIMG 2048
#define STXT 256
#define STOT 2304

// ---------------------------------------------------------------------------
// scratch (static __device__ globals per allocation rules)
// ---------------------------------------------------------------------------
__device__ float g_q[(size_t)STOT * DIM];
__device__ float g_k[(size_t)STOT * DIM];
__device__ float g_v[(size_t)STOT * DIM];
__device__ float g_o[(size_t)STOT * DIM];
__device__ __nv_bfloat16 g_xhi[(size_t)STOT * DIM];
__device__ __nv_bfloat16 g_xlo[(size_t)STOT * DIM];
__device__ __nv_bfloat16 g_whi[(size_t)4 * DIM * DIM];   // 4 weight slots
__device__ __nv_bfloat16 g_wlo[(size_t)4 * DIM * DIM];
__device__ __nv_bfloat16 g_qhi[(size_t)STOT * DIM];
__device__ __nv_bfloat16 g_qlo[(size_t)STOT * DIM];
__device__ __nv_bfloat16 g_khi[(size_t)STOT * DIM];
__device__ __nv_bfloat16 g_klo[(size_t)STOT * DIM];
__device__ __nv_bfloat16 g_vhi[(size_t)STOT * DIM];
__device__ __nv_bfloat16 g_vlo[(size_t)STOT * DIM];

// ---------------------------------------------------------------------------
// PTX helpers
// ---------------------------------------------------------------------------
__device__ __forceinline__ void cpa16(uint32_t s, const void* g) {
    asm volatile("cp.async.cg.shared.global [%0], [%1], 16;" :: "r"(s), "l"(g));
}
__device__ __forceinline__ void ldm_x4(uint32_t addr, uint32_t* r) {
    asm volatile("ldmatrix.sync.aligned.m8n8.x4.shared.b16 {%0,%1,%2,%3}, [%4];"
        : "=r"(r[0]), "=r"(r[1]), "=r"(r[2]), "=r"(r[3]) : "r"(addr));
}
__device__ __forceinline__ void ldm_x4t(uint32_t addr, uint32_t* r) {
    asm volatile("ldmatrix.sync.aligned.m8n8.x4.trans.shared.b16 {%0,%1,%2,%3}, [%4];"
        : "=r"(r[0]), "=r"(r[1]), "=r"(r[2]), "=r"(r[3]) : "r"(addr));
}
__device__ __forceinline__ void mma_bf16(float* d, const uint32_t* a,
                                         uint32_t b0, uint32_t b1) {
    asm volatile(
        "mma.sync.aligned.m16n8k16.row.col.f32.bf16.bf16.f32 "
        "{%0,%1,%2,%3}, {%4,%5,%6,%7}, {%8,%9}, {%0,%1,%2,%3};"
        : "+f"(d[0]), "+f"(d[1]), "+f"(d[2]), "+f"(d[3])
        : "r"(a[0]), "r"(a[1]), "r"(a[2]), "r"(a[3]), "r"(b0), "r"(b1));
}
// pack two floats into bf16x2 hi fragment + bf16x2 lo (residual) fragment
__device__ __forceinline__ void split2(float x, float y, uint32_t& h, uint32_t& l) {
    __nv_bfloat16 hx = __float2bfloat16(x), hy = __float2bfloat16(y);
    __nv_bfloat162 hh = __halves2bfloat162(hx, hy);
    h = *reinterpret_cast<uint32_t*>(&hh);
    __nv_bfloat162 ll = __floats2bfloat162_rn(x - __bfloat162float(hx),
                                              y - __bfloat162float(hy));
    l = *reinterpret_cast<uint32_t*>(&ll);
}

// ---------------------------------------------------------------------------
// split fp32 -> bf16 hi/lo.  n must be a multiple of 4.
// ---------------------------------------------------------------------------
__global__ void conv_split(const float* __restrict__ src,
                           __nv_bfloat16* __restrict__ hi,
                           __nv_bfloat16* __restrict__ lo, int n)
{
    int i = (blockIdx.x * blockDim.x + threadIdx.x) * 4;
    if (i >= n) return;
    float4 v = *(const float4*)(src + i);
    __nv_bfloat16 h0 = __float2bfloat16(v.x);
    __nv_bfloat16 h1 = __float2bfloat16(v.y);
    __nv_bfloat16 h2 = __float2bfloat16(v.z);
    __nv_bfloat16 h3 = __float2bfloat16(v.w);
    __nv_bfloat16 l0 = __float2bfloat16(v.x - __bfloat162float(h0));
    __nv_bfloat16 l1 = __float2bfloat16(v.y - __bfloat162float(h1));
    __nv_bfloat16 l2 = __float2bfloat16(v.z - __bfloat162float(h2));
    __nv_bfloat16 l3 = __float2bfloat16(v.w - __bfloat162float(h3));
    __nv_bfloat162* hp = (__nv_bfloat162*)(hi + i);
    __nv_bfloat162* lp = (__nv_bfloat162*)(lo + i);
    hp[0] = __halves2bfloat162(h0, h1);
    hp[1] = __halves2bfloat162(h2, h3);
    lp[0] = __halves2bfloat162(l0, l1);
    lp[1] = __halves2bfloat162(l2, l3);
}

// ---------------------------------------------------------------------------
// Tensor-core split-bf16 GEMM: C[M,3072] = A @ W + bias (fp32 accurate).
// 128x128 block tile, BK=32, 256 threads (8 warps, 4x2), warp tile 32x64.
// cp.async double-buffered smem; 3 mma terms: hi*hi + hi*lo + lo*hi.
// __launch_bounds__(256,2): cap regs at 128 -> 2 CTAs/SM for latency hiding.
// ---------------------------------------------------------------------------
#define A_LO   5120          // elements: 128*40
#define B_HI   10240         // 2*5120
#define B_LO   14592         // B_HI + 32*136
#define STG_E  18944         // stage elements (37888 bytes)

__device__ __forceinline__ void load_stage(
    uint32_t sb, int tid, int bm, int bn, int k0,
    const __nv_bfloat16* Ahi, const __nv_bfloat16* Alo,
    const __nv_bfloat16* Bhi, const __nv_bfloat16* Blo)
{
    #pragma unroll
    for (int i = 0; i < 2; i++) {
        int c = tid + i * 256;
        int r = c >> 2, cc = (c & 3) * 8;
        size_t go = (size_t)(bm + r) * DIM + k0 + cc;
        cpa16(sb + (r * 40 + cc) * 2, Ahi + go);
        cpa16(sb + (A_LO + r * 40 + cc) * 2, Alo + go);
    }
    #pragma unroll
    for (int i = 0; i < 2; i++) {
        int c = tid + i * 256;
        int r = c >> 4, cc = (c & 15) * 8;
        size_t go = (size_t)(k0 + r) * DIM + bn + cc;
        cpa16(sb + (B_HI + r * 136 + cc) * 2, Bhi + go);
        cpa16(sb + (B_LO + r * 136 + cc) * 2, Blo + go);
    }
    asm volatile("cp.async.commit_group;" ::: "memory");
}

__global__ __launch_bounds__(256, 2) void gemm_tc(
    const __nv_bfloat16* __restrict__ Ahi, const __nv_bfloat16* __restrict__ Alo,
    const __nv_bfloat16* __restrict__ Bhi, const __nv_bfloat16* __restrict__ Blo,
    const float* __restrict__ bias, float* __restrict__ C)
{
    extern __shared__ __nv_bfloat16 smbuf[];
    const int tid  = threadIdx.x;
    const int lane = tid & 31;
    const int wid  = tid >> 5;
    const int wm   = wid & 3;
    const int wn   = wid >> 2;
    const int bm   = blockIdx.y * 128;
    const int bn   = blockIdx.x * 128;
    uint32_t sb0 = (uint32_t)__cvta_generic_to_shared(smbuf);

    float acc[2][8][4] = {};

    load_stage(sb0, tid, bm, bn, 0, Ahi, Alo, Bhi, Blo);

    const int NIT = DIM / 32;
    for (int it = 0; it < NIT; it++) {
        if (it + 1 < NIT) {
            load_stage(sb0 + ((it + 1) & 1) * (STG_E * 2), tid, bm, bn,
                       (it + 1) * 32, Ahi, Alo, Bhi, Blo);
            asm volatile("cp.async.wait_group 1;" ::: "memory");
        } else {
            asm volatile("cp.async.wait_group 0;" ::: "memory");
        }
        __syncthreads();

        uint32_t sb = sb0 + (it & 1) * (STG_E * 2);
        #pragma unroll
        for (int kk = 0; kk < 32; kk += 16) {
            // A fragments for this k-step (16 regs live)
            uint32_t ra_h[2][4];
            uint32_t ra_l[2][4];
            uint32_t arow = wm * 32 + (lane & 15);
            uint32_t aoff = (arow * 40 + kk + (lane >> 4) * 8) * 2;
            ldm_x4(sb + aoff, ra_h[0]);
            ldm_x4(sb + aoff + 16 * 40 * 2, ra_h[1]);
            ldm_x4(sb + A_LO * 2 + aoff, ra_l[0]);
            ldm_x4(sb + A_LO * 2 + aoff + 16 * 40 * 2, ra_l[1]);

            int g = lane >> 3;
            uint32_t brow = kk + (g & 1) * 8 + (lane & 7);
            // B fragments loaded per-ng and consumed immediately (8 regs live)
            #pragma unroll
            for (int ng = 0; ng < 4; ng++) {
                uint32_t rb_h[4], rb_l[4];
                uint32_t col  = wn * 64 + ng * 16 + (g >> 1) * 8;
                uint32_t boff = (brow * 136 + col) * 2;
                ldm_x4t(sb + B_HI * 2 + boff, rb_h);
                ldm_x4t(sb + B_LO * 2 + boff, rb_l);
                #pragma unroll
                for (int mi = 0; mi < 2; mi++) {
                    int t0 = 2 * ng, t1 = 2 * ng + 1;
                    mma_bf16(acc[mi][t0], ra_h[mi], rb_h[0], rb_h[1]);
                    mma_bf16(acc[mi][t0], ra_h[mi], rb_l[0], rb_l[1]);
                    mma_bf16(acc[mi][t0], ra_l[mi], rb_h[0], rb_h[1]);
                    mma_bf16(acc[mi][t1], ra_h[mi], rb_h[2], rb_h[3]);
                    mma_bf16(acc[mi][t1], ra_h[mi], rb_l[2], rb_l[3]);
                    mma_bf16(acc[mi][t1], ra_l[mi], rb_h[2], rb_h[3]);
                }
            }
        }
        __syncthreads();
    }

    #pragma unroll
    for (int mi = 0; mi < 2; mi++) {
        int r0 = bm + wm * 32 + mi * 16 + (lane >> 2);
        #pragma unroll
        for (int t = 0; t < 8; t++) {
            int c = bn + wn * 64 + t * 8 + (lane & 3) * 2;
            C[(size_t)r0 * DIM + c]           = acc[mi][t][0] + bias[c];
            C[(size_t)r0 * DIM + c + 1]       = acc[mi][t][1] + bias[c + 1];
            C[(size_t)(r0 + 8) * DIM + c]     = acc[mi][t][2] + bias[c];
            C[(size_t)(r0 + 8) * DIM + c + 1] = acc[mi][t][3] + bias[c + 1];
        }
    }
}

// ---------------------------------------------------------------------------
// Fused per-head RMSNorm + RoPE + scale, writing split bf16 hi/lo.
// ---------------------------------------------------------------------------
__global__ void rmsnorm_rope_split(const float* __restrict__ in,
                                   const float* __restrict__ w,
                                   const float* __restrict__ cb,
                                   const float* __restrict__ sb,
                                   float scale,
                                   __nv_bfloat16* __restrict__ ohi,
                                   __nv_bfloat16* __restrict__ olo)
{
    const int s = blockIdx.x, h = blockIdx.y, d = threadIdx.x;
    const float* p = in + (size_t)s * DIM + h * HD;
    float val = p[d];

    float sq = val * val;
    #pragma unroll
    for (int off = 16; off; off >>= 1) sq += __shfl_xor_sync(0xffffffffu, sq, off);
    __shared__ float red[4];
    if ((d & 31) == 0) red[d >> 5] = sq;
    __syncthreads();
    float tot = red[0] + red[1] + red[2] + red[3];

    float n = val * rsqrtf(tot * (1.0f / HD) + 1e-6f) * w[d];

    __shared__ float nv[HD];
    nv[d] = n;
    __syncthreads();

    float outv = n;
    if (s < SIMG) {
        float c  = cb[s * HD + d];
        float si = sb[s * HD + d];
        float partner = (d & 1) ? nv[d - 1] : -nv[d + 1];
        outv = n * c + partner * si;
    }
    outv *= scale;

    size_t off = (size_t)s * DIM + h * HD + d;
    __nv_bfloat16 hi = __float2bfloat16(outv);
    ohi[off] = hi;
    olo[off] = __float2bfloat16(outv - __bfloat162float(hi));
}

// ---------------------------------------------------------------------------
// Flash attention, split-bf16 MMA, fp32 accumulators, register softmax.
// 128 threads (4 warps x 16 q-rows), BQ=64, BK=64, grid (36, 24).
// ---------------------------------------------------------------------------
#define AQHI 0
#define AQLO 8704
#define AKHI 17408
#define AKLO 26112
#define AVHI 34816
#define AVLO 43520
#define ATT_SMEM (52224 * 2)

__global__ __launch_bounds__(128) void attn_mma(
    const __nv_bfloat16* __restrict__ qhi, const __nv_bfloat16* __restrict__ qlo,
    const __nv_bfloat16* __restrict__ khi, const __nv_bfloat16* __restrict__ klo,
    const __nv_bfloat16* __restrict__ vhi, const __nv_bfloat16* __restrict__ vlo,
    float* __restrict__ o_out)
{
    extern __shared__ __nv_bfloat16 sm2[];
    uint32_t sb = (uint32_t)__cvta_generic_to_shared(sm2);
    const int tid = threadIdx.x, lane = tid & 31, wid = tid >> 5;
    const int q0 = blockIdx.x * 64, h = blockIdx.y;

    #pragma unroll
    for (int i = 0; i < 8; i++) {
        int idx = tid + i * 128, r = idx >> 4, c = (idx & 15) * 8;
        size_t go = (size_t)(q0 + r) * DIM + h * HD + c;
        uint32_t so = (uint32_t)(r * 136 + c) * 2;
        cpa16(sb + AQHI * 2 + so, qhi + go);
        cpa16(sb + AQLO * 2 + so, qlo + go);
    }
    #pragma unroll
    for (int i = 0; i < 8; i++) {
        int idx = tid + i * 128, r = idx >> 4, c = (idx & 15) * 8;
        size_t go = (size_t)r * DIM + h * HD + c;
        uint32_t so = (uint32_t)(r * 136 + c) * 2;
        cpa16(sb + AKHI * 2 + so, khi + go);
        cpa16(sb + AKLO * 2 + so, klo + go);
        cpa16(sb + AVHI * 2 + so, vhi + go);
        cpa16(sb + AVLO * 2 + so, vlo + go);
    }
    asm volatile("cp.async.commit_group;" ::: "memory");
    asm volatile("cp.async.wait_group 0;" ::: "memory");
    __syncthreads();

    float m0 = -1e30f, m1 = -1e30f, l0 = 0.f, l1 = 0.f;
    float oa[16][4] = {};

    const uint32_t aoff = (uint32_t)((wid * 16 + (lane & 15)) * 136 +
                                     ((lane >> 4) << 3)) * 2;
    const int brow = ((lane >> 4) << 3) + (lane & 7);
    const int bcol = ((lane >> 3) & 1) << 3;
    const int vrow = ((lane >> 3) & 1) * 8 + (lane & 7);
    const int vcol = (lane >> 4) << 3;

    const int NIT = STOT / 64;
    for (int it = 0; it < NIT; it++) {
        float sc[8][4] = {};
        #pragma unroll
        for (int ks = 0; ks < 8; ks++) {
            uint32_t qh[4], ql[4];
            ldm_x4(sb + AQHI * 2 + aoff + ks * 32, qh);
            ldm_x4(sb + AQLO * 2 + aoff + ks * 32, ql);
            #pragma unroll
            for (int bt = 0; bt < 4; bt++) {
                uint32_t kh[4], kl[4];
                uint32_t ko = (uint32_t)((bt * 16 + brow) * 136 + ks * 16 + bcol) * 2;
                ldm_x4(sb + AKHI * 2 + ko, kh);
                ldm_x4(sb + AKLO * 2 + ko, kl);
                mma_bf16(sc[2 * bt],     qh, kh[0], kh[1]);
                mma_bf16(sc[2 * bt],     qh, kl[0], kl[1]);
                mma_bf16(sc[2 * bt],     ql, kh[0], kh[1]);
                mma_bf16(sc[2 * bt + 1], qh, kh[2], kh[3]);
                mma_bf16(sc[2 * bt + 1], qh, kl[2], kl[3]);
                mma_bf16(sc[2 * bt + 1], ql, kh[2], kh[3]);
            }
        }

        float mx0 = -1e30f, mx1 = -1e30f;
        #pragma unroll
        for (int nt = 0; nt < 8; nt++) {
            mx0 = fmaxf(mx0, fmaxf(sc[nt][0], sc[nt][1]));
            mx1 = fmaxf(mx1, fmaxf(sc[nt][2], sc[nt][3]));
        }
        mx0 = fmaxf(mx0, __shfl_xor_sync(0xffffffffu, mx0, 1));
        mx0 = fmaxf(mx0, __shfl_xor_sync(0xffffffffu, mx0, 2));
        mx1 = fmaxf(mx1, __shfl_xor_sync(0xffffffffu, mx1, 1));
        mx1 = fmaxf(mx1, __shfl_xor_sync(0xffffffffu, mx1, 2));
        float mn0 = fmaxf(m0, mx0), mn1 = fmaxf(m1, mx1);
        float c0 = __expf(m0 - mn0), c1 = __expf(m1 - mn1);
        float ls0 = 0.f, ls1 = 0.f;
        #pragma unroll
        for (int nt = 0; nt < 8; nt++) {
            sc[nt][0] = __expf(sc[nt][0] - mn0);
            sc[nt][1] = __expf(sc[nt][1] - mn0);
            sc[nt][2] = __expf(sc[nt][2] - mn1);
            sc[nt][3] = __expf(sc[nt][3] - mn1);
            ls0 += sc[nt][0] + sc[nt][1];
            ls1 += sc[nt][2] + sc[nt][3];
        }
        ls0 += __shfl_xor_sync(0xffffffffu, ls0, 1);
        ls0 += __shfl_xor_sync(0xffffffffu, ls0, 2);
        ls1 += __shfl_xor_sync(0xffffffffu, ls1, 1);
        ls1 += __shfl_xor_sync(0xffffffffu, ls1, 2);
        m0 = mn0; m1 = mn1;
        l0 = l0 * c0 + ls0;
        l1 = l1 * c1 + ls1;
        #pragma unroll
        for (int nt = 0; nt < 16; nt++) {
            oa[nt][0] *= c0; oa[nt][1] *= c0;
            oa[nt][2] *= c1; oa[nt][3] *= c1;
        }

        uint32_t ph[4][4], pl[4][4];
        #pragma unroll
        for (int t = 0; t < 4; t++) {
            split2(sc[2 * t][0],     sc[2 * t][1],     ph[t][0], pl[t][0]);
            split2(sc[2 * t][2],     sc[2 * t][3],     ph[t][1], pl[t][1]);
            split2(sc[2 * t + 1][0], sc[2 * t + 1][1], ph[t][2], pl[t][2]);
            split2(sc[2 * t + 1][2], sc[2 * t + 1][3], ph[t][3], pl[t][3]);
        }

        #pragma unroll
        for (int kst = 0; kst < 4; kst++) {
            #pragma unroll
            for (int dt = 0; dt < 8; dt++) {
                uint32_t vh[4], vl[4];
                uint32_t vo = (uint32_t)((kst * 16 + vrow) * 136 + dt * 16 + vcol) * 2;
                ldm_x4t(sb + AVHI * 2 + vo, vh);
                ldm_x4t(sb + AVLO * 2 + vo, vl);
                mma_bf16(oa[2 * dt],     ph[kst], vh[0], vh[1]);
                mma_bf16(oa[2 * dt],     ph[kst], vl[0], vl[1]);
                mma_bf16(oa[2 * dt],     pl[kst], vh[0], vh[1]);
                mma_bf16(oa[2 * dt + 1], ph[kst], vh[2], vh[3]);
                mma_bf16(oa[2 * dt + 1], ph[kst], vl[2], vl[3]);
                mma_bf16(oa[2 * dt + 1], pl[kst], vh[2], vh[3]);
            }
        }

        __syncthreads();
        if (it + 1 < NIT) {
            int kt = (it + 1) * 64;
            #pragma unroll
            for (int i = 0; i < 8; i++) {
                int idx = tid + i * 128, r = idx >> 4, c = (idx & 15) * 8;
                size_t go = (size_t)(kt + r) * DIM + h * HD + c;
                uint32_t so = (uint32_t)(r * 136 + c) * 2;
                cpa16(sb + AKHI * 2 + so, khi + go);
                cpa16(sb + AKLO * 2 + so, klo + go);
                cpa16(sb + AVHI * 2 + so, vhi + go);
                cpa16(sb + AVLO * 2 + so, vlo + go);
            }
            asm volatile("cp.async.commit_group;" ::: "memory");
            asm volatile("cp.async.wait_group 0;" ::: "memory");
        }
        __syncthreads();
    }

    float inv0 = 1.0f / l0, inv1 = 1.0f / l1;
    int r0 = q0 + wid * 16 + (lane >> 2);
    int cb0 = h * HD + (lane & 3) * 2;
    #pragma unroll
    for (int nt = 0; nt < 16; nt++) {
        float2 v0 = make_float2(oa[nt][0] * inv0, oa[nt][1] * inv0);
        float2 v1 = make_float2(oa[nt][2] * inv1, oa[nt][3] * inv1);
        *(float2*)(o_out + (size_t)r0 * DIM + cb0 + nt * 8)       = v0;
        *(float2*)(o_out + (size_t)(r0 + 8) * DIM + cb0 + nt * 8) = v1;
    }
}

__global__ void copy_txt(const float* __restrict__ src, float* __restrict__ dst)
{
    int i = blockIdx.x * blockDim.x + threadIdx.x;
    if (i < STXT * DIM) dst[i] = src[i];
}

// ---------------------------------------------------------------------------
extern "C" void kernel_launch(void* const* d_in, const int* in_sizes, int n_in,
                              void* d_out, int out_size)
{
    const float* hidden = (const float*)d_in[0];
    const float* enc    = (const float*)d_in[1];
    const float* cosb   = (const float*)d_in[2];
    const float* sinb   = (const float*)d_in[3];
    const float* wq     = (const float*)d_in[4];
    const float* bq     = (const float*)d_in[5];
    const float* wk     = (const float*)d_in[6];
    const float* bk     = (const float*)d_in[7];
    const float* wv     = (const float*)d_in[8];
    const float* bv     = (const float*)d_in[9];
    const float* nqw    = (const float*)d_in[10];
    const float* nkw    = (const float*)d_in[11];
    const float* wo     = (const float*)d_in[12];
    const float* bo     = (const float*)d_in[13];
    float* out = (float*)d_out;

    float *pq, *pk, *pv, *po;
    __nv_bfloat16 *xhi, *xlo, *whi, *wlo;
    __nv_bfloat16 *aqh, *aql, *akh, *akl, *avh, *avl;
    cudaGetSymbolAddress((void**)&pq, g_q);
    cudaGetSymbolAddress((void**)&pk, g_k);
    cudaGetSymbolAddress((void**)&pv, g_v);
    cudaGetSymbolAddress((void**)&po, g_o);
    cudaGetSymbolAddress((void**)&xhi, g_xhi);
    cudaGetSymbolAddress((void**)&xlo, g_xlo);
    cudaGetSymbolAddress((void**)&whi, g_whi);
    cudaGetSymbolAddress((void**)&wlo, g_wlo);
    cudaGetSymbolAddress((void**)&aqh, g_qhi);
    cudaGetSymbolAddress((void**)&aql, g_qlo);
    cudaGetSymbolAddress((void**)&akh, g_khi);
    cudaGetSymbolAddress((void**)&akl, g_klo);
    cudaGetSymbolAddress((void**)&avh, g_vhi);
    cudaGetSymbolAddress((void**)&avl, g_vlo);

    const int gemm_smem = STG_E * 2 * 2;   // 75776 bytes
    cudaFuncSetAttribute(gemm_tc, cudaFuncAttributeMaxDynamicSharedMemorySize,
                         gemm_smem);
    cudaFuncSetAttribute(attn_mma, cudaFuncAttributeMaxDynamicSharedMemorySize,
                         ATT_SMEM);

    const size_t NW = (size_t)DIM * DIM;
    const int conv_blk = 256;
    const int grid_w = (int)((NW / 4 + conv_blk - 1) / conv_blk);

    // --- all conversions up front (no conv/gemm serialization bubbles) ---
    conv_split<<<(SIMG * DIM / 4 + 255) / 256, 256>>>(hidden, xhi, xlo, SIMG * DIM);
    conv_split<<<(STXT * DIM / 4 + 255) / 256, 256>>>(
        enc, xhi + (size_t)SIMG * DIM, xlo + (size_t)SIMG * DIM, STXT * DIM);
    conv_split<<<grid_w, conv_blk>>>(wq, whi + 0 * NW, wlo + 0 * NW, (int)NW);
    conv_split<<<grid_w, conv_blk>>>(wk, whi + 1 * NW, wlo + 1 * NW, (int)NW);
    conv_split<<<grid_w, conv_blk>>>(wv, whi + 2 * NW, wlo + 2 * NW, (int)NW);
    conv_split<<<grid_w, conv_blk>>>(wo, whi + 3 * NW, wlo + 3 * NW, (int)NW);

    // Q, K, V projections (tensor cores, split-bf16)
    dim3 gp(DIM / 128, STOT / 128);    // (24, 18)
    gemm_tc<<<gp, 256, gemm_smem>>>(xhi, xlo, whi + 0 * NW, wlo + 0 * NW, bq, pq);
    gemm_tc<<<gp, 256, gemm_smem>>>(xhi, xlo, whi + 1 * NW, wlo + 1 * NW, bk, pk);
    gemm_tc<<<gp, 256, gemm_smem>>>(xhi, xlo, whi + 2 * NW, wlo + 2 * NW, bv, pv);

    // per-head RMSNorm + RoPE -> split bf16 (scale folded into Q)
    dim3 gn(STOT, HEADS);
    rmsnorm_rope_split<<<gn, 128>>>(pq, nqw, cosb, sinb,
                                    0.08838834764831845f, aqh, aql);
    rmsnorm_rope_split<<<gn, 128>>>(pk, nkw, cosb, sinb, 1.0f, akh, akl);
    conv_split<<<(STOT * DIM / 4 + 255) / 256, 256>>>(pv, avh, avl, STOT * DIM);

    // attention (tensor cores, split-bf16)
    dim3 ga(STOT / 64, HEADS);         // (36, 24)
    attn_mma<<<ga, 128, ATT_SMEM>>>(aqh, aql, akh, akl, avh, avl, po);

    // output projection for image tokens (tensor cores)
    conv_split<<<(SIMG * DIM / 4 + 255) / 256, 256>>>(po, xhi, xlo, SIMG * DIM);
    dim3 go(DIM / 128, SIMG / 128);    // (24, 16)
    gemm_tc<<<go, 256, gemm_smem>>>(xhi, xlo, whi + 3 * NW, wlo + 3 * NW, bo, out);

    // raw copy of text tokens
    copy_txt<<<(STXT * DIM + 255) / 256, 256>>>(po + (size_t)SIMG * DIM,
                                                out + (size_t)SIMG * DIM);
}

// round 9
// speedup vs baseline: 5.3381x; 1.0072x over previous
#include <cuda_runtime.h>
#include <cuda_bf16.h>
#include <cstdint>
#include <math.h>

#define DIM 3072
#define HEADS 24
#define HD 128
#define SIMG 2048
#define STXT 256
#define STOT 2304

// ---------------------------------------------------------------------------
// scratch (static __device__ globals per allocation rules)
// ---------------------------------------------------------------------------
__device__ float g_q[(size_t)STOT * DIM];
__device__ float g_k[(size_t)STOT * DIM];
__device__ float g_v[(size_t)STOT * DIM];
__device__ float g_o[(size_t)STOT * DIM];
__device__ __nv_bfloat16 g_xhi[(size_t)STOT * DIM];
__device__ __nv_bfloat16 g_xlo[(size_t)STOT * DIM];
__device__ __nv_bfloat16 g_whi[(size_t)4 * DIM * DIM];   // 4 weight slots
__device__ __nv_bfloat16 g_wlo[(size_t)4 * DIM * DIM];
__device__ __nv_bfloat16 g_qhi[(size_t)STOT * DIM];
__device__ __nv_bfloat16 g_qlo[(size_t)STOT * DIM];
__device__ __nv_bfloat16 g_khi[(size_t)STOT * DIM];
__device__ __nv_bfloat16 g_klo[(size_t)STOT * DIM];
__device__ __nv_bfloat16 g_vhi[(size_t)STOT * DIM];
__device__ __nv_bfloat16 g_vlo[(size_t)STOT * DIM];

// ---------------------------------------------------------------------------
// PTX helpers
// ---------------------------------------------------------------------------
__device__ __forceinline__ void cpa16(uint32_t s, const void* g) {
    asm volatile("cp.async.cg.shared.global [%0], [%1], 16;" :: "r"(s), "l"(g));
}
__device__ __forceinline__ void ldm_x4(uint32_t addr, uint32_t* r) {
    asm volatile("ldmatrix.sync.aligned.m8n8.x4.shared.b16 {%0,%1,%2,%3}, [%4];"
        : "=r"(r[0]), "=r"(r[1]), "=r"(r[2]), "=r"(r[3]) : "r"(addr));
}
__device__ __forceinline__ void ldm_x4t(uint32_t addr, uint32_t* r) {
    asm volatile("ldmatrix.sync.aligned.m8n8.x4.trans.shared.b16 {%0,%1,%2,%3}, [%4];"
        : "=r"(r[0]), "=r"(r[1]), "=r"(r[2]), "=r"(r[3]) : "r"(addr));
}
__device__ __forceinline__ void mma_bf16(float* d, const uint32_t* a,
                                         uint32_t b0, uint32_t b1) {
    asm volatile(
        "mma.sync.aligned.m16n8k16.row.col.f32.bf16.bf16.f32 "
        "{%0,%1,%2,%3}, {%4,%5,%6,%7}, {%8,%9}, {%0,%1,%2,%3};"
        : "+f"(d[0]), "+f"(d[1]), "+f"(d[2]), "+f"(d[3])
        : "r"(a[0]), "r"(a[1]), "r"(a[2]), "r"(a[3]), "r"(b0), "r"(b1));
}
// pack two floats into bf16x2 hi fragment + bf16x2 lo (residual) fragment
__device__ __forceinline__ void split2(float x, float y, uint32_t& h, uint32_t& l) {
    __nv_bfloat16 hx = __float2bfloat16(x), hy = __float2bfloat16(y);
    __nv_bfloat162 hh = __halves2bfloat162(hx, hy);
    h = *reinterpret_cast<uint32_t*>(&hh);
    __nv_bfloat162 ll = __floats2bfloat162_rn(x - __bfloat162float(hx),
                                              y - __bfloat162float(hy));
    l = *reinterpret_cast<uint32_t*>(&ll);
}

// ---------------------------------------------------------------------------
// split fp32 -> bf16 hi/lo, 8 elements / thread, 16B stores.
// n must be a multiple of 8.
// ---------------------------------------------------------------------------
__global__ void conv_split8(const float* __restrict__ src,
                            __nv_bfloat16* __restrict__ hi,
                            __nv_bfloat16* __restrict__ lo, int n)
{
    int i = (blockIdx.x * blockDim.x + threadIdx.x) * 8;
    if (i >= n) return;
    float4 v0 = *(const float4*)(src + i);
    float4 v1 = *(const float4*)(src + i + 4);
    uint32_t h[4], l[4];
    split2(v0.x, v0.y, h[0], l[0]);
    split2(v0.z, v0.w, h[1], l[1]);
    split2(v1.x, v1.y, h[2], l[2]);
    split2(v1.z, v1.w, h[3], l[3]);
    *(uint4*)(hi + i) = make_uint4(h[0], h[1], h[2], h[3]);
    *(uint4*)(lo + i) = make_uint4(l[0], l[1], l[2], l[3]);
}

// ---------------------------------------------------------------------------
// Tensor-core split-bf16 GEMM body: C[128,128 tile] = A @ W + bias.
// 128x128 block tile, BK=32, 256 threads (8 warps, 4x2), warp tile 32x64.
// cp.async double-buffered smem; 3 mma terms: hi*hi + hi*lo + lo*hi.
// ---------------------------------------------------------------------------
#define A_LO   5120          // elements: 128*40
#define B_HI   10240         // 2*5120
#define B_LO   14592         // B_HI + 32*136
#define STG_E  18944         // stage elements (37888 bytes)

__device__ __forceinline__ void load_stage(
    uint32_t sb, int tid, int bm, int bn, int k0,
    const __nv_bfloat16* Ahi, const __nv_bfloat16* Alo,
    const __nv_bfloat16* Bhi, const __nv_bfloat16* Blo)
{
    #pragma unroll
    for (int i = 0; i < 2; i++) {
        int c = tid + i * 256;
        int r = c >> 2, cc = (c & 3) * 8;
        size_t go = (size_t)(bm + r) * DIM + k0 + cc;
        cpa16(sb + (r * 40 + cc) * 2, Ahi + go);
        cpa16(sb + (A_LO + r * 40 + cc) * 2, Alo + go);
    }
    #pragma unroll
    for (int i = 0; i < 2; i++) {
        int c = tid + i * 256;
        int r = c >> 4, cc = (c & 15) * 8;
        size_t go = (size_t)(k0 + r) * DIM + bn + cc;
        cpa16(sb + (B_HI + r * 136 + cc) * 2, Bhi + go);
        cpa16(sb + (B_LO + r * 136 + cc) * 2, Blo + go);
    }
    asm volatile("cp.async.commit_group;" ::: "memory");
}

__device__ __forceinline__ void gemm_body(
    const __nv_bfloat16* __restrict__ Ahi, const __nv_bfloat16* __restrict__ Alo,
    const __nv_bfloat16* __restrict__ Bhi, const __nv_bfloat16* __restrict__ Blo,
    const float* __restrict__ bias, float* __restrict__ C, int bm, int bn)
{
    extern __shared__ __nv_bfloat16 smbuf[];
    const int tid  = threadIdx.x;
    const int lane = tid & 31;
    const int wid  = tid >> 5;
    const int wm   = wid & 3;
    const int wn   = wid >> 2;
    uint32_t sb0 = (uint32_t)__cvta_generic_to_shared(smbuf);

    float acc[2][8][4] = {};

    load_stage(sb0, tid, bm, bn, 0, Ahi, Alo, Bhi, Blo);

    const int NIT = DIM / 32;
    for (int it = 0; it < NIT; it++) {
        if (it + 1 < NIT) {
            load_stage(sb0 + ((it + 1) & 1) * (STG_E * 2), tid, bm, bn,
                       (it + 1) * 32, Ahi, Alo, Bhi, Blo);
            asm volatile("cp.async.wait_group 1;" ::: "memory");
        } else {
            asm volatile("cp.async.wait_group 0;" ::: "memory");
        }
        __syncthreads();

        uint32_t sb = sb0 + (it & 1) * (STG_E * 2);
        #pragma unroll
        for (int kk = 0; kk < 32; kk += 16) {
            uint32_t ra_h[2][4];
            uint32_t ra_l[2][4];
            uint32_t arow = wm * 32 + (lane & 15);
            uint32_t aoff = (arow * 40 + kk + (lane >> 4) * 8) * 2;
            ldm_x4(sb + aoff, ra_h[0]);
            ldm_x4(sb + aoff + 16 * 40 * 2, ra_h[1]);
            ldm_x4(sb + A_LO * 2 + aoff, ra_l[0]);
            ldm_x4(sb + A_LO * 2 + aoff + 16 * 40 * 2, ra_l[1]);

            int g = lane >> 3;
            uint32_t brow = kk + (g & 1) * 8 + (lane & 7);
            #pragma unroll
            for (int ng = 0; ng < 4; ng++) {
                uint32_t rb_h[4], rb_l[4];
                uint32_t col  = wn * 64 + ng * 16 + (g >> 1) * 8;
                uint32_t boff = (brow * 136 + col) * 2;
                ldm_x4t(sb + B_HI * 2 + boff, rb_h);
                ldm_x4t(sb + B_LO * 2 + boff, rb_l);
                #pragma unroll
                for (int mi = 0; mi < 2; mi++) {
                    int t0 = 2 * ng, t1 = 2 * ng + 1;
                    mma_bf16(acc[mi][t0], ra_h[mi], rb_h[0], rb_h[1]);
                    mma_bf16(acc[mi][t0], ra_h[mi], rb_l[0], rb_l[1]);
                    mma_bf16(acc[mi][t0], ra_l[mi], rb_h[0], rb_h[1]);
                    mma_bf16(acc[mi][t1], ra_h[mi], rb_h[2], rb_h[3]);
                    mma_bf16(acc[mi][t1], ra_h[mi], rb_l[2], rb_l[3]);
                    mma_bf16(acc[mi][t1], ra_l[mi], rb_h[2], rb_h[3]);
                }
            }
        }
        __syncthreads();
    }

    #pragma unroll
    for (int mi = 0; mi < 2; mi++) {
        int r0 = bm + wm * 32 + mi * 16 + (lane >> 2);
        #pragma unroll
        for (int t = 0; t < 8; t++) {
            int c = bn + wn * 64 + t * 8 + (lane & 3) * 2;
            C[(size_t)r0 * DIM + c]           = acc[mi][t][0] + bias[c];
            C[(size_t)r0 * DIM + c + 1]       = acc[mi][t][1] + bias[c + 1];
            C[(size_t)(r0 + 8) * DIM + c]     = acc[mi][t][2] + bias[c];
            C[(size_t)(r0 + 8) * DIM + c + 1] = acc[mi][t][3] + bias[c + 1];
        }
    }
}

// single-weight GEMM (O projection)
__global__ __launch_bounds__(256, 2) void gemm_tc(
    const __nv_bfloat16* __restrict__ Ahi, const __nv_bfloat16* __restrict__ Alo,
    const __nv_bfloat16* __restrict__ Bhi, const __nv_bfloat16* __restrict__ Blo,
    const float* __restrict__ bias, float* __restrict__ C)
{
    gemm_body(Ahi, Alo, Bhi, Blo, bias, C, blockIdx.y * 128, blockIdx.x * 128);
}

// fused QKV GEMM: grid.x = 72 (3 weights x 24 column tiles), one wave train
__global__ __launch_bounds__(256, 2) void gemm_qkv(
    const __nv_bfloat16* __restrict__ Ahi, const __nv_bfloat16* __restrict__ Alo,
    const __nv_bfloat16* __restrict__ WhiBase, const __nv_bfloat16* __restrict__ WloBase,
    const float* __restrict__ bq, const float* __restrict__ bk,
    const float* __restrict__ bv,
    float* __restrict__ pq, float* __restrict__ pk, float* __restrict__ pv)
{
    const int sel = blockIdx.x / 24;
    const int bn  = (blockIdx.x % 24) * 128;
    const size_t NW = (size_t)DIM * DIM;
    const __nv_bfloat16* Bhi = WhiBase + (size_t)sel * NW;
    const __nv_bfloat16* Blo = WloBase + (size_t)sel * NW;
    const float* bias = (sel == 0) ? bq : (sel == 1) ? bk : bv;
    float* C = (sel == 0) ? pq : (sel == 1) ? pk : pv;
    gemm_body(Ahi, Alo, Bhi, Blo, bias, C, blockIdx.y * 128, bn);
}

// ---------------------------------------------------------------------------
// Fused per-head RMSNorm + RoPE + scale, writing split bf16 hi/lo.
// ---------------------------------------------------------------------------
__global__ void rmsnorm_rope_split(const float* __restrict__ in,
                                   const float* __restrict__ w,
                                   const float* __restrict__ cb,
                                   const float* __restrict__ sb,
                                   float scale,
                                   __nv_bfloat16* __restrict__ ohi,
                                   __nv_bfloat16* __restrict__ olo)
{
    const int s = blockIdx.x, h = blockIdx.y, d = threadIdx.x;
    const float* p = in + (size_t)s * DIM + h * HD;
    float val = p[d];

    float sq = val * val;
    #pragma unroll
    for (int off = 16; off; off >>= 1) sq += __shfl_xor_sync(0xffffffffu, sq, off);
    __shared__ float red[4];
    if ((d & 31) == 0) red[d >> 5] = sq;
    __syncthreads();
    float tot = red[0] + red[1] + red[2] + red[3];

    float n = val * rsqrtf(tot * (1.0f / HD) + 1e-6f) * w[d];

    __shared__ float nv[HD];
    nv[d] = n;
    __syncthreads();

    float outv = n;
    if (s < SIMG) {
        float c  = cb[s * HD + d];
        float si = sb[s * HD + d];
        float partner = (d & 1) ? nv[d - 1] : -nv[d + 1];
        outv = n * c + partner * si;
    }
    outv *= scale;

    size_t off = (size_t)s * DIM + h * HD + d;
    __nv_bfloat16 hi = __float2bfloat16(outv);
    ohi[off] = hi;
    olo[off] = __float2bfloat16(outv - __bfloat162float(hi));
}

// ---------------------------------------------------------------------------
// Flash attention, split-bf16 MMA, fp32 accumulators, register softmax.
// Epilogue writes split-bf16 (for O-proj) + fp32 for txt rows only.
// ---------------------------------------------------------------------------
#define AQHI 0
#define AQLO 8704
#define AKHI 17408
#define AKLO 26112
#define AVHI 34816
#define AVLO 43520
#define ATT_SMEM (52224 * 2)

__global__ __launch_bounds__(128) void attn_mma(
    const __nv_bfloat16* __restrict__ qhi, const __nv_bfloat16* __restrict__ qlo,
    const __nv_bfloat16* __restrict__ khi, const __nv_bfloat16* __restrict__ klo,
    const __nv_bfloat16* __restrict__ vhi, const __nv_bfloat16* __restrict__ vlo,
    __nv_bfloat16* __restrict__ ohi, __nv_bfloat16* __restrict__ olo,
    float* __restrict__ o_f32)
{
    extern __shared__ __nv_bfloat16 sm2[];
    uint32_t sb = (uint32_t)__cvta_generic_to_shared(sm2);
    const int tid = threadIdx.x, lane = tid & 31, wid = tid >> 5;
    const int q0 = blockIdx.x * 64, h = blockIdx.y;

    #pragma unroll
    for (int i = 0; i < 8; i++) {
        int idx = tid + i * 128, r = idx >> 4, c = (idx & 15) * 8;
        size_t go = (size_t)(q0 + r) * DIM + h * HD + c;
        uint32_t so = (uint32_t)(r * 136 + c) * 2;
        cpa16(sb + AQHI * 2 + so, qhi + go);
        cpa16(sb + AQLO * 2 + so, qlo + go);
    }
    #pragma unroll
    for (int i = 0; i < 8; i++) {
        int idx = tid + i * 128, r = idx >> 4, c = (idx & 15) * 8;
        size_t go = (size_t)r * DIM + h * HD + c;
        uint32_t so = (uint32_t)(r * 136 + c) * 2;
        cpa16(sb + AKHI * 2 + so, khi + go);
        cpa16(sb + AKLO * 2 + so, klo + go);
        cpa16(sb + AVHI * 2 + so, vhi + go);
        cpa16(sb + AVLO * 2 + so, vlo + go);
    }
    asm volatile("cp.async.commit_group;" ::: "memory");
    asm volatile("cp.async.wait_group 0;" ::: "memory");
    __syncthreads();

    float m0 = -1e30f, m1 = -1e30f, l0 = 0.f, l1 = 0.f;
    float oa[16][4] = {};

    const uint32_t aoff = (uint32_t)((wid * 16 + (lane & 15)) * 136 +
                                     ((lane >> 4) << 3)) * 2;
    const int brow = ((lane >> 4) << 3) + (lane & 7);
    const int bcol = ((lane >> 3) & 1) << 3;
    const int vrow = ((lane >> 3) & 1) * 8 + (lane & 7);
    const int vcol = (lane >> 4) << 3;

    const int NIT = STOT / 64;
    for (int it = 0; it < NIT; it++) {
        float sc[8][4] = {};
        #pragma unroll
        for (int ks = 0; ks < 8; ks++) {
            uint32_t qh[4], ql[4];
            ldm_x4(sb + AQHI * 2 + aoff + ks * 32, qh);
            ldm_x4(sb + AQLO * 2 + aoff + ks * 32, ql);
            #pragma unroll
            for (int bt = 0; bt < 4; bt++) {
                uint32_t kh[4], kl[4];
                uint32_t ko = (uint32_t)((bt * 16 + brow) * 136 + ks * 16 + bcol) * 2;
                ldm_x4(sb + AKHI * 2 + ko, kh);
                ldm_x4(sb + AKLO * 2 + ko, kl);
                mma_bf16(sc[2 * bt],     qh, kh[0], kh[1]);
                mma_bf16(sc[2 * bt],     qh, kl[0], kl[1]);
                mma_bf16(sc[2 * bt],     ql, kh[0], kh[1]);
                mma_bf16(sc[2 * bt + 1], qh, kh[2], kh[3]);
                mma_bf16(sc[2 * bt + 1], qh, kl[2], kl[3]);
                mma_bf16(sc[2 * bt + 1], ql, kh[2], kh[3]);
            }
        }

        float mx0 = -1e30f, mx1 = -1e30f;
        #pragma unroll
        for (int nt = 0; nt < 8; nt++) {
            mx0 = fmaxf(mx0, fmaxf(sc[nt][0], sc[nt][1]));
            mx1 = fmaxf(mx1, fmaxf(sc[nt][2], sc[nt][3]));
        }
        mx0 = fmaxf(mx0, __shfl_xor_sync(0xffffffffu, mx0, 1));
        mx0 = fmaxf(mx0, __shfl_xor_sync(0xffffffffu, mx0, 2));
        mx1 = fmaxf(mx1, __shfl_xor_sync(0xffffffffu, mx1, 1));
        mx1 = fmaxf(mx1, __shfl_xor_sync(0xffffffffu, mx1, 2));
        float mn0 = fmaxf(m0, mx0), mn1 = fmaxf(m1, mx1);
        float c0 = __expf(m0 - mn0), c1 = __expf(m1 - mn1);
        float ls0 = 0.f, ls1 = 0.f;
        #pragma unroll
        for (int nt = 0; nt < 8; nt++) {
            sc[nt][0] = __expf(sc[nt][0] - mn0);
            sc[nt][1] = __expf(sc[nt][1] - mn0);
            sc[nt][2] = __expf(sc[nt][2] - mn1);
            sc[nt][3] = __expf(sc[nt][3] - mn1);
            ls0 += sc[nt][0] + sc[nt][1];
            ls1 += sc[nt][2] + sc[nt][3];
        }
        ls0 += __shfl_xor_sync(0xffffffffu, ls0, 1);
        ls0 += __shfl_xor_sync(0xffffffffu, ls0, 2);
        ls1 += __shfl_xor_sync(0xffffffffu, ls1, 1);
        ls1 += __shfl_xor_sync(0xffffffffu, ls1, 2);
        m0 = mn0; m1 = mn1;
        l0 = l0 * c0 + ls0;
        l1 = l1 * c1 + ls1;
        #pragma unroll
        for (int nt = 0; nt < 16; nt++) {
            oa[nt][0] *= c0; oa[nt][1] *= c0;
            oa[nt][2] *= c1; oa[nt][3] *= c1;
        }

        uint32_t ph[4][4], pl[4][4];
        #pragma unroll
        for (int t = 0; t < 4; t++) {
            split2(sc[2 * t][0],     sc[2 * t][1],     ph[t][0], pl[t][0]);
            split2(sc[2 * t][2],     sc[2 * t][3],     ph[t][1], pl[t][1]);
            split2(sc[2 * t + 1][0], sc[2 * t + 1][1], ph[t][2], pl[t][2]);
            split2(sc[2 * t + 1][2], sc[2 * t + 1][3], ph[t][3], pl[t][3]);
        }

        #pragma unroll
        for (int kst = 0; kst < 4; kst++) {
            #pragma unroll
            for (int dt = 0; dt < 8; dt++) {
                uint32_t vh[4], vl[4];
                uint32_t vo = (uint32_t)((kst * 16 + vrow) * 136 + dt * 16 + vcol) * 2;
                ldm_x4t(sb + AVHI * 2 + vo, vh);
                ldm_x4t(sb + AVLO * 2 + vo, vl);
                mma_bf16(oa[2 * dt],     ph[kst], vh[0], vh[1]);
                mma_bf16(oa[2 * dt],     ph[kst], vl[0], vl[1]);
                mma_bf16(oa[2 * dt],     pl[kst], vh[0], vh[1]);
                mma_bf16(oa[2 * dt + 1], ph[kst], vh[2], vh[3]);
                mma_bf16(oa[2 * dt + 1], ph[kst], vl[2], vl[3]);
                mma_bf16(oa[2 * dt + 1], pl[kst], vh[2], vh[3]);
            }
        }

        __syncthreads();
        if (it + 1 < NIT) {
            int kt = (it + 1) * 64;
            #pragma unroll
            for (int i = 0; i < 8; i++) {
                int idx = tid + i * 128, r = idx >> 4, c = (idx & 15) * 8;
                size_t go = (size_t)(kt + r) * DIM + h * HD + c;
                uint32_t so = (uint32_t)(r * 136 + c) * 2;
                cpa16(sb + AKHI * 2 + so, khi + go);
                cpa16(sb + AKLO * 2 + so, klo + go);
                cpa16(sb + AVHI * 2 + so, vhi + go);
                cpa16(sb + AVLO * 2 + so, vlo + go);
            }
            asm volatile("cp.async.commit_group;" ::: "memory");
            asm volatile("cp.async.wait_group 0;" ::: "memory");
        }
        __syncthreads();
    }

    // ---- normalize + store: split bf16 always, fp32 only for txt rows ----
    float inv0 = 1.0f / l0, inv1 = 1.0f / l1;
    int r0 = q0 + wid * 16 + (lane >> 2);
    int cb0 = h * HD + (lane & 3) * 2;
    const bool wr32 = (q0 >= SIMG);
    #pragma unroll
    for (int nt = 0; nt < 16; nt++) {
        float a0 = oa[nt][0] * inv0, a1 = oa[nt][1] * inv0;
        float a2 = oa[nt][2] * inv1, a3 = oa[nt][3] * inv1;
        uint32_t h0, lo0, h1, lo1;
        split2(a0, a1, h0, lo0);
        split2(a2, a3, h1, lo1);
        size_t off0 = (size_t)r0 * DIM + cb0 + nt * 8;
        size_t off1 = (size_t)(r0 + 8) * DIM + cb0 + nt * 8;
        *(uint32_t*)(ohi + off0) = h0;
        *(uint32_t*)(olo + off0) = lo0;
        *(uint32_t*)(ohi + off1) = h1;
        *(uint32_t*)(olo + off1) = lo1;
        if (wr32) {
            *(float2*)(o_f32 + off0) = make_float2(a0, a1);
            *(float2*)(o_f32 + off1) = make_float2(a2, a3);
        }
    }
}

__global__ void copy_txt(const float* __restrict__ src, float* __restrict__ dst)
{
    int i = blockIdx.x * blockDim.x + threadIdx.x;
    if (i < STXT * DIM) dst[i] = src[i];
}

// ---------------------------------------------------------------------------
extern "C" void kernel_launch(void* const* d_in, const int* in_sizes, int n_in,
                              void* d_out, int out_size)
{
    const float* hidden = (const float*)d_in[0];
    const float* enc    = (const float*)d_in[1];
    const float* cosb   = (const float*)d_in[2];
    const float* sinb   = (const float*)d_in[3];
    const float* wq     = (const float*)d_in[4];
    const float* bq     = (const float*)d_in[5];
    const float* wk     = (const float*)d_in[6];
    const float* bk     = (const float*)d_in[7];
    const float* wv     = (const float*)d_in[8];
    const float* bv     = (const float*)d_in[9];
    const float* nqw    = (const float*)d_in[10];
    const float* nkw    = (const float*)d_in[11];
    const float* wo     = (const float*)d_in[12];
    const float* bo     = (const float*)d_in[13];
    float* out = (float*)d_out;

    float *pq, *pk, *pv, *po;
    __nv_bfloat16 *xhi, *xlo, *whi, *wlo;
    __nv_bfloat16 *aqh, *aql, *akh, *akl, *avh, *avl;
    cudaGetSymbolAddress((void**)&pq, g_q);
    cudaGetSymbolAddress((void**)&pk, g_k);
    cudaGetSymbolAddress((void**)&pv, g_v);
    cudaGetSymbolAddress((void**)&po, g_o);
    cudaGetSymbolAddress((void**)&xhi, g_xhi);
    cudaGetSymbolAddress((void**)&xlo, g_xlo);
    cudaGetSymbolAddress((void**)&whi, g_whi);
    cudaGetSymbolAddress((void**)&wlo, g_wlo);
    cudaGetSymbolAddress((void**)&aqh, g_qhi);
    cudaGetSymbolAddress((void**)&aql, g_qlo);
    cudaGetSymbolAddress((void**)&akh, g_khi);
    cudaGetSymbolAddress((void**)&akl, g_klo);
    cudaGetSymbolAddress((void**)&avh, g_vhi);
    cudaGetSymbolAddress((void**)&avl, g_vlo);

    const int gemm_smem = STG_E * 2 * 2;   // 75776 bytes
    cudaFuncSetAttribute(gemm_tc, cudaFuncAttributeMaxDynamicSharedMemorySize,
                         gemm_smem);
    cudaFuncSetAttribute(gemm_qkv, cudaFuncAttributeMaxDynamicSharedMemorySize,
                         gemm_smem);
    cudaFuncSetAttribute(attn_mma, cudaFuncAttributeMaxDynamicSharedMemorySize,
                         ATT_SMEM);

    const size_t NW = (size_t)DIM * DIM;
    const int conv_blk = 256;
    const int grid_w = (int)((NW / 8 + conv_blk - 1) / conv_blk);

    // --- all conversions up front ---
    conv_split8<<<(SIMG * DIM / 8 + 255) / 256, 256>>>(hidden, xhi, xlo, SIMG * DIM);
    conv_split8<<<(STXT * DIM / 8 + 255) / 256, 256>>>(
        enc, xhi + (size_t)SIMG * DIM, xlo + (size_t)SIMG * DIM, STXT * DIM);
    conv_split8<<<grid_w, conv_blk>>>(wq, whi + 0 * NW, wlo + 0 * NW, (int)NW);
    conv_split8<<<grid_w, conv_blk>>>(wk, whi + 1 * NW, wlo + 1 * NW, (int)NW);
    conv_split8<<<grid_w, conv_blk>>>(wv, whi + 2 * NW, wlo + 2 * NW, (int)NW);
    conv_split8<<<grid_w, conv_blk>>>(wo, whi + 3 * NW, wlo + 3 * NW, (int)NW);

    // fused Q, K, V projections: one launch, 1296 CTAs
    dim3 gq(72, STOT / 128);           // (72, 18)
    gemm_qkv<<<gq, 256, gemm_smem>>>(xhi, xlo, whi, wlo, bq, bk, bv, pq, pk, pv);

    // per-head RMSNorm + RoPE -> split bf16 (scale folded into Q)
    dim3 gn(STOT, HEADS);
    rmsnorm_rope_split<<<gn, 128>>>(pq, nqw, cosb, sinb,
                                    0.08838834764831845f, aqh, aql);
    rmsnorm_rope_split<<<gn, 128>>>(pk, nkw, cosb, sinb, 1.0f, akh, akl);
    conv_split8<<<(STOT * DIM / 8 + 255) / 256, 256>>>(pv, avh, avl, STOT * DIM);

    // attention (tensor cores, split-bf16) -> writes split output directly
    dim3 ga(STOT / 64, HEADS);         // (36, 24)
    attn_mma<<<ga, 128, ATT_SMEM>>>(aqh, aql, akh, akl, avh, avl,
                                    xhi, xlo, po);

    // output projection for image tokens (tensor cores)
    dim3 go(DIM / 128, SIMG / 128);    // (24, 16)
    gemm_tc<<<go, 256, gemm_smem>>>(xhi, xlo, whi + 3 * NW, wlo + 3 * NW, bo, out);

    // raw copy of text tokens
    copy_txt<<<(STXT * DIM + 255) / 256, 256>>>(po + (size_t)SIMG * DIM,
                                                out + (size_t)SIMG * DIM);
}

// round 11
// speedup vs baseline: 7.4096x; 1.3881x over previous
#include <cuda_runtime.h>
#include <cuda_fp16.h>
#include <cstdint>
#include <math.h>

#define DIM 3072
#define HEADS 24
#define HD 128
#define SIMG 2048
#define STXT 256
#define STOT 2304

// ---------------------------------------------------------------------------
// scratch (static __device__ globals per allocation rules)
// ---------------------------------------------------------------------------
__device__ float g_q[(size_t)STOT * DIM];
__device__ float g_k[(size_t)STOT * DIM];
__device__ float g_v[(size_t)STOT * DIM];
__device__ float g_o[(size_t)STOT * DIM];
__device__ __half g_xhi[(size_t)STOT * DIM];
__device__ __half g_xlo[(size_t)STOT * DIM];
__device__ __half g_whi[(size_t)4 * DIM * DIM];   // 4 weight slots, hi only
__device__ __half g_qhi[(size_t)STOT * DIM];
__device__ __half g_qlo[(size_t)STOT * DIM];
__device__ __half g_khi[(size_t)STOT * DIM];
__device__ __half g_klo[(size_t)STOT * DIM];      // written, unused (K is B-side)
__device__ __half g_vhi[(size_t)STOT * DIM];

// ---------------------------------------------------------------------------
// PTX helpers
// ---------------------------------------------------------------------------
__device__ __forceinline__ void cpa16(uint32_t s, const void* g) {
    asm volatile("cp.async.cg.shared.global [%0], [%1], 16;" :: "r"(s), "l"(g));
}
__device__ __forceinline__ void ldm_x4(uint32_t addr, uint32_t* r) {
    asm volatile("ldmatrix.sync.aligned.m8n8.x4.shared.b16 {%0,%1,%2,%3}, [%4];"
        : "=r"(r[0]), "=r"(r[1]), "=r"(r[2]), "=r"(r[3]) : "r"(addr));
}
__device__ __forceinline__ void ldm_x4t(uint32_t addr, uint32_t* r) {
    asm volatile("ldmatrix.sync.aligned.m8n8.x4.trans.shared.b16 {%0,%1,%2,%3}, [%4];"
        : "=r"(r[0]), "=r"(r[1]), "=r"(r[2]), "=r"(r[3]) : "r"(addr));
}
__device__ __forceinline__ void mma_f16(float* d, const uint32_t* a,
                                        uint32_t b0, uint32_t b1) {
    asm volatile(
        "mma.sync.aligned.m16n8k16.row.col.f32.f16.f16.f32 "
        "{%0,%1,%2,%3}, {%4,%5,%6,%7}, {%8,%9}, {%0,%1,%2,%3};"
        : "+f"(d[0]), "+f"(d[1]), "+f"(d[2]), "+f"(d[3])
        : "r"(a[0]), "r"(a[1]), "r"(a[2]), "r"(a[3]), "r"(b0), "r"(b1));
}
// pack two floats into fp16x2 hi fragment + fp16x2 lo (residual) fragment
__device__ __forceinline__ void split2h(float x, float y, uint32_t& h, uint32_t& l) {
    __half hx = __float2half_rn(x), hy = __float2half_rn(y);
    __half2 hh = __halves2half2(hx, hy);
    h = *reinterpret_cast<uint32_t*>(&hh);
    __half2 ll = __floats2half2_rn(x - __half2float(hx), y - __half2float(hy));
    l = *reinterpret_cast<uint32_t*>(&ll);
}
__device__ __forceinline__ uint32_t pack2h(float x, float y) {
    __half2 hh = __floats2half2_rn(x, y);
    return *reinterpret_cast<uint32_t*>(&hh);
}

// ---------------------------------------------------------------------------
// fp32 -> fp16 hi/lo split, 8 elems/thread
// ---------------------------------------------------------------------------
__global__ void conv_split8(const float* __restrict__ src,
                            __half* __restrict__ hi,
                            __half* __restrict__ lo, int n)
{
    int i = (blockIdx.x * blockDim.x + threadIdx.x) * 8;
    if (i >= n) return;
    float4 v0 = *(const float4*)(src + i);
    float4 v1 = *(const float4*)(src + i + 4);
    uint32_t h[4], l[4];
    split2h(v0.x, v0.y, h[0], l[0]);
    split2h(v0.z, v0.w, h[1], l[1]);
    split2h(v1.x, v1.y, h[2], l[2]);
    split2h(v1.z, v1.w, h[3], l[3]);
    *(uint4*)(hi + i) = make_uint4(h[0], h[1], h[2], h[3]);
    *(uint4*)(lo + i) = make_uint4(l[0], l[1], l[2], l[3]);
}

// fp32 -> fp16 hi only, 8 elems/thread (B-side operands)
__global__ void conv_hi8(const float* __restrict__ src,
                         __half* __restrict__ hi, int n)
{
    int i = (blockIdx.x * blockDim.x + threadIdx.x) * 8;
    if (i >= n) return;
    float4 v0 = *(const float4*)(src + i);
    float4 v1 = *(const float4*)(src + i + 4);
    uint4 h;
    h.x = pack2h(v0.x, v0.y);
    h.y = pack2h(v0.z, v0.w);
    h.z = pack2h(v1.x, v1.y);
    h.w = pack2h(v1.z, v1.w);
    *(uint4*)(hi + i) = h;
}

// ---------------------------------------------------------------------------
// Tensor-core fp16 2-term GEMM: C = (A_hi + A_lo) @ W_hi + bias.
// 128x128 block tile, BK=32, 256 threads (8 warps, 4x2), warp tile 32x64.
// ---------------------------------------------------------------------------
#define A_LO   5120          // elements: 128*40
#define B_HI   10240         // 2*5120
#define STG_E  14592         // stage elements (29184 bytes)

__device__ __forceinline__ void load_stage(
    uint32_t sb, int tid, int bm, int bn, int k0,
    const __half* Ahi, const __half* Alo, const __half* Bhi)
{
    #pragma unroll
    for (int i = 0; i < 2; i++) {
        int c = tid + i * 256;
        int r = c >> 2, cc = (c & 3) * 8;
        size_t go = (size_t)(bm + r) * DIM + k0 + cc;
        cpa16(sb + (r * 40 + cc) * 2, Ahi + go);
        cpa16(sb + (A_LO + r * 40 + cc) * 2, Alo + go);
    }
    #pragma unroll
    for (int i = 0; i < 2; i++) {
        int c = tid + i * 256;
        int r = c >> 4, cc = (c & 15) * 8;
        size_t go = (size_t)(k0 + r) * DIM + bn + cc;
        cpa16(sb + (B_HI + r * 136 + cc) * 2, Bhi + go);
    }
    asm volatile("cp.async.commit_group;" ::: "memory");
}

__device__ __forceinline__ void gemm_body(
    const __half* __restrict__ Ahi, const __half* __restrict__ Alo,
    const __half* __restrict__ Bhi,
    const float* __restrict__ bias, float* __restrict__ C, int bm, int bn)
{
    extern __shared__ __half smbuf[];
    const int tid  = threadIdx.x;
    const int lane = tid & 31;
    const int wid  = tid >> 5;
    const int wm   = wid & 3;
    const int wn   = wid >> 2;
    uint32_t sb0 = (uint32_t)__cvta_generic_to_shared(smbuf);

    float acc[2][8][4] = {};

    load_stage(sb0, tid, bm, bn, 0, Ahi, Alo, Bhi);

    const int NIT = DIM / 32;
    for (int it = 0; it < NIT; it++) {
        if (it + 1 < NIT) {
            load_stage(sb0 + ((it + 1) & 1) * (STG_E * 2), tid, bm, bn,
                       (it + 1) * 32, Ahi, Alo, Bhi);
            asm volatile("cp.async.wait_group 1;" ::: "memory");
        } else {
            asm volatile("cp.async.wait_group 0;" ::: "memory");
        }
        __syncthreads();

        uint32_t sb = sb0 + (it & 1) * (STG_E * 2);
        #pragma unroll
        for (int kk = 0; kk < 32; kk += 16) {
            uint32_t ra_h[2][4];
            uint32_t ra_l[2][4];
            uint32_t arow = wm * 32 + (lane & 15);
            uint32_t aoff = (arow * 40 + kk + (lane >> 4) * 8) * 2;
            ldm_x4(sb + aoff, ra_h[0]);
            ldm_x4(sb + aoff + 16 * 40 * 2, ra_h[1]);
            ldm_x4(sb + A_LO * 2 + aoff, ra_l[0]);
            ldm_x4(sb + A_LO * 2 + aoff + 16 * 40 * 2, ra_l[1]);

            int g = lane >> 3;
            uint32_t brow = kk + (g & 1) * 8 + (lane & 7);
            #pragma unroll
            for (int ng = 0; ng < 4; ng++) {
                uint32_t rb_h[4];
                uint32_t col  = wn * 64 + ng * 16 + (g >> 1) * 8;
                uint32_t boff = (brow * 136 + col) * 2;
                ldm_x4t(sb + B_HI * 2 + boff, rb_h);
                #pragma unroll
                for (int mi = 0; mi < 2; mi++) {
                    int t0 = 2 * ng, t1 = 2 * ng + 1;
                    mma_f16(acc[mi][t0], ra_h[mi], rb_h[0], rb_h[1]);
                    mma_f16(acc[mi][t0], ra_l[mi], rb_h[0], rb_h[1]);
                    mma_f16(acc[mi][t1], ra_h[mi], rb_h[2], rb_h[3]);
                    mma_f16(acc[mi][t1], ra_l[mi], rb_h[2], rb_h[3]);
                }
            }
        }
        __syncthreads();
    }

    #pragma unroll
    for (int mi = 0; mi < 2; mi++) {
        int r0 = bm + wm * 32 + mi * 16 + (lane >> 2);
        #pragma unroll
        for (int t = 0; t < 8; t++) {
            int c = bn + wn * 64 + t * 8 + (lane & 3) * 2;
            C[(size_t)r0 * DIM + c]           = acc[mi][t][0] + bias[c];
            C[(size_t)r0 * DIM + c + 1]       = acc[mi][t][1] + bias[c + 1];
            C[(size_t)(r0 + 8) * DIM + c]     = acc[mi][t][2] + bias[c];
            C[(size_t)(r0 + 8) * DIM + c + 1] = acc[mi][t][3] + bias[c + 1];
        }
    }
}

// single-weight GEMM (O projection)
__global__ __launch_bounds__(256, 2) void gemm_tc(
    const __half* __restrict__ Ahi, const __half* __restrict__ Alo,
    const __half* __restrict__ Bhi,
    const float* __restrict__ bias, float* __restrict__ C)
{
    gemm_body(Ahi, Alo, Bhi, bias, C, blockIdx.y * 128, blockIdx.x * 128);
}

// fused QKV GEMM: grid.x = 72 (3 weights x 24 column tiles)
__global__ __launch_bounds__(256, 2) void gemm_qkv(
    const __half* __restrict__ Ahi, const __half* __restrict__ Alo,
    const __half* __restrict__ WhiBase,
    const float* __restrict__ bq, const float* __restrict__ bk,
    const float* __restrict__ bv,
    float* __restrict__ pq, float* __restrict__ pk, float* __restrict__ pv)
{
    const int sel = blockIdx.x / 24;
    const int bn  = (blockIdx.x % 24) * 128;
    const size_t NW = (size_t)DIM * DIM;
    const __half* Bhi = WhiBase + (size_t)sel * NW;
    const float* bias = (sel == 0) ? bq : (sel == 1) ? bk : bv;
    float* C = (sel == 0) ? pq : (sel == 1) ? pk : pv;
    gemm_body(Ahi, Alo, Bhi, bias, C, blockIdx.y * 128, bn);
}

// ---------------------------------------------------------------------------
// Fused per-head RMSNorm + RoPE + scale, writing split fp16 hi/lo.
// ---------------------------------------------------------------------------
__global__ void rmsnorm_rope_split(const float* __restrict__ in,
                                   const float* __restrict__ w,
                                   const float* __restrict__ cb,
                                   const float* __restrict__ sb,
                                   float scale,
                                   __half* __restrict__ ohi,
                                   __half* __restrict__ olo)
{
    const int s = blockIdx.x, h = blockIdx.y, d = threadIdx.x;
    const float* p = in + (size_t)s * DIM + h * HD;
    float val = p[d];

    float sq = val * val;
    #pragma unroll
    for (int off = 16; off; off >>= 1) sq += __shfl_xor_sync(0xffffffffu, sq, off);
    __shared__ float red[4];
    if ((d & 31) == 0) red[d >> 5] = sq;
    __syncthreads();
    float tot = red[0] + red[1] + red[2] + red[3];

    float n = val * rsqrtf(tot * (1.0f / HD) + 1e-6f) * w[d];

    __shared__ float nv[HD];
    nv[d] = n;
    __syncthreads();

    float outv = n;
    if (s < SIMG) {
        float c  = cb[s * HD + d];
        float si = sb[s * HD + d];
        float partner = (d & 1) ? nv[d - 1] : -nv[d + 1];
        outv = n * c + partner * si;
    }
    outv *= scale;

    size_t off = (size_t)s * DIM + h * HD + d;
    __half hi = __float2half_rn(outv);
    ohi[off] = hi;
    olo[off] = __float2half_rn(outv - __half2float(hi));
}

// ---------------------------------------------------------------------------
// Flash attention, fp16 2-term MMA, fp32 accumulators, register softmax.
// Q hi+lo; K, V hi-only. 128 threads (4 warps x 16 q-rows), BQ=BK=64.
// smem: 4 tiles x 64x136 fp16 = 69632 B -> 2 CTAs/SM.
// ---------------------------------------------------------------------------
#define AQHI 0
#define AQLO 8704
#define AKHI 17408
#define AVHI 26112
#define ATT_SMEM (34816 * 2)

__global__ __launch_bounds__(128) void attn_mma(
    const __half* __restrict__ qhi, const __half* __restrict__ qlo,
    const __half* __restrict__ khi, const __half* __restrict__ vhi,
    __half* __restrict__ ohi, __half* __restrict__ olo,
    float* __restrict__ o_f32)
{
    extern __shared__ __half sm2[];
    uint32_t sb = (uint32_t)__cvta_generic_to_shared(sm2);
    const int tid = threadIdx.x, lane = tid & 31, wid = tid >> 5;
    const int q0 = blockIdx.x * 64, h = blockIdx.y;

    #pragma unroll
    for (int i = 0; i < 8; i++) {
        int idx = tid + i * 128, r = idx >> 4, c = (idx & 15) * 8;
        size_t go = (size_t)(q0 + r) * DIM + h * HD + c;
        uint32_t so = (uint32_t)(r * 136 + c) * 2;
        cpa16(sb + AQHI * 2 + so, qhi + go);
        cpa16(sb + AQLO * 2 + so, qlo + go);
    }
    #pragma unroll
    for (int i = 0; i < 8; i++) {
        int idx = tid + i * 128, r = idx >> 4, c = (idx & 15) * 8;
        size_t go = (size_t)r * DIM + h * HD + c;
        uint32_t so = (uint32_t)(r * 136 + c) * 2;
        cpa16(sb + AKHI * 2 + so, khi + go);
        cpa16(sb + AVHI * 2 + so, vhi + go);
    }
    asm volatile("cp.async.commit_group;" ::: "memory");
    asm volatile("cp.async.wait_group 0;" ::: "memory");
    __syncthreads();

    float m0 = -1e30f, m1 = -1e30f, l0 = 0.f, l1 = 0.f;
    float oa[16][4] = {};

    const uint32_t aoff = (uint32_t)((wid * 16 + (lane & 15)) * 136 +
                                     ((lane >> 4) << 3)) * 2;
    const int brow = ((lane >> 4) << 3) + (lane & 7);
    const int bcol = ((lane >> 3) & 1) << 3;
    const int vrow = ((lane >> 3) & 1) * 8 + (lane & 7);
    const int vcol = (lane >> 4) << 3;

    const int NIT = STOT / 64;
    for (int it = 0; it < NIT; it++) {
        // ---- S = (Q_hi + Q_lo) @ K_hi^T ----
        float sc[8][4] = {};
        #pragma unroll
        for (int ks = 0; ks < 8; ks++) {
            uint32_t qh[4], ql[4];
            ldm_x4(sb + AQHI * 2 + aoff + ks * 32, qh);
            ldm_x4(sb + AQLO * 2 + aoff + ks * 32, ql);
            #pragma unroll
            for (int bt = 0; bt < 4; bt++) {
                uint32_t kh[4];
                uint32_t ko = (uint32_t)((bt * 16 + brow) * 136 + ks * 16 + bcol) * 2;
                ldm_x4(sb + AKHI * 2 + ko, kh);
                mma_f16(sc[2 * bt],     qh, kh[0], kh[1]);
                mma_f16(sc[2 * bt],     ql, kh[0], kh[1]);
                mma_f16(sc[2 * bt + 1], qh, kh[2], kh[3]);
                mma_f16(sc[2 * bt + 1], ql, kh[2], kh[3]);
            }
        }

        // ---- online softmax in registers ----
        float mx0 = -1e30f, mx1 = -1e30f;
        #pragma unroll
        for (int nt = 0; nt < 8; nt++) {
            mx0 = fmaxf(mx0, fmaxf(sc[nt][0], sc[nt][1]));
            mx1 = fmaxf(mx1, fmaxf(sc[nt][2], sc[nt][3]));
        }
        mx0 = fmaxf(mx0, __shfl_xor_sync(0xffffffffu, mx0, 1));
        mx0 = fmaxf(mx0, __shfl_xor_sync(0xffffffffu, mx0, 2));
        mx1 = fmaxf(mx1, __shfl_xor_sync(0xffffffffu, mx1, 1));
        mx1 = fmaxf(mx1, __shfl_xor_sync(0xffffffffu, mx1, 2));
        float mn0 = fmaxf(m0, mx0), mn1 = fmaxf(m1, mx1);
        float c0 = __expf(m0 - mn0), c1 = __expf(m1 - mn1);
        float ls0 = 0.f, ls1 = 0.f;
        #pragma unroll
        for (int nt = 0; nt < 8; nt++) {
            sc[nt][0] = __expf(sc[nt][0] - mn0);
            sc[nt][1] = __expf(sc[nt][1] - mn0);
            sc[nt][2] = __expf(sc[nt][2] - mn1);
            sc[nt][3] = __expf(sc[nt][3] - mn1);
            ls0 += sc[nt][0] + sc[nt][1];
            ls1 += sc[nt][2] + sc[nt][3];
        }
        ls0 += __shfl_xor_sync(0xffffffffu, ls0, 1);
        ls0 += __shfl_xor_sync(0xffffffffu, ls0, 2);
        ls1 += __shfl_xor_sync(0xffffffffu, ls1, 1);
        ls1 += __shfl_xor_sync(0xffffffffu, ls1, 2);
        m0 = mn0; m1 = mn1;
        l0 = l0 * c0 + ls0;
        l1 = l1 * c1 + ls1;
        #pragma unroll
        for (int nt = 0; nt < 16; nt++) {
            oa[nt][0] *= c0; oa[nt][1] *= c0;
            oa[nt][2] *= c1; oa[nt][3] *= c1;
        }

        // ---- P: accumulator frags -> fp16 A frags (registers) ----
        uint32_t ph[4][4], pl[4][4];
        #pragma unroll
        for (int t = 0; t < 4; t++) {
            split2h(sc[2 * t][0],     sc[2 * t][1],     ph[t][0], pl[t][0]);
            split2h(sc[2 * t][2],     sc[2 * t][3],     ph[t][1], pl[t][1]);
            split2h(sc[2 * t + 1][0], sc[2 * t + 1][1], ph[t][2], pl[t][2]);
            split2h(sc[2 * t + 1][2], sc[2 * t + 1][3], ph[t][3], pl[t][3]);
        }

        // ---- O += (P_hi + P_lo) @ V_hi ----
        #pragma unroll
        for (int kst = 0; kst < 4; kst++) {
            #pragma unroll
            for (int dt = 0; dt < 8; dt++) {
                uint32_t vh[4];
                uint32_t vo = (uint32_t)((kst * 16 + vrow) * 136 + dt * 16 + vcol) * 2;
                ldm_x4t(sb + AVHI * 2 + vo, vh);
                mma_f16(oa[2 * dt],     ph[kst], vh[0], vh[1]);
                mma_f16(oa[2 * dt],     pl[kst], vh[0], vh[1]);
                mma_f16(oa[2 * dt + 1], ph[kst], vh[2], vh[3]);
                mma_f16(oa[2 * dt + 1], pl[kst], vh[2], vh[3]);
            }
        }

        __syncthreads();
        if (it + 1 < NIT) {
            int kt = (it + 1) * 64;
            #pragma unroll
            for (int i = 0; i < 8; i++) {
                int idx = tid + i * 128, r = idx >> 4, c = (idx & 15) * 8;
                size_t go = (size_t)(kt + r) * DIM + h * HD + c;
                uint32_t so = (uint32_t)(r * 136 + c) * 2;
                cpa16(sb + AKHI * 2 + so, khi + go);
                cpa16(sb + AVHI * 2 + so, vhi + go);
            }
            asm volatile("cp.async.commit_group;" ::: "memory");
            asm volatile("cp.async.wait_group 0;" ::: "memory");
        }
        __syncthreads();
    }

    // ---- normalize + store: split fp16 always, fp32 only for txt rows ----
    float inv0 = 1.0f / l0, inv1 = 1.0f / l1;
    int r0 = q0 + wid * 16 + (lane >> 2);
    int cb0 = h * HD + (lane & 3) * 2;
    const bool wr32 = (q0 >= SIMG);
    #pragma unroll
    for (int nt = 0; nt < 16; nt++) {
        float a0 = oa[nt][0] * inv0, a1 = oa[nt][1] * inv0;
        float a2 = oa[nt][2] * inv1, a3 = oa[nt][3] * inv1;
        uint32_t h0, lo0, h1, lo1;
        split2h(a0, a1, h0, lo0);
        split2h(a2, a3, h1, lo1);
        size_t off0 = (size_t)r0 * DIM + cb0 + nt * 8;
        size_t off1 = (size_t)(r0 + 8) * DIM + cb0 + nt * 8;
        *(uint32_t*)(ohi + off0) = h0;
        *(uint32_t*)(olo + off0) = lo0;
        *(uint32_t*)(ohi + off1) = h1;
        *(uint32_t*)(olo + off1) = lo1;
        if (wr32) {
            *(float2*)(o_f32 + off0) = make_float2(a0, a1);
            *(float2*)(o_f32 + off1) = make_float2(a2, a3);
        }
    }
}

__global__ void copy_txt(const float* __restrict__ src, float* __restrict__ dst)
{
    int i = blockIdx.x * blockDim.x + threadIdx.x;
    if (i < STXT * DIM) dst[i] = src[i];
}

// ---------------------------------------------------------------------------
extern "C" void kernel_launch(void* const* d_in, const int* in_sizes, int n_in,
                              void* d_out, int out_size)
{
    const float* hidden = (const float*)d_in[0];
    const float* enc    = (const float*)d_in[1];
    const float* cosb   = (const float*)d_in[2];
    const float* sinb   = (const float*)d_in[3];
    const float* wq     = (const float*)d_in[4];
    const float* bq     = (const float*)d_in[5];
    const float* wk     = (const float*)d_in[6];
    const float* bk     = (const float*)d_in[7];
    const float* wv     = (const float*)d_in[8];
    const float* bv     = (const float*)d_in[9];
    const float* nqw    = (const float*)d_in[10];
    const float* nkw    = (const float*)d_in[11];
    const float* wo     = (const float*)d_in[12];
    const float* bo     = (const float*)d_in[13];
    float* out = (float*)d_out;

    float *pq, *pk, *pv, *po;
    __half *xhi, *xlo, *whi;
    __half *aqh, *aql, *akh, *akl, *avh;
    cudaGetSymbolAddress((void**)&pq, g_q);
    cudaGetSymbolAddress((void**)&pk, g_k);
    cudaGetSymbolAddress((void**)&pv, g_v);
    cudaGetSymbolAddress((void**)&po, g_o);
    cudaGetSymbolAddress((void**)&xhi, g_xhi);
    cudaGetSymbolAddress((void**)&xlo, g_xlo);
    cudaGetSymbolAddress((void**)&whi, g_whi);
    cudaGetSymbolAddress((void**)&aqh, g_qhi);
    cudaGetSymbolAddress((void**)&aql, g_qlo);
    cudaGetSymbolAddress((void**)&akh, g_khi);
    cudaGetSymbolAddress((void**)&akl, g_klo);
    cudaGetSymbolAddress((void**)&avh, g_vhi);

    const int gemm_smem = STG_E * 2 * 2;   // 58368 bytes
    cudaFuncSetAttribute(gemm_tc, cudaFuncAttributeMaxDynamicSharedMemorySize,
                         gemm_smem);
    cudaFuncSetAttribute(gemm_qkv, cudaFuncAttributeMaxDynamicSharedMemorySize,
                         gemm_smem);
    cudaFuncSetAttribute(attn_mma, cudaFuncAttributeMaxDynamicSharedMemorySize,
                         ATT_SMEM);

    const size_t NW = (size_t)DIM * DIM;
    const int conv_blk = 256;
    const int grid_w = (int)((NW / 8 + conv_blk - 1) / conv_blk);

    // --- all conversions up front ---
    conv_split8<<<(SIMG * DIM / 8 + 255) / 256, 256>>>(hidden, xhi, xlo, SIMG * DIM);
    conv_split8<<<(STXT * DIM / 8 + 255) / 256, 256>>>(
        enc, xhi + (size_t)SIMG * DIM, xlo + (size_t)SIMG * DIM, STXT * DIM);
    conv_hi8<<<grid_w, conv_blk>>>(wq, whi + 0 * NW, (int)NW);
    conv_hi8<<<grid_w, conv_blk>>>(wk, whi + 1 * NW, (int)NW);
    conv_hi8<<<grid_w, conv_blk>>>(wv, whi + 2 * NW, (int)NW);
    conv_hi8<<<grid_w, conv_blk>>>(wo, whi + 3 * NW, (int)NW);

    // fused Q, K, V projections: one launch, 1296 CTAs
    dim3 gq(72, STOT / 128);           // (72, 18)
    gemm_qkv<<<gq, 256, gemm_smem>>>(xhi, xlo, whi, bq, bk, bv, pq, pk, pv);

    // per-head RMSNorm + RoPE -> split fp16 (scale folded into Q)
    dim3 gn(STOT, HEADS);
    rmsnorm_rope_split<<<gn, 128>>>(pq, nqw, cosb, sinb,
                                    0.08838834764831845f, aqh, aql);
    rmsnorm_rope_split<<<gn, 128>>>(pk, nkw, cosb, sinb, 1.0f, akh, akl);
    conv_hi8<<<(STOT * DIM / 8 + 255) / 256, 256>>>(pv, avh, STOT * DIM);

    // attention (fp16 2-term mma) -> writes split output directly
    dim3 ga(STOT / 64, HEADS);         // (36, 24)
    attn_mma<<<ga, 128, ATT_SMEM>>>(aqh, aql, akh, avh, xhi, xlo, po);

    // output projection for image tokens
    dim3 go(DIM / 128, SIMG / 128);    // (24, 16)
    gemm_tc<<<go, 256, gemm_smem>>>(xhi, xlo, whi + 3 * NW, bo, out);

    // raw copy of text tokens
    copy_txt<<<(STXT * DIM + 255) / 256, 256>>>(po + (size_t)SIMG * DIM,
                                                out + (size_t)SIMG * DIM);
}

// round 13
// speedup vs baseline: 7.6316x; 1.0300x over previous
#include <cuda_runtime.h>
#include <cuda_fp16.h>
#include <cstdint>
#include <math.h>

#define DIM 3072
#define HEADS 24
#define HD 128
#define SIMG 2048
#define STXT 256
#define STOT 2304

// ---------------------------------------------------------------------------
// scratch (static __device__ globals per allocation rules)
// ---------------------------------------------------------------------------
__device__ float g_q[(size_t)STOT * DIM];
__device__ float g_k[(size_t)STOT * DIM];
__device__ float g_o[(size_t)STOT * DIM];
__device__ __half g_xhi[(size_t)STOT * DIM];
__device__ __half g_xlo[(size_t)STOT * DIM];
__device__ __half g_whi[(size_t)4 * DIM * DIM];   // 4 weight slots, hi only
__device__ __half g_qhi[(size_t)STOT * DIM];
__device__ __half g_qlo[(size_t)STOT * DIM];
__device__ __half g_khi[(size_t)STOT * DIM];
__device__ __half g_klo[(size_t)STOT * DIM];      // written, unused (K is B-side)
__device__ __half g_vhi[(size_t)STOT * DIM];

// ---------------------------------------------------------------------------
// PTX helpers
// ---------------------------------------------------------------------------
__device__ __forceinline__ void cpa16(uint32_t s, const void* g) {
    asm volatile("cp.async.cg.shared.global [%0], [%1], 16;" :: "r"(s), "l"(g));
}
__device__ __forceinline__ void ldm_x4(uint32_t addr, uint32_t* r) {
    asm volatile("ldmatrix.sync.aligned.m8n8.x4.shared.b16 {%0,%1,%2,%3}, [%4];"
        : "=r"(r[0]), "=r"(r[1]), "=r"(r[2]), "=r"(r[3]) : "r"(addr));
}
__device__ __forceinline__ void ldm_x4t(uint32_t addr, uint32_t* r) {
    asm volatile("ldmatrix.sync.aligned.m8n8.x4.trans.shared.b16 {%0,%1,%2,%3}, [%4];"
        : "=r"(r[0]), "=r"(r[1]), "=r"(r[2]), "=r"(r[3]) : "r"(addr));
}
__device__ __forceinline__ void mma_f16(float* d, const uint32_t* a,
                                        uint32_t b0, uint32_t b1) {
    asm volatile(
        "mma.sync.aligned.m16n8k16.row.col.f32.f16.f16.f32 "
        "{%0,%1,%2,%3}, {%4,%5,%6,%7}, {%8,%9}, {%0,%1,%2,%3};"
        : "+f"(d[0]), "+f"(d[1]), "+f"(d[2]), "+f"(d[3])
        : "r"(a[0]), "r"(a[1]), "r"(a[2]), "r"(a[3]), "r"(b0), "r"(b1));
}
__device__ __forceinline__ void split2h(float x, float y, uint32_t& h, uint32_t& l) {
    __half hx = __float2half_rn(x), hy = __float2half_rn(y);
    __half2 hh = __halves2half2(hx, hy);
    h = *reinterpret_cast<uint32_t*>(&hh);
    __half2 ll = __floats2half2_rn(x - __half2float(hx), y - __half2float(hy));
    l = *reinterpret_cast<uint32_t*>(&ll);
}
__device__ __forceinline__ uint32_t pack2h(float x, float y) {
    __half2 hh = __floats2half2_rn(x, y);
    return *reinterpret_cast<uint32_t*>(&hh);
}

// ---------------------------------------------------------------------------
// fp32 -> fp16 hi/lo split, 8 elems/thread
// ---------------------------------------------------------------------------
__global__ void conv_split8(const float* __restrict__ src,
                            __half* __restrict__ hi,
                            __half* __restrict__ lo, int n)
{
    int i = (blockIdx.x * blockDim.x + threadIdx.x) * 8;
    if (i >= n) return;
    float4 v0 = *(const float4*)(src + i);
    float4 v1 = *(const float4*)(src + i + 4);
    uint32_t h[4], l[4];
    split2h(v0.x, v0.y, h[0], l[0]);
    split2h(v0.z, v0.w, h[1], l[1]);
    split2h(v1.x, v1.y, h[2], l[2]);
    split2h(v1.z, v1.w, h[3], l[3]);
    *(uint4*)(hi + i) = make_uint4(h[0], h[1], h[2], h[3]);
    *(uint4*)(lo + i) = make_uint4(l[0], l[1], l[2], l[3]);
}

// fp32 -> fp16 hi only, 8 elems/thread (B-side operands)
__global__ void conv_hi8(const float* __restrict__ src,
                         __half* __restrict__ hi, int n)
{
    int i = (blockIdx.x * blockDim.x + threadIdx.x) * 8;
    if (i >= n) return;
    float4 v0 = *(const float4*)(src + i);
    float4 v1 = *(const float4*)(src + i + 4);
    uint4 h;
    h.x = pack2h(v0.x, v0.y);
    h.y = pack2h(v0.z, v0.w);
    h.z = pack2h(v1.x, v1.y);
    h.w = pack2h(v1.z, v1.w);
    *(uint4*)(hi + i) = h;
}

// ---------------------------------------------------------------------------
// Tensor-core fp16 2-term GEMM: C = (A_hi + A_lo) @ W_hi + bias.
// 128x128 block tile, BK=32, 256 threads (8 warps, 4x2), warp tile 32x64.
// 3-stage cp.async pipeline, one __syncthreads per K-iteration.
// ---------------------------------------------------------------------------
#define A_LO   5120          // elements: 128*40
#define B_HI   10240         // 2*5120
#define STG_E  14592         // stage elements (29184 bytes)
#define GEMM_SMEM (STG_E * 2 * 3)   // 87552 bytes

__device__ __forceinline__ void load_stage(
    uint32_t sb, int tid, int bm, int bn, int k0,
    const __half* Ahi, const __half* Alo, const __half* Bhi)
{
    #pragma unroll
    for (int i = 0; i < 2; i++) {
        int c = tid + i * 256;
        int r = c >> 2, cc = (c & 3) * 8;
        size_t go = (size_t)(bm + r) * DIM + k0 + cc;
        cpa16(sb + (r * 40 + cc) * 2, Ahi + go);
        cpa16(sb + (A_LO + r * 40 + cc) * 2, Alo + go);
    }
    #pragma unroll
    for (int i = 0; i < 2; i++) {
        int c = tid + i * 256;
        int r = c >> 4, cc = (c & 15) * 8;
        size_t go = (size_t)(k0 + r) * DIM + bn + cc;
        cpa16(sb + (B_HI + r * 136 + cc) * 2, Bhi + go);
    }
    asm volatile("cp.async.commit_group;" ::: "memory");
}

// If Ch != nullptr, write fp16 (hi-only) output; else fp32.
__device__ __forceinline__ void gemm_body(
    const __half* __restrict__ Ahi, const __half* __restrict__ Alo,
    const __half* __restrict__ Bhi,
    const float* __restrict__ bias, float* __restrict__ C,
    __half* __restrict__ Ch, int bm, int bn)
{
    extern __shared__ __half smbuf[];
    const int tid  = threadIdx.x;
    const int lane = tid & 31;
    const int wid  = tid >> 5;
    const int wm   = wid & 3;
    const int wn   = wid >> 2;
    uint32_t sb0 = (uint32_t)__cvta_generic_to_shared(smbuf);

    float acc[2][8][4] = {};

    const int NIT = DIM / 32;   // 96
    load_stage(sb0, tid, bm, bn, 0, Ahi, Alo, Bhi);
    load_stage(sb0 + STG_E * 2, tid, bm, bn, 32, Ahi, Alo, Bhi);

    int buf = 0;                 // it % 3
    for (int it = 0; it < NIT; it++) {
        if (it < NIT - 1) {
            asm volatile("cp.async.wait_group 1;" ::: "memory");
        } else {
            asm volatile("cp.async.wait_group 0;" ::: "memory");
        }
        __syncthreads();

        if (it + 2 < NIT) {
            int nb = buf + 2; if (nb >= 3) nb -= 3;
            load_stage(sb0 + (uint32_t)nb * (STG_E * 2), tid, bm, bn,
                       (it + 2) * 32, Ahi, Alo, Bhi);
        }

        uint32_t sb = sb0 + (uint32_t)buf * (STG_E * 2);
        #pragma unroll
        for (int kk = 0; kk < 32; kk += 16) {
            uint32_t ra_h[2][4];
            uint32_t ra_l[2][4];
            uint32_t arow = wm * 32 + (lane & 15);
            uint32_t aoff = (arow * 40 + kk + (lane >> 4) * 8) * 2;
            ldm_x4(sb + aoff, ra_h[0]);
            ldm_x4(sb + aoff + 16 * 40 * 2, ra_h[1]);
            ldm_x4(sb + A_LO * 2 + aoff, ra_l[0]);
            ldm_x4(sb + A_LO * 2 + aoff + 16 * 40 * 2, ra_l[1]);

            int g = lane >> 3;
            uint32_t brow = kk + (g & 1) * 8 + (lane & 7);
            #pragma unroll
            for (int ng = 0; ng < 4; ng++) {
                uint32_t rb_h[4];
                uint32_t col  = wn * 64 + ng * 16 + (g >> 1) * 8;
                uint32_t boff = (brow * 136 + col) * 2;
                ldm_x4t(sb + B_HI * 2 + boff, rb_h);
                #pragma unroll
                for (int mi = 0; mi < 2; mi++) {
                    int t0 = 2 * ng, t1 = 2 * ng + 1;
                    mma_f16(acc[mi][t0], ra_h[mi], rb_h[0], rb_h[1]);
                    mma_f16(acc[mi][t0], ra_l[mi], rb_h[0], rb_h[1]);
                    mma_f16(acc[mi][t1], ra_h[mi], rb_h[2], rb_h[3]);
                    mma_f16(acc[mi][t1], ra_l[mi], rb_h[2], rb_h[3]);
                }
            }
        }
        if (++buf == 3) buf = 0;
    }

    #pragma unroll
    for (int mi = 0; mi < 2; mi++) {
        int r0 = bm + wm * 32 + mi * 16 + (lane >> 2);
        #pragma unroll
        for (int t = 0; t < 8; t++) {
            int c = bn + wn * 64 + t * 8 + (lane & 3) * 2;
            float v00 = acc[mi][t][0] + bias[c];
            float v01 = acc[mi][t][1] + bias[c + 1];
            float v10 = acc[mi][t][2] + bias[c];
            float v11 = acc[mi][t][3] + bias[c + 1];
            if (Ch) {
                *(uint32_t*)(Ch + (size_t)r0 * DIM + c)       = pack2h(v00, v01);
                *(uint32_t*)(Ch + (size_t)(r0 + 8) * DIM + c) = pack2h(v10, v11);
            } else {
                C[(size_t)r0 * DIM + c]           = v00;
                C[(size_t)r0 * DIM + c + 1]       = v01;
                C[(size_t)(r0 + 8) * DIM + c]     = v10;
                C[(size_t)(r0 + 8) * DIM + c + 1] = v11;
            }
        }
    }
}

// single-weight GEMM (O projection, fp32 out)
__global__ __launch_bounds__(256, 2) void gemm_tc(
    const __half* __restrict__ Ahi, const __half* __restrict__ Alo,
    const __half* __restrict__ Bhi,
    const float* __restrict__ bias, float* __restrict__ C)
{
    gemm_body(Ahi, Alo, Bhi, bias, C, nullptr, blockIdx.y * 128, blockIdx.x * 128);
}

// fused QKV GEMM: grid.x = 72 (3 weights x 24 col tiles); V writes fp16 direct
__global__ __launch_bounds__(256, 2) void gemm_qkv(
    const __half* __restrict__ Ahi, const __half* __restrict__ Alo,
    const __half* __restrict__ WhiBase,
    const float* __restrict__ bq, const float* __restrict__ bk,
    const float* __restrict__ bv,
    float* __restrict__ pq, float* __restrict__ pk, __half* __restrict__ vh)
{
    const int sel = blockIdx.x / 24;
    const int bn  = (blockIdx.x % 24) * 128;
    const size_t NW = (size_t)DIM * DIM;
    const __half* Bhi = WhiBase + (size_t)sel * NW;
    const float* bias = (sel == 0) ? bq : (sel == 1) ? bk : bv;
    float* C = (sel == 0) ? pq : (sel == 1) ? pk : nullptr;
    __half* Ch = (sel == 2) ? vh : nullptr;
    gemm_body(Ahi, Alo, Bhi, bias, C, Ch, blockIdx.y * 128, bn);
}

// ---------------------------------------------------------------------------
// Fused per-head RMSNorm + RoPE + scale, writing split fp16 hi/lo.
// ---------------------------------------------------------------------------
__global__ void rmsnorm_rope_split(const float* __restrict__ in,
                                   const float* __restrict__ w,
                                   const float* __restrict__ cb,
                                   const float* __restrict__ sb,
                                   float scale,
                                   __half* __restrict__ ohi,
                                   __half* __restrict__ olo)
{
    const int s = blockIdx.x, h = blockIdx.y, d = threadIdx.x;
    const float* p = in + (size_t)s * DIM + h * HD;
    float val = p[d];

    float sq = val * val;
    #pragma unroll
    for (int off = 16; off; off >>= 1) sq += __shfl_xor_sync(0xffffffffu, sq, off);
    __shared__ float red[4];
    if ((d & 31) == 0) red[d >> 5] = sq;
    __syncthreads();
    float tot = red[0] + red[1] + red[2] + red[3];

    float n = val * rsqrtf(tot * (1.0f / HD) + 1e-6f) * w[d];

    __shared__ float nv[HD];
    nv[d] = n;
    __syncthreads();

    float outv = n;
    if (s < SIMG) {
        float c  = cb[s * HD + d];
        float si = sb[s * HD + d];
        float partner = (d & 1) ? nv[d - 1] : -nv[d + 1];
        outv = n * c + partner * si;
    }
    outv *= scale;

    size_t off = (size_t)s * DIM + h * HD + d;
    __half hi = __float2half_rn(outv);
    ohi[off] = hi;
    olo[off] = __float2half_rn(outv - __half2float(hi));
}

// ---------------------------------------------------------------------------
// Flash attention, fp16 2-term MMA, fp32 accumulators, register softmax.
// Q hi+lo; K single-buffer; V double-buffer. K/V prefetch overlaps with
// softmax + PV compute. smem 87040 B -> 2 CTAs/SM.
// ---------------------------------------------------------------------------
#define AQHI 0
#define AQLO 8704
#define AKHI 17408
#define AVH0 26112
#define AVH1 34816
#define ATT_SMEM (43520 * 2)

__global__ __launch_bounds__(128) void attn_mma(
    const __half* __restrict__ qhi, const __half* __restrict__ qlo,
    const __half* __restrict__ khi, const __half* __restrict__ vhi,
    __half* __restrict__ ohi, __half* __restrict__ olo,
    float* __restrict__ o_f32)
{
    extern __shared__ __half sm2[];
    uint32_t sb = (uint32_t)__cvta_generic_to_shared(sm2);
    const int tid = threadIdx.x, lane = tid & 31, wid = tid >> 5;
    const int q0 = blockIdx.x * 64, h = blockIdx.y;

    // prologue: Q tiles + K(0) + V(0)
    #pragma unroll
    for (int i = 0; i < 8; i++) {
        int idx = tid + i * 128, r = idx >> 4, c = (idx & 15) * 8;
        size_t go = (size_t)(q0 + r) * DIM + h * HD + c;
        uint32_t so = (uint32_t)(r * 136 + c) * 2;
        cpa16(sb + AQHI * 2 + so, qhi + go);
        cpa16(sb + AQLO * 2 + so, qlo + go);
    }
    #pragma unroll
    for (int i = 0; i < 8; i++) {
        int idx = tid + i * 128, r = idx >> 4, c = (idx & 15) * 8;
        size_t go = (size_t)r * DIM + h * HD + c;
        uint32_t so = (uint32_t)(r * 136 + c) * 2;
        cpa16(sb + AKHI * 2 + so, khi + go);
        cpa16(sb + AVH0 * 2 + so, vhi + go);
    }
    asm volatile("cp.async.commit_group;" ::: "memory");
    asm volatile("cp.async.wait_group 0;" ::: "memory");
    __syncthreads();

    float m0 = -1e30f, m1 = -1e30f, l0 = 0.f, l1 = 0.f;
    float oa[16][4] = {};

    const uint32_t aoff = (uint32_t)((wid * 16 + (lane & 15)) * 136 +
                                     ((lane >> 4) << 3)) * 2;
    const int brow = ((lane >> 4) << 3) + (lane & 7);
    const int bcol = ((lane >> 3) & 1) << 3;
    const int vrow = ((lane >> 3) & 1) * 8 + (lane & 7);
    const int vcol = (lane >> 4) << 3;

    const int NIT = STOT / 64;
    for (int it = 0; it < NIT; it++) {
        // ---- S = (Q_hi + Q_lo) @ K_hi^T  (reads K buffer) ----
        float sc[8][4] = {};
        #pragma unroll
        for (int ks = 0; ks < 8; ks++) {
            uint32_t qh[4], ql[4];
            ldm_x4(sb + AQHI * 2 + aoff + ks * 32, qh);
            ldm_x4(sb + AQLO * 2 + aoff + ks * 32, ql);
            #pragma unroll
            for (int bt = 0; bt < 4; bt++) {
                uint32_t kh[4];
                uint32_t ko = (uint32_t)((bt * 16 + brow) * 136 + ks * 16 + bcol) * 2;
                ldm_x4(sb + AKHI * 2 + ko, kh);
                mma_f16(sc[2 * bt],     qh, kh[0], kh[1]);
                mma_f16(sc[2 * bt],     ql, kh[0], kh[1]);
                mma_f16(sc[2 * bt + 1], qh, kh[2], kh[3]);
                mma_f16(sc[2 * bt + 1], ql, kh[2], kh[3]);
            }
        }
        __syncthreads();    // all warps done reading K

        // ---- prefetch K(it+1) and V(it+1): overlaps softmax + PV below ----
        if (it + 1 < NIT) {
            int kt = (it + 1) * 64;
            uint32_t vdst = ((it + 1) & 1) ? AVH1 : AVH0;
            #pragma unroll
            for (int i = 0; i < 8; i++) {
                int idx = tid + i * 128, r = idx >> 4, c = (idx & 15) * 8;
                size_t go = (size_t)(kt + r) * DIM + h * HD + c;
                uint32_t so = (uint32_t)(r * 136 + c) * 2;
                cpa16(sb + AKHI * 2 + so, khi + go);
                cpa16(sb + vdst * 2 + so, vhi + go);
            }
            asm volatile("cp.async.commit_group;" ::: "memory");
        }

        // ---- online softmax in registers ----
        float mx0 = -1e30f, mx1 = -1e30f;
        #pragma unroll
        for (int nt = 0; nt < 8; nt++) {
            mx0 = fmaxf(mx0, fmaxf(sc[nt][0], sc[nt][1]));
            mx1 = fmaxf(mx1, fmaxf(sc[nt][2], sc[nt][3]));
        }
        mx0 = fmaxf(mx0, __shfl_xor_sync(0xffffffffu, mx0, 1));
        mx0 = fmaxf(mx0, __shfl_xor_sync(0xffffffffu, mx0, 2));
        mx1 = fmaxf(mx1, __shfl_xor_sync(0xffffffffu, mx1, 1));
        mx1 = fmaxf(mx1, __shfl_xor_sync(0xffffffffu, mx1, 2));
        float mn0 = fmaxf(m0, mx0), mn1 = fmaxf(m1, mx1);
        float c0 = __expf(m0 - mn0), c1 = __expf(m1 - mn1);
        float ls0 = 0.f, ls1 = 0.f;
        #pragma unroll
        for (int nt = 0; nt < 8; nt++) {
            sc[nt][0] = __expf(sc[nt][0] - mn0);
            sc[nt][1] = __expf(sc[nt][1] - mn0);
            sc[nt][2] = __expf(sc[nt][2] - mn1);
            sc[nt][3] = __expf(sc[nt][3] - mn1);
            ls0 += sc[nt][0] + sc[nt][1];
            ls1 += sc[nt][2] + sc[nt][3];
        }
        ls0 += __shfl_xor_sync(0xffffffffu, ls0, 1);
        ls0 += __shfl_xor_sync(0xffffffffu, ls0, 2);
        ls1 += __shfl_xor_sync(0xffffffffu, ls1, 1);
        ls1 += __shfl_xor_sync(0xffffffffu, ls1, 2);
        m0 = mn0; m1 = mn1;
        l0 = l0 * c0 + ls0;
        l1 = l1 * c1 + ls1;
        #pragma unroll
        for (int nt = 0; nt < 16; nt++) {
            oa[nt][0] *= c0; oa[nt][1] *= c0;
            oa[nt][2] *= c1; oa[nt][3] *= c1;
        }

        // ---- P frags (registers) ----
        uint32_t ph[4][4], pl[4][4];
        #pragma unroll
        for (int t = 0; t < 4; t++) {
            split2h(sc[2 * t][0],     sc[2 * t][1],     ph[t][0], pl[t][0]);
            split2h(sc[2 * t][2],     sc[2 * t][3],     ph[t][1], pl[t][1]);
            split2h(sc[2 * t + 1][0], sc[2 * t + 1][1], ph[t][2], pl[t][2]);
            split2h(sc[2 * t + 1][2], sc[2 * t + 1][3], ph[t][3], pl[t][3]);
        }

        // ---- O += (P_hi + P_lo) @ V_hi  (reads V[it&1]) ----
        uint32_t vbase = (it & 1) ? AVH1 : AVH0;
        #pragma unroll
        for (int kst = 0; kst < 4; kst++) {
            #pragma unroll
            for (int dt = 0; dt < 8; dt++) {
                uint32_t vh[4];
                uint32_t vo = (uint32_t)((kst * 16 + vrow) * 136 + dt * 16 + vcol) * 2;
                ldm_x4t(sb + vbase * 2 + vo, vh);
                mma_f16(oa[2 * dt],     ph[kst], vh[0], vh[1]);
                mma_f16(oa[2 * dt],     pl[kst], vh[0], vh[1]);
                mma_f16(oa[2 * dt + 1], ph[kst], vh[2], vh[3]);
                mma_f16(oa[2 * dt + 1], pl[kst], vh[2], vh[3]);
            }
        }

        if (it + 1 < NIT) {
            asm volatile("cp.async.wait_group 0;" ::: "memory");
        }
        __syncthreads();
    }

    // ---- normalize + store: split fp16 always, fp32 only for txt rows ----
    float inv0 = 1.0f / l0, inv1 = 1.0f / l1;
    int r0 = q0 + wid * 16 + (lane >> 2);
    int cb0 = h * HD + (lane & 3) * 2;
    const bool wr32 = (q0 >= SIMG);
    #pragma unroll
    for (int nt = 0; nt < 16; nt++) {
        float a0 = oa[nt][0] * inv0, a1 = oa[nt][1] * inv0;
        float a2 = oa[nt][2] * inv1, a3 = oa[nt][3] * inv1;
        uint32_t h0, lo0, h1, lo1;
        split2h(a0, a1, h0, lo0);
        split2h(a2, a3, h1, lo1);
        size_t off0 = (size_t)r0 * DIM + cb0 + nt * 8;
        size_t off1 = (size_t)(r0 + 8) * DIM + cb0 + nt * 8;
        *(uint32_t*)(ohi + off0) = h0;
        *(uint32_t*)(olo + off0) = lo0;
        *(uint32_t*)(ohi + off1) = h1;
        *(uint32_t*)(olo + off1) = lo1;
        if (wr32) {
            *(float2*)(o_f32 + off0) = make_float2(a0, a1);
            *(float2*)(o_f32 + off1) = make_float2(a2, a3);
        }
    }
}

__global__ void copy_txt(const float* __restrict__ src, float* __restrict__ dst)
{
    int i = blockIdx.x * blockDim.x + threadIdx.x;
    if (i < STXT * DIM) dst[i] = src[i];
}

// ---------------------------------------------------------------------------
extern "C" void kernel_launch(void* const* d_in, const int* in_sizes, int n_in,
                              void* d_out, int out_size)
{
    const float* hidden = (const float*)d_in[0];
    const float* enc    = (const float*)d_in[1];
    const float* cosb   = (const float*)d_in[2];
    const float* sinb   = (const float*)d_in[3];
    const float* wq     = (const float*)d_in[4];
    const float* bq     = (const float*)d_in[5];
    const float* wk     = (const float*)d_in[6];
    const float* bk     = (const float*)d_in[7];
    const float* wv     = (const float*)d_in[8];
    const float* bv     = (const float*)d_in[9];
    const float* nqw    = (const float*)d_in[10];
    const float* nkw    = (const float*)d_in[11];
    const float* wo     = (const float*)d_in[12];
    const float* bo     = (const float*)d_in[13];
    float* out = (float*)d_out;

    float *pq, *pk, *po;
    __half *xhi, *xlo, *whi;
    __half *aqh, *aql, *akh, *akl, *avh;
    cudaGetSymbolAddress((void**)&pq, g_q);
    cudaGetSymbolAddress((void**)&pk, g_k);
    cudaGetSymbolAddress((void**)&po, g_o);
    cudaGetSymbolAddress((void**)&xhi, g_xhi);
    cudaGetSymbolAddress((void**)&xlo, g_xlo);
    cudaGetSymbolAddress((void**)&whi, g_whi);
    cudaGetSymbolAddress((void**)&aqh, g_qhi);
    cudaGetSymbolAddress((void**)&aql, g_qlo);
    cudaGetSymbolAddress((void**)&akh, g_khi);
    cudaGetSymbolAddress((void**)&akl, g_klo);
    cudaGetSymbolAddress((void**)&avh, g_vhi);

    cudaFuncSetAttribute(gemm_tc, cudaFuncAttributeMaxDynamicSharedMemorySize,
                         GEMM_SMEM);
    cudaFuncSetAttribute(gemm_qkv, cudaFuncAttributeMaxDynamicSharedMemorySize,
                         GEMM_SMEM);
    cudaFuncSetAttribute(attn_mma, cudaFuncAttributeMaxDynamicSharedMemorySize,
                         ATT_SMEM);

    const size_t NW = (size_t)DIM * DIM;
    const int conv_blk = 256;
    const int grid_w = (int)((NW / 8 + conv_blk - 1) / conv_blk);

    // --- all conversions up front ---
    conv_split8<<<(SIMG * DIM / 8 + 255) / 256, 256>>>(hidden, xhi, xlo, SIMG * DIM);
    conv_split8<<<(STXT * DIM / 8 + 255) / 256, 256>>>(
        enc, xhi + (size_t)SIMG * DIM, xlo + (size_t)SIMG * DIM, STXT * DIM);
    conv_hi8<<<grid_w, conv_blk>>>(wq, whi + 0 * NW, (int)NW);
    conv_hi8<<<grid_w, conv_blk>>>(wk, whi + 1 * NW, (int)NW);
    conv_hi8<<<grid_w, conv_blk>>>(wv, whi + 2 * NW, (int)NW);
    conv_hi8<<<grid_w, conv_blk>>>(wo, whi + 3 * NW, (int)NW);

    // fused Q, K, V projections (V writes fp16 directly)
    dim3 gq(72, STOT / 128);           // (72, 18)
    gemm_qkv<<<gq, 256, GEMM_SMEM>>>(xhi, xlo, whi, bq, bk, bv, pq, pk, avh);

    // per-head RMSNorm + RoPE -> split fp16 (scale folded into Q)
    dim3 gn(STOT, HEADS);
    rmsnorm_rope_split<<<gn, 128>>>(pq, nqw, cosb, sinb,
                                    0.08838834764831845f, aqh, aql);
    rmsnorm_rope_split<<<gn, 128>>>(pk, nkw, cosb, sinb, 1.0f, akh, akl);

    // attention (fp16 2-term mma) -> writes split output directly
    dim3 ga(STOT / 64, HEADS);         // (36, 24)
    attn_mma<<<ga, 128, ATT_SMEM>>>(aqh, aql, akh, avh, xhi, xlo, po);

    // output projection for image tokens
    dim3 go(DIM / 128, SIMG / 128);    // (24, 16)
    gemm_tc<<<go, 256, GEMM_SMEM>>>(xhi, xlo, whi + 3 * NW, bo, out);

    // raw copy of text tokens
    copy_txt<<<(STXT * DIM + 255) / 256, 256>>>(po + (size_t)SIMG * DIM,
                                                out + (size_t)SIMG * DIM);
}

// round 15
// speedup vs baseline: 8.4177x; 1.1030x over previous
#include <cuda_runtime.h>
#include <cuda_fp16.h>
#include <cstdint>
#include <math.h>

#define DIM 3072
#define HEADS 24
#define HD 128
#define SIMG 2048
#define STXT 256
#define STOT 2304

// ---------------------------------------------------------------------------
// scratch (static __device__ globals per allocation rules)
// ---------------------------------------------------------------------------
__device__ float g_q[(size_t)STOT * DIM];
__device__ float g_k[(size_t)STOT * DIM];
__device__ __half g_xhi[(size_t)STOT * DIM];
__device__ __half g_xlo[(size_t)STOT * DIM];
__device__ __half g_whi[(size_t)4 * DIM * DIM];   // 4 weight slots, hi only
__device__ __half g_qhi[(size_t)STOT * DIM];
__device__ __half g_khi[(size_t)STOT * DIM];
__device__ __half g_vhi[(size_t)STOT * DIM];

// ---------------------------------------------------------------------------
// PTX helpers
// ---------------------------------------------------------------------------
__device__ __forceinline__ void cpa16(uint32_t s, const void* g) {
    asm volatile("cp.async.cg.shared.global [%0], [%1], 16;" :: "r"(s), "l"(g));
}
__device__ __forceinline__ void ldm_x4(uint32_t addr, uint32_t* r) {
    asm volatile("ldmatrix.sync.aligned.m8n8.x4.shared.b16 {%0,%1,%2,%3}, [%4];"
        : "=r"(r[0]), "=r"(r[1]), "=r"(r[2]), "=r"(r[3]) : "r"(addr));
}
__device__ __forceinline__ void ldm_x4t(uint32_t addr, uint32_t* r) {
    asm volatile("ldmatrix.sync.aligned.m8n8.x4.trans.shared.b16 {%0,%1,%2,%3}, [%4];"
        : "=r"(r[0]), "=r"(r[1]), "=r"(r[2]), "=r"(r[3]) : "r"(addr));
}
__device__ __forceinline__ void mma_f16(float* d, const uint32_t* a,
                                        uint32_t b0, uint32_t b1) {
    asm volatile(
        "mma.sync.aligned.m16n8k16.row.col.f32.f16.f16.f32 "
        "{%0,%1,%2,%3}, {%4,%5,%6,%7}, {%8,%9}, {%0,%1,%2,%3};"
        : "+f"(d[0]), "+f"(d[1]), "+f"(d[2]), "+f"(d[3])
        : "r"(a[0]), "r"(a[1]), "r"(a[2]), "r"(a[3]), "r"(b0), "r"(b1));
}
__device__ __forceinline__ void split2h(float x, float y, uint32_t& h, uint32_t& l) {
    __half hx = __float2half_rn(x), hy = __float2half_rn(y);
    __half2 hh = __halves2half2(hx, hy);
    h = *reinterpret_cast<uint32_t*>(&hh);
    __half2 ll = __floats2half2_rn(x - __half2float(hx), y - __half2float(hy));
    l = *reinterpret_cast<uint32_t*>(&ll);
}
__device__ __forceinline__ uint32_t pack2h(float x, float y) {
    __half2 hh = __floats2half2_rn(x, y);
    return *reinterpret_cast<uint32_t*>(&hh);
}

// ---------------------------------------------------------------------------
// fp32 -> fp16 hi/lo split, 8 elems/thread
// ---------------------------------------------------------------------------
__global__ void conv_split8(const float* __restrict__ src,
                            __half* __restrict__ hi,
                            __half* __restrict__ lo, int n)
{
    int i = (blockIdx.x * blockDim.x + threadIdx.x) * 8;
    if (i >= n) return;
    float4 v0 = *(const float4*)(src + i);
    float4 v1 = *(const float4*)(src + i + 4);
    uint32_t h[4], l[4];
    split2h(v0.x, v0.y, h[0], l[0]);
    split2h(v0.z, v0.w, h[1], l[1]);
    split2h(v1.x, v1.y, h[2], l[2]);
    split2h(v1.z, v1.w, h[3], l[3]);
    *(uint4*)(hi + i) = make_uint4(h[0], h[1], h[2], h[3]);
    *(uint4*)(lo + i) = make_uint4(l[0], l[1], l[2], l[3]);
}

// fp32 -> fp16 hi only, 8 elems/thread (B-side operands)
__global__ void conv_hi8(const float* __restrict__ src,
                         __half* __restrict__ hi, int n)
{
    int i = (blockIdx.x * blockDim.x + threadIdx.x) * 8;
    if (i >= n) return;
    float4 v0 = *(const float4*)(src + i);
    float4 v1 = *(const float4*)(src + i + 4);
    uint4 h;
    h.x = pack2h(v0.x, v0.y);
    h.y = pack2h(v0.z, v0.w);
    h.z = pack2h(v1.x, v1.y);
    h.w = pack2h(v1.z, v1.w);
    *(uint4*)(hi + i) = h;
}

// ---------------------------------------------------------------------------
// Tensor-core fp16 2-term GEMM: C = (A_hi + A_lo) @ W_hi + bias.
// 128x128 block tile, BK=32, 256 threads (8 warps, 4x2), warp tile 32x64.
// 3-stage cp.async pipeline, one __syncthreads per K-iteration.
// ---------------------------------------------------------------------------
#define A_LO   5120          // elements: 128*40
#define B_HI   10240         // 2*5120
#define STG_E  14592         // stage elements (29184 bytes)
#define GEMM_SMEM (STG_E * 2 * 3)   // 87552 bytes

__device__ __forceinline__ void load_stage(
    uint32_t sb, int tid, int bm, int bn, int k0,
    const __half* Ahi, const __half* Alo, const __half* Bhi)
{
    #pragma unroll
    for (int i = 0; i < 2; i++) {
        int c = tid + i * 256;
        int r = c >> 2, cc = (c & 3) * 8;
        size_t go = (size_t)(bm + r) * DIM + k0 + cc;
        cpa16(sb + (r * 40 + cc) * 2, Ahi + go);
        cpa16(sb + (A_LO + r * 40 + cc) * 2, Alo + go);
    }
    #pragma unroll
    for (int i = 0; i < 2; i++) {
        int c = tid + i * 256;
        int r = c >> 4, cc = (c & 15) * 8;
        size_t go = (size_t)(k0 + r) * DIM + bn + cc;
        cpa16(sb + (B_HI + r * 136 + cc) * 2, Bhi + go);
    }
    asm volatile("cp.async.commit_group;" ::: "memory");
}

// If Ch != nullptr, write fp16 (hi-only) output; else fp32.
__device__ __forceinline__ void gemm_body(
    const __half* __restrict__ Ahi, const __half* __restrict__ Alo,
    const __half* __restrict__ Bhi,
    const float* __restrict__ bias, float* __restrict__ C,
    __half* __restrict__ Ch, int bm, int bn)
{
    extern __shared__ __half smbuf[];
    const int tid  = threadIdx.x;
    const int lane = tid & 31;
    const int wid  = tid >> 5;
    const int wm   = wid & 3;
    const int wn   = wid >> 2;
    uint32_t sb0 = (uint32_t)__cvta_generic_to_shared(smbuf);

    float acc[2][8][4] = {};

    const int NIT = DIM / 32;   // 96
    load_stage(sb0, tid, bm, bn, 0, Ahi, Alo, Bhi);
    load_stage(sb0 + STG_E * 2, tid, bm, bn, 32, Ahi, Alo, Bhi);

    int buf = 0;                 // it % 3
    for (int it = 0; it < NIT; it++) {
        if (it < NIT - 1) {
            asm volatile("cp.async.wait_group 1;" ::: "memory");
        } else {
            asm volatile("cp.async.wait_group 0;" ::: "memory");
        }
        __syncthreads();

        if (it + 2 < NIT) {
            int nb = buf + 2; if (nb >= 3) nb -= 3;
            load_stage(sb0 + (uint32_t)nb * (STG_E * 2), tid, bm, bn,
                       (it + 2) * 32, Ahi, Alo, Bhi);
        }

        uint32_t sb = sb0 + (uint32_t)buf * (STG_E * 2);
        #pragma unroll
        for (int kk = 0; kk < 32; kk += 16) {
            uint32_t ra_h[2][4];
            uint32_t ra_l[2][4];
            uint32_t arow = wm * 32 + (lane & 15);
            uint32_t aoff = (arow * 40 + kk + (lane >> 4) * 8) * 2;
            ldm_x4(sb + aoff, ra_h[0]);
            ldm_x4(sb + aoff + 16 * 40 * 2, ra_h[1]);
            ldm_x4(sb + A_LO * 2 + aoff, ra_l[0]);
            ldm_x4(sb + A_LO * 2 + aoff + 16 * 40 * 2, ra_l[1]);

            int g = lane >> 3;
            uint32_t brow = kk + (g & 1) * 8 + (lane & 7);
            #pragma unroll
            for (int ng = 0; ng < 4; ng++) {
                uint32_t rb_h[4];
                uint32_t col  = wn * 64 + ng * 16 + (g >> 1) * 8;
                uint32_t boff = (brow * 136 + col) * 2;
                ldm_x4t(sb + B_HI * 2 + boff, rb_h);
                #pragma unroll
                for (int mi = 0; mi < 2; mi++) {
                    int t0 = 2 * ng, t1 = 2 * ng + 1;
                    mma_f16(acc[mi][t0], ra_h[mi], rb_h[0], rb_h[1]);
                    mma_f16(acc[mi][t0], ra_l[mi], rb_h[0], rb_h[1]);
                    mma_f16(acc[mi][t1], ra_h[mi], rb_h[2], rb_h[3]);
                    mma_f16(acc[mi][t1], ra_l[mi], rb_h[2], rb_h[3]);
                }
            }
        }
        if (++buf == 3) buf = 0;
    }

    #pragma unroll
    for (int mi = 0; mi < 2; mi++) {
        int r0 = bm + wm * 32 + mi * 16 + (lane >> 2);
        #pragma unroll
        for (int t = 0; t < 8; t++) {
            int c = bn + wn * 64 + t * 8 + (lane & 3) * 2;
            float v00 = acc[mi][t][0] + bias[c];
            float v01 = acc[mi][t][1] + bias[c + 1];
            float v10 = acc[mi][t][2] + bias[c];
            float v11 = acc[mi][t][3] + bias[c + 1];
            if (Ch) {
                *(uint32_t*)(Ch + (size_t)r0 * DIM + c)       = pack2h(v00, v01);
                *(uint32_t*)(Ch + (size_t)(r0 + 8) * DIM + c) = pack2h(v10, v11);
            } else {
                C[(size_t)r0 * DIM + c]           = v00;
                C[(size_t)r0 * DIM + c + 1]       = v01;
                C[(size_t)(r0 + 8) * DIM + c]     = v10;
                C[(size_t)(r0 + 8) * DIM + c + 1] = v11;
            }
        }
    }
}

// single-weight GEMM (O projection, fp32 out)
__global__ __launch_bounds__(256, 2) void gemm_tc(
    const __half* __restrict__ Ahi, const __half* __restrict__ Alo,
    const __half* __restrict__ Bhi,
    const float* __restrict__ bias, float* __restrict__ C)
{
    gemm_body(Ahi, Alo, Bhi, bias, C, nullptr, blockIdx.y * 128, blockIdx.x * 128);
}

// fused QKV GEMM: grid.x = 72 (3 weights x 24 col tiles); V writes fp16 direct
__global__ __launch_bounds__(256, 2) void gemm_qkv(
    const __half* __restrict__ Ahi, const __half* __restrict__ Alo,
    const __half* __restrict__ WhiBase,
    const float* __restrict__ bq, const float* __restrict__ bk,
    const float* __restrict__ bv,
    float* __restrict__ pq, float* __restrict__ pk, __half* __restrict__ vh)
{
    const int sel = blockIdx.x / 24;
    const int bn  = (blockIdx.x % 24) * 128;
    const size_t NW = (size_t)DIM * DIM;
    const __half* Bhi = WhiBase + (size_t)sel * NW;
    const float* bias = (sel == 0) ? bq : (sel == 1) ? bk : bv;
    float* C = (sel == 0) ? pq : (sel == 1) ? pk : nullptr;
    __half* Ch = (sel == 2) ? vh : nullptr;
    gemm_body(Ahi, Alo, Bhi, bias, C, Ch, blockIdx.y * 128, bn);
}

// ---------------------------------------------------------------------------
// Fused per-head RMSNorm + RoPE + scale, writing fp16 hi only.
// ---------------------------------------------------------------------------
__global__ void rmsnorm_rope_hi(const float* __restrict__ in,
                                const float* __restrict__ w,
                                const float* __restrict__ cb,
                                const float* __restrict__ sb,
                                float scale,
                                __half* __restrict__ ohi)
{
    const int s = blockIdx.x, h = blockIdx.y, d = threadIdx.x;
    const float* p = in + (size_t)s * DIM + h * HD;
    float val = p[d];

    float sq = val * val;
    #pragma unroll
    for (int off = 16; off; off >>= 1) sq += __shfl_xor_sync(0xffffffffu, sq, off);
    __shared__ float red[4];
    if ((d & 31) == 0) red[d >> 5] = sq;
    __syncthreads();
    float tot = red[0] + red[1] + red[2] + red[3];

    float n = val * rsqrtf(tot * (1.0f / HD) + 1e-6f) * w[d];

    __shared__ float nv[HD];
    nv[d] = n;
    __syncthreads();

    float outv = n;
    if (s < SIMG) {
        float c  = cb[s * HD + d];
        float si = sb[s * HD + d];
        float partner = (d & 1) ? nv[d - 1] : -nv[d + 1];
        outv = n * c + partner * si;
    }
    outv *= scale;

    ohi[(size_t)s * DIM + h * HD + d] = __float2half_rn(outv);
}

// ---------------------------------------------------------------------------
// Flash attention, pure fp16 MMA (single-term), fp32 accumulators.
// Q, K single buffer; V double-buffer. smem 69632 B -> 2 CTAs/SM.
// txt rows (q0 >= SIMG) write fp32 directly into d_out.
// ---------------------------------------------------------------------------
#define AQHI 0
#define AKHI 8704
#define AVH0 17408
#define AVH1 26112
#define ATT_SMEM (34816 * 2)

__global__ __launch_bounds__(128) void attn_mma(
    const __half* __restrict__ qhi,
    const __half* __restrict__ khi, const __half* __restrict__ vhi,
    __half* __restrict__ ohi, __half* __restrict__ olo,
    float* __restrict__ o_f32)
{
    extern __shared__ __half sm2[];
    uint32_t sb = (uint32_t)__cvta_generic_to_shared(sm2);
    const int tid = threadIdx.x, lane = tid & 31, wid = tid >> 5;
    const int q0 = blockIdx.x * 64, h = blockIdx.y;

    // prologue: Q + K(0) + V(0)
    #pragma unroll
    for (int i = 0; i < 8; i++) {
        int idx = tid + i * 128, r = idx >> 4, c = (idx & 15) * 8;
        size_t gq = (size_t)(q0 + r) * DIM + h * HD + c;
        size_t gk = (size_t)r * DIM + h * HD + c;
        uint32_t so = (uint32_t)(r * 136 + c) * 2;
        cpa16(sb + AQHI * 2 + so, qhi + gq);
        cpa16(sb + AKHI * 2 + so, khi + gk);
        cpa16(sb + AVH0 * 2 + so, vhi + gk);
    }
    asm volatile("cp.async.commit_group;" ::: "memory");
    asm volatile("cp.async.wait_group 0;" ::: "memory");
    __syncthreads();

    float m0 = -1e30f, m1 = -1e30f, l0 = 0.f, l1 = 0.f;
    float oa[16][4] = {};

    const uint32_t aoff = (uint32_t)((wid * 16 + (lane & 15)) * 136 +
                                     ((lane >> 4) << 3)) * 2;
    const int brow = ((lane >> 4) << 3) + (lane & 7);
    const int bcol = ((lane >> 3) & 1) << 3;
    const int vrow = ((lane >> 3) & 1) * 8 + (lane & 7);
    const int vcol = (lane >> 4) << 3;

    const int NIT = STOT / 64;
    for (int it = 0; it < NIT; it++) {
        // ---- S = Q_hi @ K_hi^T ----
        float sc[8][4] = {};
        #pragma unroll
        for (int ks = 0; ks < 8; ks++) {
            uint32_t qh[4];
            ldm_x4(sb + AQHI * 2 + aoff + ks * 32, qh);
            #pragma unroll
            for (int bt = 0; bt < 4; bt++) {
                uint32_t kh[4];
                uint32_t ko = (uint32_t)((bt * 16 + brow) * 136 + ks * 16 + bcol) * 2;
                ldm_x4(sb + AKHI * 2 + ko, kh);
                mma_f16(sc[2 * bt],     qh, kh[0], kh[1]);
                mma_f16(sc[2 * bt + 1], qh, kh[2], kh[3]);
            }
        }
        __syncthreads();    // all warps done reading K

        // ---- prefetch K(it+1), V(it+1): overlaps softmax + PV ----
        if (it + 1 < NIT) {
            int kt = (it + 1) * 64;
            uint32_t vdst = ((it + 1) & 1) ? AVH1 : AVH0;
            #pragma unroll
            for (int i = 0; i < 8; i++) {
                int idx = tid + i * 128, r = idx >> 4, c = (idx & 15) * 8;
                size_t go = (size_t)(kt + r) * DIM + h * HD + c;
                uint32_t so = (uint32_t)(r * 136 + c) * 2;
                cpa16(sb + AKHI * 2 + so, khi + go);
                cpa16(sb + vdst * 2 + so, vhi + go);
            }
            asm volatile("cp.async.commit_group;" ::: "memory");
        }

        // ---- online softmax in registers ----
        float mx0 = -1e30f, mx1 = -1e30f;
        #pragma unroll
        for (int nt = 0; nt < 8; nt++) {
            mx0 = fmaxf(mx0, fmaxf(sc[nt][0], sc[nt][1]));
            mx1 = fmaxf(mx1, fmaxf(sc[nt][2], sc[nt][3]));
        }
        mx0 = fmaxf(mx0, __shfl_xor_sync(0xffffffffu, mx0, 1));
        mx0 = fmaxf(mx0, __shfl_xor_sync(0xffffffffu, mx0, 2));
        mx1 = fmaxf(mx1, __shfl_xor_sync(0xffffffffu, mx1, 1));
        mx1 = fmaxf(mx1, __shfl_xor_sync(0xffffffffu, mx1, 2));
        float mn0 = fmaxf(m0, mx0), mn1 = fmaxf(m1, mx1);
        float c0 = __expf(m0 - mn0), c1 = __expf(m1 - mn1);
        float ls0 = 0.f, ls1 = 0.f;
        #pragma unroll
        for (int nt = 0; nt < 8; nt++) {
            sc[nt][0] = __expf(sc[nt][0] - mn0);
            sc[nt][1] = __expf(sc[nt][1] - mn0);
            sc[nt][2] = __expf(sc[nt][2] - mn1);
            sc[nt][3] = __expf(sc[nt][3] - mn1);
            ls0 += sc[nt][0] + sc[nt][1];
            ls1 += sc[nt][2] + sc[nt][3];
        }
        ls0 += __shfl_xor_sync(0xffffffffu, ls0, 1);
        ls0 += __shfl_xor_sync(0xffffffffu, ls0, 2);
        ls1 += __shfl_xor_sync(0xffffffffu, ls1, 1);
        ls1 += __shfl_xor_sync(0xffffffffu, ls1, 2);
        m0 = mn0; m1 = mn1;
        l0 = l0 * c0 + ls0;
        l1 = l1 * c1 + ls1;
        #pragma unroll
        for (int nt = 0; nt < 16; nt++) {
            oa[nt][0] *= c0; oa[nt][1] *= c0;
            oa[nt][2] *= c1; oa[nt][3] *= c1;
        }

        // ---- P frags (fp16 hi only, registers) ----
        uint32_t ph[4][4];
        #pragma unroll
        for (int t = 0; t < 4; t++) {
            ph[t][0] = pack2h(sc[2 * t][0],     sc[2 * t][1]);
            ph[t][1] = pack2h(sc[2 * t][2],     sc[2 * t][3]);
            ph[t][2] = pack2h(sc[2 * t + 1][0], sc[2 * t + 1][1]);
            ph[t][3] = pack2h(sc[2 * t + 1][2], sc[2 * t + 1][3]);
        }

        // ---- O += P_hi @ V_hi (reads V[it&1]) ----
        uint32_t vbase = (it & 1) ? AVH1 : AVH0;
        #pragma unroll
        for (int kst = 0; kst < 4; kst++) {
            #pragma unroll
            for (int dt = 0; dt < 8; dt++) {
                uint32_t vh[4];
                uint32_t vo = (uint32_t)((kst * 16 + vrow) * 136 + dt * 16 + vcol) * 2;
                ldm_x4t(sb + vbase * 2 + vo, vh);
                mma_f16(oa[2 * dt],     ph[kst], vh[0], vh[1]);
                mma_f16(oa[2 * dt + 1], ph[kst], vh[2], vh[3]);
            }
        }

        if (it + 1 < NIT) {
            asm volatile("cp.async.wait_group 0;" ::: "memory");
        }
        __syncthreads();
    }

    // ---- normalize + store: split fp16 for O-proj; fp32 direct to d_out for txt ----
    float inv0 = 1.0f / l0, inv1 = 1.0f / l1;
    int r0 = q0 + wid * 16 + (lane >> 2);
    int cb0 = h * HD + (lane & 3) * 2;
    const bool wr32 = (q0 >= SIMG);
    #pragma unroll
    for (int nt = 0; nt < 16; nt++) {
        float a0 = oa[nt][0] * inv0, a1 = oa[nt][1] * inv0;
        float a2 = oa[nt][2] * inv1, a3 = oa[nt][3] * inv1;
        uint32_t h0, lo0, h1, lo1;
        split2h(a0, a1, h0, lo0);
        split2h(a2, a3, h1, lo1);
        size_t off0 = (size_t)r0 * DIM + cb0 + nt * 8;
        size_t off1 = (size_t)(r0 + 8) * DIM + cb0 + nt * 8;
        *(uint32_t*)(ohi + off0) = h0;
        *(uint32_t*)(olo + off0) = lo0;
        *(uint32_t*)(ohi + off1) = h1;
        *(uint32_t*)(olo + off1) = lo1;
        if (wr32) {
            *(float2*)(o_f32 + off0) = make_float2(a0, a1);
            *(float2*)(o_f32 + off1) = make_float2(a2, a3);
        }
    }
}

// ---------------------------------------------------------------------------
extern "C" void kernel_launch(void* const* d_in, const int* in_sizes, int n_in,
                              void* d_out, int out_size)
{
    const float* hidden = (const float*)d_in[0];
    const float* enc    = (const float*)d_in[1];
    const float* cosb   = (const float*)d_in[2];
    const float* sinb   = (const float*)d_in[3];
    const float* wq     = (const float*)d_in[4];
    const float* bq     = (const float*)d_in[5];
    const float* wk     = (const float*)d_in[6];
    const float* bk     = (const float*)d_in[7];
    const float* wv     = (const float*)d_in[8];
    const float* bv     = (const float*)d_in[9];
    const float* nqw    = (const float*)d_in[10];
    const float* nkw    = (const float*)d_in[11];
    const float* wo     = (const float*)d_in[12];
    const float* bo     = (const float*)d_in[13];
    float* out = (float*)d_out;

    float *pq, *pk;
    __half *xhi, *xlo, *whi;
    __half *aqh, *akh, *avh;
    cudaGetSymbolAddress((void**)&pq, g_q);
    cudaGetSymbolAddress((void**)&pk, g_k);
    cudaGetSymbolAddress((void**)&xhi, g_xhi);
    cudaGetSymbolAddress((void**)&xlo, g_xlo);
    cudaGetSymbolAddress((void**)&whi, g_whi);
    cudaGetSymbolAddress((void**)&aqh, g_qhi);
    cudaGetSymbolAddress((void**)&akh, g_khi);
    cudaGetSymbolAddress((void**)&avh, g_vhi);

    cudaFuncSetAttribute(gemm_tc, cudaFuncAttributeMaxDynamicSharedMemorySize,
                         GEMM_SMEM);
    cudaFuncSetAttribute(gemm_qkv, cudaFuncAttributeMaxDynamicSharedMemorySize,
                         GEMM_SMEM);
    cudaFuncSetAttribute(attn_mma, cudaFuncAttributeMaxDynamicSharedMemorySize,
                         ATT_SMEM);

    const size_t NW = (size_t)DIM * DIM;
    const int conv_blk = 256;
    const int grid_w = (int)((NW / 8 + conv_blk - 1) / conv_blk);

    // --- all conversions up front ---
    conv_split8<<<(SIMG * DIM / 8 + 255) / 256, 256>>>(hidden, xhi, xlo, SIMG * DIM);
    conv_split8<<<(STXT * DIM / 8 + 255) / 256, 256>>>(
        enc, xhi + (size_t)SIMG * DIM, xlo + (size_t)SIMG * DIM, STXT * DIM);
    conv_hi8<<<grid_w, conv_blk>>>(wq, whi + 0 * NW, (int)NW);
    conv_hi8<<<grid_w, conv_blk>>>(wk, whi + 1 * NW, (int)NW);
    conv_hi8<<<grid_w, conv_blk>>>(wv, whi + 2 * NW, (int)NW);
    conv_hi8<<<grid_w, conv_blk>>>(wo, whi + 3 * NW, (int)NW);

    // fused Q, K, V projections (V writes fp16 directly)
    dim3 gq(72, STOT / 128);           // (72, 18)
    gemm_qkv<<<gq, 256, GEMM_SMEM>>>(xhi, xlo, whi, bq, bk, bv, pq, pk, avh);

    // per-head RMSNorm + RoPE -> fp16 hi (scale folded into Q)
    dim3 gn(STOT, HEADS);
    rmsnorm_rope_hi<<<gn, 128>>>(pq, nqw, cosb, sinb,
                                 0.08838834764831845f, aqh);
    rmsnorm_rope_hi<<<gn, 128>>>(pk, nkw, cosb, sinb, 1.0f, akh);

    // attention (pure fp16 mma) -> split fp16 for O-proj; txt fp32 direct to out
    dim3 ga(STOT / 64, HEADS);         // (36, 24)
    attn_mma<<<ga, 128, ATT_SMEM>>>(aqh, akh, avh, xhi, xlo, out);

    // output projection for image tokens
    dim3 go(DIM / 128, SIMG / 128);    // (24, 16)
    gemm_tc<<<go, 256, GEMM_SMEM>>>(xhi, xlo, whi + 3 * NW, bo, out);
}

// round 16
// speedup vs baseline: 9.5173x; 1.1306x over previous
#include <cuda_runtime.h>
#include <cuda_fp16.h>
#include <cstdint>
#include <math.h>

#define DIM 3072
#define HEADS 24
#define HD 128
#define SIMG 2048
#define STXT 256
#define STOT 2304

// ---------------------------------------------------------------------------
// scratch (static __device__ globals per allocation rules)
// ---------------------------------------------------------------------------
__device__ float g_q[(size_t)STOT * DIM];
__device__ float g_k[(size_t)STOT * DIM];
__device__ __half g_xhi[(size_t)STOT * DIM];
__device__ __half g_xlo[(size_t)STOT * DIM];
__device__ __half g_whi[(size_t)4 * DIM * DIM];   // 4 weight slots, hi only
__device__ __half g_qhi[(size_t)STOT * DIM];
__device__ __half g_khi[(size_t)STOT * DIM];
__device__ __half g_vhi[(size_t)STOT * DIM];

// ---------------------------------------------------------------------------
// PTX helpers
// ---------------------------------------------------------------------------
__device__ __forceinline__ void cpa16(uint32_t s, const void* g) {
    asm volatile("cp.async.cg.shared.global [%0], [%1], 16;" :: "r"(s), "l"(g));
}
__device__ __forceinline__ void ldm_x4(uint32_t addr, uint32_t* r) {
    asm volatile("ldmatrix.sync.aligned.m8n8.x4.shared.b16 {%0,%1,%2,%3}, [%4];"
        : "=r"(r[0]), "=r"(r[1]), "=r"(r[2]), "=r"(r[3]) : "r"(addr));
}
__device__ __forceinline__ void ldm_x4t(uint32_t addr, uint32_t* r) {
    asm volatile("ldmatrix.sync.aligned.m8n8.x4.trans.shared.b16 {%0,%1,%2,%3}, [%4];"
        : "=r"(r[0]), "=r"(r[1]), "=r"(r[2]), "=r"(r[3]) : "r"(addr));
}
__device__ __forceinline__ void mma_f16(float* d, const uint32_t* a,
                                        uint32_t b0, uint32_t b1) {
    asm volatile(
        "mma.sync.aligned.m16n8k16.row.col.f32.f16.f16.f32 "
        "{%0,%1,%2,%3}, {%4,%5,%6,%7}, {%8,%9}, {%0,%1,%2,%3};"
        : "+f"(d[0]), "+f"(d[1]), "+f"(d[2]), "+f"(d[3])
        : "r"(a[0]), "r"(a[1]), "r"(a[2]), "r"(a[3]), "r"(b0), "r"(b1));
}
__device__ __forceinline__ void split2h(float x, float y, uint32_t& h, uint32_t& l) {
    __half hx = __float2half_rn(x), hy = __float2half_rn(y);
    __half2 hh = __halves2half2(hx, hy);
    h = *reinterpret_cast<uint32_t*>(&hh);
    __half2 ll = __floats2half2_rn(x - __half2float(hx), y - __half2float(hy));
    l = *reinterpret_cast<uint32_t*>(&ll);
}
__device__ __forceinline__ uint32_t pack2h(float x, float y) {
    __half2 hh = __floats2half2_rn(x, y);
    return *reinterpret_cast<uint32_t*>(&hh);
}

// ---------------------------------------------------------------------------
// fp32 -> fp16 hi/lo split, 8 elems/thread
// ---------------------------------------------------------------------------
__global__ void conv_split8(const float* __restrict__ src,
                            __half* __restrict__ hi,
                            __half* __restrict__ lo, int n)
{
    int i = (blockIdx.x * blockDim.x + threadIdx.x) * 8;
    if (i >= n) return;
    float4 v0 = *(const float4*)(src + i);
    float4 v1 = *(const float4*)(src + i + 4);
    uint32_t h[4], l[4];
    split2h(v0.x, v0.y, h[0], l[0]);
    split2h(v0.z, v0.w, h[1], l[1]);
    split2h(v1.x, v1.y, h[2], l[2]);
    split2h(v1.z, v1.w, h[3], l[3]);
    *(uint4*)(hi + i) = make_uint4(h[0], h[1], h[2], h[3]);
    *(uint4*)(lo + i) = make_uint4(l[0], l[1], l[2], l[3]);
}

// fp32 -> fp16 hi only, 8 elems/thread (B-side operands)
__global__ void conv_hi8(const float* __restrict__ src,
                         __half* __restrict__ hi, int n)
{
    int i = (blockIdx.x * blockDim.x + threadIdx.x) * 8;
    if (i >= n) return;
    float4 v0 = *(const float4*)(src + i);
    float4 v1 = *(const float4*)(src + i + 4);
    uint4 h;
    h.x = pack2h(v0.x, v0.y);
    h.y = pack2h(v0.z, v0.w);
    h.z = pack2h(v1.x, v1.y);
    h.w = pack2h(v1.z, v1.w);
    *(uint4*)(hi + i) = h;
}

// ---------------------------------------------------------------------------
// Tensor-core fp16 GEMM: C = A @ W_hi + bias.
// TWO=true: A = A_hi + A_lo (2 mma terms); TWO=false: A = A_hi (1 term).
// 128x128 block tile, BK=32, 256 threads (8 warps, 4x2), warp tile 32x64.
// 3-stage cp.async pipeline, one __syncthreads per K-iteration.
// ---------------------------------------------------------------------------
#define A_LO   5120          // elements: 128*40
#define B_HI   10240         // 2*5120
#define STG_E  14592         // stage elements (29184 bytes)
#define GEMM_SMEM (STG_E * 2 * 3)   // 87552 bytes

template<bool TWO>
__device__ __forceinline__ void load_stage(
    uint32_t sb, int tid, int bm, int bn, int k0,
    const __half* Ahi, const __half* Alo, const __half* Bhi)
{
    #pragma unroll
    for (int i = 0; i < 2; i++) {
        int c = tid + i * 256;
        int r = c >> 2, cc = (c & 3) * 8;
        size_t go = (size_t)(bm + r) * DIM + k0 + cc;
        cpa16(sb + (r * 40 + cc) * 2, Ahi + go);
        if (TWO) cpa16(sb + (A_LO + r * 40 + cc) * 2, Alo + go);
    }
    #pragma unroll
    for (int i = 0; i < 2; i++) {
        int c = tid + i * 256;
        int r = c >> 4, cc = (c & 15) * 8;
        size_t go = (size_t)(k0 + r) * DIM + bn + cc;
        cpa16(sb + (B_HI + r * 136 + cc) * 2, Bhi + go);
    }
    asm volatile("cp.async.commit_group;" ::: "memory");
}

// If Ch != nullptr, write fp16 (hi-only) output; else fp32.
template<bool TWO>
__device__ __forceinline__ void gemm_body(
    const __half* __restrict__ Ahi, const __half* __restrict__ Alo,
    const __half* __restrict__ Bhi,
    const float* __restrict__ bias, float* __restrict__ C,
    __half* __restrict__ Ch, int bm, int bn)
{
    extern __shared__ __half smbuf[];
    const int tid  = threadIdx.x;
    const int lane = tid & 31;
    const int wid  = tid >> 5;
    const int wm   = wid & 3;
    const int wn   = wid >> 2;
    uint32_t sb0 = (uint32_t)__cvta_generic_to_shared(smbuf);

    float acc[2][8][4] = {};

    const int NIT = DIM / 32;   // 96
    load_stage<TWO>(sb0, tid, bm, bn, 0, Ahi, Alo, Bhi);
    load_stage<TWO>(sb0 + STG_E * 2, tid, bm, bn, 32, Ahi, Alo, Bhi);

    int buf = 0;                 // it % 3
    for (int it = 0; it < NIT; it++) {
        if (it < NIT - 1) {
            asm volatile("cp.async.wait_group 1;" ::: "memory");
        } else {
            asm volatile("cp.async.wait_group 0;" ::: "memory");
        }
        __syncthreads();

        if (it + 2 < NIT) {
            int nb = buf + 2; if (nb >= 3) nb -= 3;
            load_stage<TWO>(sb0 + (uint32_t)nb * (STG_E * 2), tid, bm, bn,
                            (it + 2) * 32, Ahi, Alo, Bhi);
        }

        uint32_t sb = sb0 + (uint32_t)buf * (STG_E * 2);
        #pragma unroll
        for (int kk = 0; kk < 32; kk += 16) {
            uint32_t ra_h[2][4];
            uint32_t ra_l[2][4];
            uint32_t arow = wm * 32 + (lane & 15);
            uint32_t aoff = (arow * 40 + kk + (lane >> 4) * 8) * 2;
            ldm_x4(sb + aoff, ra_h[0]);
            ldm_x4(sb + aoff + 16 * 40 * 2, ra_h[1]);
            if (TWO) {
                ldm_x4(sb + A_LO * 2 + aoff, ra_l[0]);
                ldm_x4(sb + A_LO * 2 + aoff + 16 * 40 * 2, ra_l[1]);
            }

            int g = lane >> 3;
            uint32_t brow = kk + (g & 1) * 8 + (lane & 7);
            #pragma unroll
            for (int ng = 0; ng < 4; ng++) {
                uint32_t rb_h[4];
                uint32_t col  = wn * 64 + ng * 16 + (g >> 1) * 8;
                uint32_t boff = (brow * 136 + col) * 2;
                ldm_x4t(sb + B_HI * 2 + boff, rb_h);
                #pragma unroll
                for (int mi = 0; mi < 2; mi++) {
                    int t0 = 2 * ng, t1 = 2 * ng + 1;
                    mma_f16(acc[mi][t0], ra_h[mi], rb_h[0], rb_h[1]);
                    if (TWO) mma_f16(acc[mi][t0], ra_l[mi], rb_h[0], rb_h[1]);
                    mma_f16(acc[mi][t1], ra_h[mi], rb_h[2], rb_h[3]);
                    if (TWO) mma_f16(acc[mi][t1], ra_l[mi], rb_h[2], rb_h[3]);
                }
            }
        }
        if (++buf == 3) buf = 0;
    }

    #pragma unroll
    for (int mi = 0; mi < 2; mi++) {
        int r0 = bm + wm * 32 + mi * 16 + (lane >> 2);
        #pragma unroll
        for (int t = 0; t < 8; t++) {
            int c = bn + wn * 64 + t * 8 + (lane & 3) * 2;
            float v00 = acc[mi][t][0] + bias[c];
            float v01 = acc[mi][t][1] + bias[c + 1];
            float v10 = acc[mi][t][2] + bias[c];
            float v11 = acc[mi][t][3] + bias[c + 1];
            if (Ch) {
                *(uint32_t*)(Ch + (size_t)r0 * DIM + c)       = pack2h(v00, v01);
                *(uint32_t*)(Ch + (size_t)(r0 + 8) * DIM + c) = pack2h(v10, v11);
            } else {
                C[(size_t)r0 * DIM + c]           = v00;
                C[(size_t)r0 * DIM + c + 1]       = v01;
                C[(size_t)(r0 + 8) * DIM + c]     = v10;
                C[(size_t)(r0 + 8) * DIM + c + 1] = v11;
            }
        }
    }
}

// O projection: single-term (last layer, error does not propagate), fp32 out
__global__ __launch_bounds__(256, 2) void gemm_o(
    const __half* __restrict__ Ahi, const __half* __restrict__ Bhi,
    const float* __restrict__ bias, float* __restrict__ C)
{
    gemm_body<false>(Ahi, nullptr, Bhi, bias, C, nullptr,
                     blockIdx.y * 128, blockIdx.x * 128);
}

// fused QKV GEMM (2-term): grid.x = 72; V writes fp16 direct
__global__ __launch_bounds__(256, 2) void gemm_qkv(
    const __half* __restrict__ Ahi, const __half* __restrict__ Alo,
    const __half* __restrict__ WhiBase,
    const float* __restrict__ bq, const float* __restrict__ bk,
    const float* __restrict__ bv,
    float* __restrict__ pq, float* __restrict__ pk, __half* __restrict__ vh)
{
    const int sel = blockIdx.x / 24;
    const int bn  = (blockIdx.x % 24) * 128;
    const size_t NW = (size_t)DIM * DIM;
    const __half* Bhi = WhiBase + (size_t)sel * NW;
    const float* bias = (sel == 0) ? bq : (sel == 1) ? bk : bv;
    float* C = (sel == 0) ? pq : (sel == 1) ? pk : nullptr;
    __half* Ch = (sel == 2) ? vh : nullptr;
    gemm_body<true>(Ahi, Alo, Bhi, bias, C, Ch, blockIdx.y * 128, bn);
}

// ---------------------------------------------------------------------------
// Fused per-head RMSNorm + RoPE + scale -> fp16 hi.
// One warp per (token, head); 8 warps/block; float4 per lane.
// RoPE pairs (2i, 2i+1) are inside each lane's float4 — no exchange needed.
// ---------------------------------------------------------------------------
__global__ __launch_bounds__(256) void rmsnorm_rope_hi(
    const float* __restrict__ in, const float* __restrict__ w,
    const float* __restrict__ cb, const float* __restrict__ sb,
    float scale, __half* __restrict__ ohi)
{
    const int warp = threadIdx.x >> 5, lane = threadIdx.x & 31;
    const int ghi = blockIdx.x * 8 + warp;
    const int s = ghi / HEADS, h = ghi - s * HEADS;
    const size_t base = (size_t)s * DIM + h * HD + lane * 4;

    float4 v = *(const float4*)(in + base);
    float sq = v.x * v.x + v.y * v.y + v.z * v.z + v.w * v.w;
    #pragma unroll
    for (int off = 16; off; off >>= 1) sq += __shfl_xor_sync(0xffffffffu, sq, off);

    float inv = rsqrtf(sq * (1.0f / HD) + 1e-6f) * scale;
    float4 w4 = *(const float4*)(w + lane * 4);
    float n0 = v.x * inv * w4.x;
    float n1 = v.y * inv * w4.y;
    float n2 = v.z * inv * w4.z;
    float n3 = v.w * inv * w4.w;

    float o0 = n0, o1 = n1, o2 = n2, o3 = n3;
    if (s < SIMG) {
        float4 c4 = *(const float4*)(cb + s * HD + lane * 4);
        float4 s4 = *(const float4*)(sb + s * HD + lane * 4);
        o0 = n0 * c4.x - n1 * s4.x;
        o1 = n1 * c4.y + n0 * s4.y;
        o2 = n2 * c4.z - n3 * s4.z;
        o3 = n3 * c4.w + n2 * s4.w;
    }
    *(uint2*)(ohi + base) = make_uint2(pack2h(o0, o1), pack2h(o2, o3));
}

// ---------------------------------------------------------------------------
// Flash attention, pure fp16 MMA (single-term), fp32 accumulators.
// Q, K single buffer; V double-buffer. smem 69632 B -> 2 CTAs/SM.
// txt rows (q0 >= SIMG) write fp32 directly into d_out; img rows write fp16 hi.
// ---------------------------------------------------------------------------
#define AQHI 0
#define AKHI 8704
#define AVH0 17408
#define AVH1 26112
#define ATT_SMEM (34816 * 2)

__global__ __launch_bounds__(128) void attn_mma(
    const __half* __restrict__ qhi,
    const __half* __restrict__ khi, const __half* __restrict__ vhi,
    __half* __restrict__ ohi, float* __restrict__ o_f32)
{
    extern __shared__ __half sm2[];
    uint32_t sb = (uint32_t)__cvta_generic_to_shared(sm2);
    const int tid = threadIdx.x, lane = tid & 31, wid = tid >> 5;
    const int q0 = blockIdx.x * 64, h = blockIdx.y;

    // prologue: Q + K(0) + V(0)
    #pragma unroll
    for (int i = 0; i < 8; i++) {
        int idx = tid + i * 128, r = idx >> 4, c = (idx & 15) * 8;
        size_t gq = (size_t)(q0 + r) * DIM + h * HD + c;
        size_t gk = (size_t)r * DIM + h * HD + c;
        uint32_t so = (uint32_t)(r * 136 + c) * 2;
        cpa16(sb + AQHI * 2 + so, qhi + gq);
        cpa16(sb + AKHI * 2 + so, khi + gk);
        cpa16(sb + AVH0 * 2 + so, vhi + gk);
    }
    asm volatile("cp.async.commit_group;" ::: "memory");
    asm volatile("cp.async.wait_group 0;" ::: "memory");
    __syncthreads();

    float m0 = -1e30f, m1 = -1e30f, l0 = 0.f, l1 = 0.f;
    float oa[16][4] = {};

    const uint32_t aoff = (uint32_t)((wid * 16 + (lane & 15)) * 136 +
                                     ((lane >> 4) << 3)) * 2;
    const int brow = ((lane >> 4) << 3) + (lane & 7);
    const int bcol = ((lane >> 3) & 1) << 3;
    const int vrow = ((lane >> 3) & 1) * 8 + (lane & 7);
    const int vcol = (lane >> 4) << 3;

    const int NIT = STOT / 64;
    for (int it = 0; it < NIT; it++) {
        // ---- S = Q_hi @ K_hi^T ----
        float sc[8][4] = {};
        #pragma unroll
        for (int ks = 0; ks < 8; ks++) {
            uint32_t qh[4];
            ldm_x4(sb + AQHI * 2 + aoff + ks * 32, qh);
            #pragma unroll
            for (int bt = 0; bt < 4; bt++) {
                uint32_t kh[4];
                uint32_t ko = (uint32_t)((bt * 16 + brow) * 136 + ks * 16 + bcol) * 2;
                ldm_x4(sb + AKHI * 2 + ko, kh);
                mma_f16(sc[2 * bt],     qh, kh[0], kh[1]);
                mma_f16(sc[2 * bt + 1], qh, kh[2], kh[3]);
            }
        }
        __syncthreads();    // all warps done reading K

        // ---- prefetch K(it+1), V(it+1): overlaps softmax + PV ----
        if (it + 1 < NIT) {
            int kt = (it + 1) * 64;
            uint32_t vdst = ((it + 1) & 1) ? AVH1 : AVH0;
            #pragma unroll
            for (int i = 0; i < 8; i++) {
                int idx = tid + i * 128, r = idx >> 4, c = (idx & 15) * 8;
                size_t go = (size_t)(kt + r) * DIM + h * HD + c;
                uint32_t so = (uint32_t)(r * 136 + c) * 2;
                cpa16(sb + AKHI * 2 + so, khi + go);
                cpa16(sb + vdst * 2 + so, vhi + go);
            }
            asm volatile("cp.async.commit_group;" ::: "memory");
        }

        // ---- online softmax in registers ----
        float mx0 = -1e30f, mx1 = -1e30f;
        #pragma unroll
        for (int nt = 0; nt < 8; nt++) {
            mx0 = fmaxf(mx0, fmaxf(sc[nt][0], sc[nt][1]));
            mx1 = fmaxf(mx1, fmaxf(sc[nt][2], sc[nt][3]));
        }
        mx0 = fmaxf(mx0, __shfl_xor_sync(0xffffffffu, mx0, 1));
        mx0 = fmaxf(mx0, __shfl_xor_sync(0xffffffffu, mx0, 2));
        mx1 = fmaxf(mx1, __shfl_xor_sync(0xffffffffu, mx1, 1));
        mx1 = fmaxf(mx1, __shfl_xor_sync(0xffffffffu, mx1, 2));
        float mn0 = fmaxf(m0, mx0), mn1 = fmaxf(m1, mx1);
        float c0 = __expf(m0 - mn0), c1 = __expf(m1 - mn1);
        float ls0 = 0.f, ls1 = 0.f;
        #pragma unroll
        for (int nt = 0; nt < 8; nt++) {
            sc[nt][0] = __expf(sc[nt][0] - mn0);
            sc[nt][1] = __expf(sc[nt][1] - mn0);
            sc[nt][2] = __expf(sc[nt][2] - mn1);
            sc[nt][3] = __expf(sc[nt][3] - mn1);
            ls0 += sc[nt][0] + sc[nt][1];
            ls1 += sc[nt][2] + sc[nt][3];
        }
        ls0 += __shfl_xor_sync(0xffffffffu, ls0, 1);
        ls0 += __shfl_xor_sync(0xffffffffu, ls0, 2);
        ls1 += __shfl_xor_sync(0xffffffffu, ls1, 1);
        ls1 += __shfl_xor_sync(0xffffffffu, ls1, 2);
        m0 = mn0; m1 = mn1;
        l0 = l0 * c0 + ls0;
        l1 = l1 * c1 + ls1;
        #pragma unroll
        for (int nt = 0; nt < 16; nt++) {
            oa[nt][0] *= c0; oa[nt][1] *= c0;
            oa[nt][2] *= c1; oa[nt][3] *= c1;
        }

        // ---- P frags (fp16 hi only, registers) ----
        uint32_t ph[4][4];
        #pragma unroll
        for (int t = 0; t < 4; t++) {
            ph[t][0] = pack2h(sc[2 * t][0],     sc[2 * t][1]);
            ph[t][1] = pack2h(sc[2 * t][2],     sc[2 * t][3]);
            ph[t][2] = pack2h(sc[2 * t + 1][0], sc[2 * t + 1][1]);
            ph[t][3] = pack2h(sc[2 * t + 1][2], sc[2 * t + 1][3]);
        }

        // ---- O += P_hi @ V_hi (reads V[it&1]) ----
        uint32_t vbase = (it & 1) ? AVH1 : AVH0;
        #pragma unroll
        for (int kst = 0; kst < 4; kst++) {
            #pragma unroll
            for (int dt = 0; dt < 8; dt++) {
                uint32_t vh[4];
                uint32_t vo = (uint32_t)((kst * 16 + vrow) * 136 + dt * 16 + vcol) * 2;
                ldm_x4t(sb + vbase * 2 + vo, vh);
                mma_f16(oa[2 * dt],     ph[kst], vh[0], vh[1]);
                mma_f16(oa[2 * dt + 1], ph[kst], vh[2], vh[3]);
            }
        }

        if (it + 1 < NIT) {
            asm volatile("cp.async.wait_group 0;" ::: "memory");
        }
        __syncthreads();
    }

    // ---- normalize + store: fp16 hi for O-proj; fp32 direct to d_out for txt ----
    float inv0 = 1.0f / l0, inv1 = 1.0f / l1;
    int r0 = q0 + wid * 16 + (lane >> 2);
    int cb0 = h * HD + (lane & 3) * 2;
    const bool wr32 = (q0 >= SIMG);
    #pragma unroll
    for (int nt = 0; nt < 16; nt++) {
        float a0 = oa[nt][0] * inv0, a1 = oa[nt][1] * inv0;
        float a2 = oa[nt][2] * inv1, a3 = oa[nt][3] * inv1;
        size_t off0 = (size_t)r0 * DIM + cb0 + nt * 8;
        size_t off1 = (size_t)(r0 + 8) * DIM + cb0 + nt * 8;
        *(uint32_t*)(ohi + off0) = pack2h(a0, a1);
        *(uint32_t*)(ohi + off1) = pack2h(a2, a3);
        if (wr32) {
            *(float2*)(o_f32 + off0) = make_float2(a0, a1);
            *(float2*)(o_f32 + off1) = make_float2(a2, a3);
        }
    }
}

// ---------------------------------------------------------------------------
extern "C" void kernel_launch(void* const* d_in, const int* in_sizes, int n_in,
                              void* d_out, int out_size)
{
    const float* hidden = (const float*)d_in[0];
    const float* enc    = (const float*)d_in[1];
    const float* cosb   = (const float*)d_in[2];
    const float* sinb   = (const float*)d_in[3];
    const float* wq     = (const float*)d_in[4];
    const float* bq     = (const float*)d_in[5];
    const float* wk     = (const float*)d_in[6];
    const float* bk     = (const float*)d_in[7];
    const float* wv     = (const float*)d_in[8];
    const float* bv     = (const float*)d_in[9];
    const float* nqw    = (const float*)d_in[10];
    const float* nkw    = (const float*)d_in[11];
    const float* wo     = (const float*)d_in[12];
    const float* bo     = (const float*)d_in[13];
    float* out = (float*)d_out;

    float *pq, *pk;
    __half *xhi, *xlo, *whi;
    __half *aqh, *akh, *avh;
    cudaGetSymbolAddress((void**)&pq, g_q);
    cudaGetSymbolAddress((void**)&pk, g_k);
    cudaGetSymbolAddress((void**)&xhi, g_xhi);
    cudaGetSymbolAddress((void**)&xlo, g_xlo);
    cudaGetSymbolAddress((void**)&whi, g_whi);
    cudaGetSymbolAddress((void**)&aqh, g_qhi);
    cudaGetSymbolAddress((void**)&akh, g_khi);
    cudaGetSymbolAddress((void**)&avh, g_vhi);

    cudaFuncSetAttribute(gemm_o, cudaFuncAttributeMaxDynamicSharedMemorySize,
                         GEMM_SMEM);
    cudaFuncSetAttribute(gemm_qkv, cudaFuncAttributeMaxDynamicSharedMemorySize,
                         GEMM_SMEM);
    cudaFuncSetAttribute(attn_mma, cudaFuncAttributeMaxDynamicSharedMemorySize,
                         ATT_SMEM);

    const size_t NW = (size_t)DIM * DIM;
    const int conv_blk = 256;
    const int grid_w = (int)((NW / 8 + conv_blk - 1) / conv_blk);

    // --- all conversions up front ---
    conv_split8<<<(SIMG * DIM / 8 + 255) / 256, 256>>>(hidden, xhi, xlo, SIMG * DIM);
    conv_split8<<<(STXT * DIM / 8 + 255) / 256, 256>>>(
        enc, xhi + (size_t)SIMG * DIM, xlo + (size_t)SIMG * DIM, STXT * DIM);
    conv_hi8<<<grid_w, conv_blk>>>(wq, whi + 0 * NW, (int)NW);
    conv_hi8<<<grid_w, conv_blk>>>(wk, whi + 1 * NW, (int)NW);
    conv_hi8<<<grid_w, conv_blk>>>(wv, whi + 2 * NW, (int)NW);
    conv_hi8<<<grid_w, conv_blk>>>(wo, whi + 3 * NW, (int)NW);

    // fused Q, K, V projections (V writes fp16 directly)
    dim3 gq(72, STOT / 128);           // (72, 18)
    gemm_qkv<<<gq, 256, GEMM_SMEM>>>(xhi, xlo, whi, bq, bk, bv, pq, pk, avh);

    // per-head RMSNorm + RoPE -> fp16 hi (scale folded into Q); warp-per-head
    const int rms_grid = STOT * HEADS / 8;   // 6912
    rmsnorm_rope_hi<<<rms_grid, 256>>>(pq, nqw, cosb, sinb,
                                       0.08838834764831845f, aqh);
    rmsnorm_rope_hi<<<rms_grid, 256>>>(pk, nkw, cosb, sinb, 1.0f, akh);

    // attention (pure fp16 mma) -> fp16 hi for O-proj; txt fp32 direct to out
    dim3 ga(STOT / 64, HEADS);         // (36, 24)
    attn_mma<<<ga, 128, ATT_SMEM>>>(aqh, akh, avh, xhi, out);

    // output projection for image tokens (single-term fp16)
    dim3 go(DIM / 128, SIMG / 128);    // (24, 16)
    gemm_o<<<go, 256, GEMM_SMEM>>>(xhi, whi + 3 * NW, bo, out);
}

// round 17
// speedup vs baseline: 13.0677x; 1.3730x over previous
#include <cuda_runtime.h>
#include <cuda_fp16.h>
#include <cstdint>
#include <math.h>

#define DIM 3072
#define HEADS 24
#define HD 128
#define SIMG 2048
#define STXT 256
#define STOT 2304

// ---------------------------------------------------------------------------
// scratch (static __device__ globals per allocation rules)
// ---------------------------------------------------------------------------
__device__ float g_q[(size_t)STOT * DIM];
__device__ float g_k[(size_t)STOT * DIM];
__device__ __half g_xhi[(size_t)STOT * DIM];
__device__ __half g_whi[(size_t)4 * DIM * DIM];   // 4 weight slots, hi only
__device__ __half g_qhi[(size_t)STOT * DIM];
__device__ __half g_khi[(size_t)STOT * DIM];
__device__ __half g_vhi[(size_t)STOT * DIM];

// ---------------------------------------------------------------------------
// PTX helpers
// ---------------------------------------------------------------------------
__device__ __forceinline__ void cpa16(uint32_t s, const void* g) {
    asm volatile("cp.async.cg.shared.global [%0], [%1], 16;" :: "r"(s), "l"(g));
}
__device__ __forceinline__ void ldm_x4(uint32_t addr, uint32_t* r) {
    asm volatile("ldmatrix.sync.aligned.m8n8.x4.shared.b16 {%0,%1,%2,%3}, [%4];"
        : "=r"(r[0]), "=r"(r[1]), "=r"(r[2]), "=r"(r[3]) : "r"(addr));
}
__device__ __forceinline__ void ldm_x4t(uint32_t addr, uint32_t* r) {
    asm volatile("ldmatrix.sync.aligned.m8n8.x4.trans.shared.b16 {%0,%1,%2,%3}, [%4];"
        : "=r"(r[0]), "=r"(r[1]), "=r"(r[2]), "=r"(r[3]) : "r"(addr));
}
__device__ __forceinline__ void mma_f16(float* d, const uint32_t* a,
                                        uint32_t b0, uint32_t b1) {
    asm volatile(
        "mma.sync.aligned.m16n8k16.row.col.f32.f16.f16.f32 "
        "{%0,%1,%2,%3}, {%4,%5,%6,%7}, {%8,%9}, {%0,%1,%2,%3};"
        : "+f"(d[0]), "+f"(d[1]), "+f"(d[2]), "+f"(d[3])
        : "r"(a[0]), "r"(a[1]), "r"(a[2]), "r"(a[3]), "r"(b0), "r"(b1));
}
__device__ __forceinline__ uint32_t pack2h(float x, float y) {
    __half2 hh = __floats2half2_rn(x, y);
    return *reinterpret_cast<uint32_t*>(&hh);
}

// ---------------------------------------------------------------------------
// fp32 -> fp16 hi, 8 elems/thread
// ---------------------------------------------------------------------------
__global__ void conv_hi8(const float* __restrict__ src,
                         __half* __restrict__ hi, int n)
{
    int i = (blockIdx.x * blockDim.x + threadIdx.x) * 8;
    if (i >= n) return;
    float4 v0 = *(const float4*)(src + i);
    float4 v1 = *(const float4*)(src + i + 4);
    uint4 h;
    h.x = pack2h(v0.x, v0.y);
    h.y = pack2h(v0.z, v0.w);
    h.z = pack2h(v1.x, v1.y);
    h.w = pack2h(v1.z, v1.w);
    *(uint4*)(hi + i) = h;
}

// ---------------------------------------------------------------------------
// Tensor-core fp16 GEMM: C = A_hi @ W_hi + bias (single-term).
// 128x128 block tile, BK=32, 256 threads (8 warps, 4x2), warp tile 32x64.
// 3-stage cp.async pipeline, one __syncthreads per K-iteration.
// ---------------------------------------------------------------------------
#define B_HI   5120          // elements: A is 128*40
#define STG_E  9472          // stage elements (18944 bytes): A 5120 + B 4352
#define GEMM_SMEM (STG_E * 2 * 3)   // 56832 bytes

__device__ __forceinline__ void load_stage(
    uint32_t sb, int tid, int bm, int bn, int k0,
    const __half* Ahi, const __half* Bhi)
{
    #pragma unroll
    for (int i = 0; i < 2; i++) {
        int c = tid + i * 256;
        int r = c >> 2, cc = (c & 3) * 8;
        size_t go = (size_t)(bm + r) * DIM + k0 + cc;
        cpa16(sb + (r * 40 + cc) * 2, Ahi + go);
    }
    #pragma unroll
    for (int i = 0; i < 2; i++) {
        int c = tid + i * 256;
        int r = c >> 4, cc = (c & 15) * 8;
        size_t go = (size_t)(k0 + r) * DIM + bn + cc;
        cpa16(sb + (B_HI + r * 136 + cc) * 2, Bhi + go);
    }
    asm volatile("cp.async.commit_group;" ::: "memory");
}

// If Ch != nullptr, write fp16 (hi-only) output; else fp32.
__device__ __forceinline__ void gemm_body(
    const __half* __restrict__ Ahi, const __half* __restrict__ Bhi,
    const float* __restrict__ bias, float* __restrict__ C,
    __half* __restrict__ Ch, int bm, int bn)
{
    extern __shared__ __half smbuf[];
    const int tid  = threadIdx.x;
    const int lane = tid & 31;
    const int wid  = tid >> 5;
    const int wm   = wid & 3;
    const int wn   = wid >> 2;
    uint32_t sb0 = (uint32_t)__cvta_generic_to_shared(smbuf);

    float acc[2][8][4] = {};

    const int NIT = DIM / 32;   // 96
    load_stage(sb0, tid, bm, bn, 0, Ahi, Bhi);
    load_stage(sb0 + STG_E * 2, tid, bm, bn, 32, Ahi, Bhi);

    int buf = 0;                 // it % 3
    for (int it = 0; it < NIT; it++) {
        if (it < NIT - 1) {
            asm volatile("cp.async.wait_group 1;" ::: "memory");
        } else {
            asm volatile("cp.async.wait_group 0;" ::: "memory");
        }
        __syncthreads();

        if (it + 2 < NIT) {
            int nb = buf + 2; if (nb >= 3) nb -= 3;
            load_stage(sb0 + (uint32_t)nb * (STG_E * 2), tid, bm, bn,
                       (it + 2) * 32, Ahi, Bhi);
        }

        uint32_t sb = sb0 + (uint32_t)buf * (STG_E * 2);
        #pragma unroll
        for (int kk = 0; kk < 32; kk += 16) {
            uint32_t ra_h[2][4];
            uint32_t arow = wm * 32 + (lane & 15);
            uint32_t aoff = (arow * 40 + kk + (lane >> 4) * 8) * 2;
            ldm_x4(sb + aoff, ra_h[0]);
            ldm_x4(sb + aoff + 16 * 40 * 2, ra_h[1]);

            int g = lane >> 3;
            uint32_t brow = kk + (g & 1) * 8 + (lane & 7);
            #pragma unroll
            for (int ng = 0; ng < 4; ng++) {
                uint32_t rb_h[4];
                uint32_t col  = wn * 64 + ng * 16 + (g >> 1) * 8;
                uint32_t boff = (brow * 136 + col) * 2;
                ldm_x4t(sb + B_HI * 2 + boff, rb_h);
                #pragma unroll
                for (int mi = 0; mi < 2; mi++) {
                    int t0 = 2 * ng, t1 = 2 * ng + 1;
                    mma_f16(acc[mi][t0], ra_h[mi], rb_h[0], rb_h[1]);
                    mma_f16(acc[mi][t1], ra_h[mi], rb_h[2], rb_h[3]);
                }
            }
        }
        if (++buf == 3) buf = 0;
    }

    #pragma unroll
    for (int mi = 0; mi < 2; mi++) {
        int r0 = bm + wm * 32 + mi * 16 + (lane >> 2);
        #pragma unroll
        for (int t = 0; t < 8; t++) {
            int c = bn + wn * 64 + t * 8 + (lane & 3) * 2;
            float v00 = acc[mi][t][0] + bias[c];
            float v01 = acc[mi][t][1] + bias[c + 1];
            float v10 = acc[mi][t][2] + bias[c];
            float v11 = acc[mi][t][3] + bias[c + 1];
            if (Ch) {
                *(uint32_t*)(Ch + (size_t)r0 * DIM + c)       = pack2h(v00, v01);
                *(uint32_t*)(Ch + (size_t)(r0 + 8) * DIM + c) = pack2h(v10, v11);
            } else {
                C[(size_t)r0 * DIM + c]           = v00;
                C[(size_t)r0 * DIM + c + 1]       = v01;
                C[(size_t)(r0 + 8) * DIM + c]     = v10;
                C[(size_t)(r0 + 8) * DIM + c + 1] = v11;
            }
        }
    }
}

// O projection (fp32 out)
__global__ __launch_bounds__(256, 2) void gemm_o(
    const __half* __restrict__ Ahi, const __half* __restrict__ Bhi,
    const float* __restrict__ bias, float* __restrict__ C)
{
    gemm_body(Ahi, Bhi, bias, C, nullptr, blockIdx.y * 128, blockIdx.x * 128);
}

// fused QKV GEMM: grid.x = 72 (3 weights x 24 col tiles); V writes fp16 direct
__global__ __launch_bounds__(256, 2) void gemm_qkv(
    const __half* __restrict__ Ahi, const __half* __restrict__ WhiBase,
    const float* __restrict__ bq, const float* __restrict__ bk,
    const float* __restrict__ bv,
    float* __restrict__ pq, float* __restrict__ pk, __half* __restrict__ vh)
{
    const int sel = blockIdx.x / 24;
    const int bn  = (blockIdx.x % 24) * 128;
    const size_t NW = (size_t)DIM * DIM;
    const __half* Bhi = WhiBase + (size_t)sel * NW;
    const float* bias = (sel == 0) ? bq : (sel == 1) ? bk : bv;
    float* C = (sel == 0) ? pq : (sel == 1) ? pk : nullptr;
    __half* Ch = (sel == 2) ? vh : nullptr;
    gemm_body(Ahi, Bhi, bias, C, Ch, blockIdx.y * 128, bn);
}

// ---------------------------------------------------------------------------
// Fused per-head RMSNorm + RoPE + scale -> fp16 hi.
// One warp per (token, head); 8 warps/block; float4 per lane.
// ---------------------------------------------------------------------------
__global__ __launch_bounds__(256) void rmsnorm_rope_hi(
    const float* __restrict__ in, const float* __restrict__ w,
    const float* __restrict__ cb, const float* __restrict__ sb,
    float scale, __half* __restrict__ ohi)
{
    const int warp = threadIdx.x >> 5, lane = threadIdx.x & 31;
    const int ghi = blockIdx.x * 8 + warp;
    const int s = ghi / HEADS, h = ghi - s * HEADS;
    const size_t base = (size_t)s * DIM + h * HD + lane * 4;

    float4 v = *(const float4*)(in + base);
    float sq = v.x * v.x + v.y * v.y + v.z * v.z + v.w * v.w;
    #pragma unroll
    for (int off = 16; off; off >>= 1) sq += __shfl_xor_sync(0xffffffffu, sq, off);

    float inv = rsqrtf(sq * (1.0f / HD) + 1e-6f) * scale;
    float4 w4 = *(const float4*)(w + lane * 4);
    float n0 = v.x * inv * w4.x;
    float n1 = v.y * inv * w4.y;
    float n2 = v.z * inv * w4.z;
    float n3 = v.w * inv * w4.w;

    float o0 = n0, o1 = n1, o2 = n2, o3 = n3;
    if (s < SIMG) {
        float4 c4 = *(const float4*)(cb + s * HD + lane * 4);
        float4 s4 = *(const float4*)(sb + s * HD + lane * 4);
        o0 = n0 * c4.x - n1 * s4.x;
        o1 = n1 * c4.y + n0 * s4.y;
        o2 = n2 * c4.z - n3 * s4.z;
        o3 = n3 * c4.w + n2 * s4.w;
    }
    *(uint2*)(ohi + base) = make_uint2(pack2h(o0, o1), pack2h(o2, o3));
}

// ---------------------------------------------------------------------------
// Flash attention, pure fp16 MMA, fp32 accumulators.
// Q, K single buffer; V double-buffer. smem 69632 B -> 2 CTAs/SM.
// txt rows (q0 >= SIMG) write fp32 directly into d_out; img rows write fp16 hi.
// ---------------------------------------------------------------------------
#define AQHI 0
#define AKHI 8704
#define AVH0 17408
#define AVH1 26112
#define ATT_SMEM (34816 * 2)

__global__ __launch_bounds__(128) void attn_mma(
    const __half* __restrict__ qhi,
    const __half* __restrict__ khi, const __half* __restrict__ vhi,
    __half* __restrict__ ohi, float* __restrict__ o_f32)
{
    extern __shared__ __half sm2[];
    uint32_t sb = (uint32_t)__cvta_generic_to_shared(sm2);
    const int tid = threadIdx.x, lane = tid & 31, wid = tid >> 5;
    const int q0 = blockIdx.x * 64, h = blockIdx.y;

    // prologue: Q + K(0) + V(0)
    #pragma unroll
    for (int i = 0; i < 8; i++) {
        int idx = tid + i * 128, r = idx >> 4, c = (idx & 15) * 8;
        size_t gq = (size_t)(q0 + r) * DIM + h * HD + c;
        size_t gk = (size_t)r * DIM + h * HD + c;
        uint32_t so = (uint32_t)(r * 136 + c) * 2;
        cpa16(sb + AQHI * 2 + so, qhi + gq);
        cpa16(sb + AKHI * 2 + so, khi + gk);
        cpa16(sb + AVH0 * 2 + so, vhi + gk);
    }
    asm volatile("cp.async.commit_group;" ::: "memory");
    asm volatile("cp.async.wait_group 0;" ::: "memory");
    __syncthreads();

    float m0 = -1e30f, m1 = -1e30f, l0 = 0.f, l1 = 0.f;
    float oa[16][4] = {};

    const uint32_t aoff = (uint32_t)((wid * 16 + (lane & 15)) * 136 +
                                     ((lane >> 4) << 3)) * 2;
    const int brow = ((lane >> 4) << 3) + (lane & 7);
    const int bcol = ((lane >> 3) & 1) << 3;
    const int vrow = ((lane >> 3) & 1) * 8 + (lane & 7);
    const int vcol = (lane >> 4) << 3;

    const int NIT = STOT / 64;
    for (int it = 0; it < NIT; it++) {
        // ---- S = Q_hi @ K_hi^T ----
        float sc[8][4] = {};
        #pragma unroll
        for (int ks = 0; ks < 8; ks++) {
            uint32_t qh[4];
            ldm_x4(sb + AQHI * 2 + aoff + ks * 32, qh);
            #pragma unroll
            for (int bt = 0; bt < 4; bt++) {
                uint32_t kh[4];
                uint32_t ko = (uint32_t)((bt * 16 + brow) * 136 + ks * 16 + bcol) * 2;
                ldm_x4(sb + AKHI * 2 + ko, kh);
                mma_f16(sc[2 * bt],     qh, kh[0], kh[1]);
                mma_f16(sc[2 * bt + 1], qh, kh[2], kh[3]);
            }
        }
        __syncthreads();    // all warps done reading K

        // ---- prefetch K(it+1), V(it+1): overlaps softmax + PV ----
        if (it + 1 < NIT) {
            int kt = (it + 1) * 64;
            uint32_t vdst = ((it + 1) & 1) ? AVH1 : AVH0;
            #pragma unroll
            for (int i = 0; i < 8; i++) {
                int idx = tid + i * 128, r = idx >> 4, c = (idx & 15) * 8;
                size_t go = (size_t)(kt + r) * DIM + h * HD + c;
                uint32_t so = (uint32_t)(r * 136 + c) * 2;
                cpa16(sb + AKHI * 2 + so, khi + go);
                cpa16(sb + vdst * 2 + so, vhi + go);
            }
            asm volatile("cp.async.commit_group;" ::: "memory");
        }

        // ---- online softmax in registers ----
        float mx0 = -1e30f, mx1 = -1e30f;
        #pragma unroll
        for (int nt = 0; nt < 8; nt++) {
            mx0 = fmaxf(mx0, fmaxf(sc[nt][0], sc[nt][1]));
            mx1 = fmaxf(mx1, fmaxf(sc[nt][2], sc[nt][3]));
        }
        mx0 = fmaxf(mx0, __shfl_xor_sync(0xffffffffu, mx0, 1));
        mx0 = fmaxf(mx0, __shfl_xor_sync(0xffffffffu, mx0, 2));
        mx1 = fmaxf(mx1, __shfl_xor_sync(0xffffffffu, mx1, 1));
        mx1 = fmaxf(mx1, __shfl_xor_sync(0xffffffffu, mx1, 2));
        float mn0 = fmaxf(m0, mx0), mn1 = fmaxf(m1, mx1);
        float c0 = __expf(m0 - mn0), c1 = __expf(m1 - mn1);
        float ls0 = 0.f, ls1 = 0.f;
        #pragma unroll
        for (int nt = 0; nt < 8; nt++) {
            sc[nt][0] = __expf(sc[nt][0] - mn0);
            sc[nt][1] = __expf(sc[nt][1] - mn0);
            sc[nt][2] = __expf(sc[nt][2] - mn1);
            sc[nt][3] = __expf(sc[nt][3] - mn1);
            ls0 += sc[nt][0] + sc[nt][1];
            ls1 += sc[nt][2] + sc[nt][3];
        }
        ls0 += __shfl_xor_sync(0xffffffffu, ls0, 1);
        ls0 += __shfl_xor_sync(0xffffffffu, ls0, 2);
        ls1 += __shfl_xor_sync(0xffffffffu, ls1, 1);
        ls1 += __shfl_xor_sync(0xffffffffu, ls1, 2);
        m0 = mn0; m1 = mn1;
        l0 = l0 * c0 + ls0;
        l1 = l1 * c1 + ls1;
        #pragma unroll
        for (int nt = 0; nt < 16; nt++) {
            oa[nt][0] *= c0; oa[nt][1] *= c0;
            oa[nt][2] *= c1; oa[nt][3] *= c1;
        }

        // ---- P frags (fp16, registers) ----
        uint32_t ph[4][4];
        #pragma unroll
        for (int t = 0; t < 4; t++) {
            ph[t][0] = pack2h(sc[2 * t][0],     sc[2 * t][1]);
            ph[t][1] = pack2h(sc[2 * t][2],     sc[2 * t][3]);
            ph[t][2] = pack2h(sc[2 * t + 1][0], sc[2 * t + 1][1]);
            ph[t][3] = pack2h(sc[2 * t + 1][2], sc[2 * t + 1][3]);
        }

        // ---- O += P @ V (reads V[it&1]) ----
        uint32_t vbase = (it & 1) ? AVH1 : AVH0;
        #pragma unroll
        for (int kst = 0; kst < 4; kst++) {
            #pragma unroll
            for (int dt = 0; dt < 8; dt++) {
                uint32_t vh[4];
                uint32_t vo = (uint32_t)((kst * 16 + vrow) * 136 + dt * 16 + vcol) * 2;
                ldm_x4t(sb + vbase * 2 + vo, vh);
                mma_f16(oa[2 * dt],     ph[kst], vh[0], vh[1]);
                mma_f16(oa[2 * dt + 1], ph[kst], vh[2], vh[3]);
            }
        }

        if (it + 1 < NIT) {
            asm volatile("cp.async.wait_group 0;" ::: "memory");
        }
        __syncthreads();
    }

    // ---- normalize + store: fp16 hi for O-proj; fp32 direct to d_out for txt ----
    float inv0 = 1.0f / l0, inv1 = 1.0f / l1;
    int r0 = q0 + wid * 16 + (lane >> 2);
    int cb0 = h * HD + (lane & 3) * 2;
    const bool wr32 = (q0 >= SIMG);
    #pragma unroll
    for (int nt = 0; nt < 16; nt++) {
        float a0 = oa[nt][0] * inv0, a1 = oa[nt][1] * inv0;
        float a2 = oa[nt][2] * inv1, a3 = oa[nt][3] * inv1;
        size_t off0 = (size_t)r0 * DIM + cb0 + nt * 8;
        size_t off1 = (size_t)(r0 + 8) * DIM + cb0 + nt * 8;
        *(uint32_t*)(ohi + off0) = pack2h(a0, a1);
        *(uint32_t*)(ohi + off1) = pack2h(a2, a3);
        if (wr32) {
            *(float2*)(o_f32 + off0) = make_float2(a0, a1);
            *(float2*)(o_f32 + off1) = make_float2(a2, a3);
        }
    }
}

// ---------------------------------------------------------------------------
extern "C" void kernel_launch(void* const* d_in, const int* in_sizes, int n_in,
                              void* d_out, int out_size)
{
    const float* hidden = (const float*)d_in[0];
    const float* enc    = (const float*)d_in[1];
    const float* cosb   = (const float*)d_in[2];
    const float* sinb   = (const float*)d_in[3];
    const float* wq     = (const float*)d_in[4];
    const float* bq     = (const float*)d_in[5];
    const float* wk     = (const float*)d_in[6];
    const float* bk     = (const float*)d_in[7];
    const float* wv     = (const float*)d_in[8];
    const float* bv     = (const float*)d_in[9];
    const float* nqw    = (const float*)d_in[10];
    const float* nkw    = (const float*)d_in[11];
    const float* wo     = (const float*)d_in[12];
    const float* bo     = (const float*)d_in[13];
    float* out = (float*)d_out;

    float *pq, *pk;
    __half *xhi, *whi;
    __half *aqh, *akh, *avh;
    cudaGetSymbolAddress((void**)&pq, g_q);
    cudaGetSymbolAddress((void**)&pk, g_k);
    cudaGetSymbolAddress((void**)&xhi, g_xhi);
    cudaGetSymbolAddress((void**)&whi, g_whi);
    cudaGetSymbolAddress((void**)&aqh, g_qhi);
    cudaGetSymbolAddress((void**)&akh, g_khi);
    cudaGetSymbolAddress((void**)&avh, g_vhi);

    cudaFuncSetAttribute(gemm_o, cudaFuncAttributeMaxDynamicSharedMemorySize,
                         GEMM_SMEM);
    cudaFuncSetAttribute(gemm_qkv, cudaFuncAttributeMaxDynamicSharedMemorySize,
                         GEMM_SMEM);
    cudaFuncSetAttribute(attn_mma, cudaFuncAttributeMaxDynamicSharedMemorySize,
                         ATT_SMEM);

    const size_t NW = (size_t)DIM * DIM;
    const int conv_blk = 256;
    const int grid_w = (int)((NW / 8 + conv_blk - 1) / conv_blk);

    // --- all conversions up front (everything hi-only fp16 now) ---
    conv_hi8<<<(SIMG * DIM / 8 + 255) / 256, 256>>>(hidden, xhi, SIMG * DIM);
    conv_hi8<<<(STXT * DIM / 8 + 255) / 256, 256>>>(
        enc, xhi + (size_t)SIMG * DIM, STXT * DIM);
    conv_hi8<<<grid_w, conv_blk>>>(wq, whi + 0 * NW, (int)NW);
    conv_hi8<<<grid_w, conv_blk>>>(wk, whi + 1 * NW, (int)NW);
    conv_hi8<<<grid_w, conv_blk>>>(wv, whi + 2 * NW, (int)NW);
    conv_hi8<<<grid_w, conv_blk>>>(wo, whi + 3 * NW, (int)NW);

    // fused Q, K, V projections, single-term fp16 (V writes fp16 directly)
    dim3 gq(72, STOT / 128);           // (72, 18)
    gemm_qkv<<<gq, 256, GEMM_SMEM>>>(xhi, whi, bq, bk, bv, pq, pk, avh);

    // per-head RMSNorm + RoPE -> fp16 hi (scale folded into Q); warp-per-head
    const int rms_grid = STOT * HEADS / 8;   // 6912
    rmsnorm_rope_hi<<<rms_grid, 256>>>(pq, nqw, cosb, sinb,
                                       0.08838834764831845f, aqh);
    rmsnorm_rope_hi<<<rms_grid, 256>>>(pk, nkw, cosb, sinb, 1.0f, akh);

    // attention (pure fp16 mma) -> fp16 hi for O-proj; txt fp32 direct to out
    dim3 ga(STOT / 64, HEADS);         // (36, 24)
    attn_mma<<<ga, 128, ATT_SMEM>>>(aqh, akh, avh, xhi, out);

    // output projection for image tokens (single-term fp16)
    dim3 go(DIM / 128, SIMG / 128);    // (24, 16)
    gemm_o<<<go, 256, GEMM_SMEM>>>(xhi, whi + 3 * NW, bo, out);
}